// round 4
// baseline (speedup 1.0000x reference)
#include <cuda_runtime.h>
#include <cuda_bf16.h>
#include <math.h>

#define BB 2
#define TT 1024
#define CC 2048
#define HH 32
#define NN 64
#define FFD 8192
#define BT (BB*TT)
#define EPS_ 1e-5f

// ---------------- scratch (device globals; allocation-free) ----------------
__device__ float g_XL [BT*CC];
__device__ float g_XK [BT*CC];
__device__ float g_XV [BT*CC];
__device__ float g_XR [BT*CC];
__device__ float g_XG [BT*CC];
__device__ float g_R  [BT*CC];
__device__ float g_K  [BT*CC];
__device__ float g_V  [BT*CC];
__device__ float g_G  [BT*CC];
__device__ float g_ATT[BT*CC];
__device__ float g_AG [BT*CC];
__device__ float g_X1 [BT*CC];
__device__ float g_XL2[BT*CC];
__device__ float g_CK [BT*CC];
__device__ float g_CR [BT*CC];
__device__ float g_KV [BT*CC];
__device__ float g_KK [BT*FFD];
__device__ float g_AB [BT*HH];

// ---------------- LayerNorm over last dim (C=2048), one block per row ------
__global__ void ln_kernel(const float* __restrict__ x, const float* __restrict__ g,
                          const float* __restrict__ b, float* __restrict__ out) {
    __shared__ float sa[8], sb[8];
    const int row = blockIdx.x;
    const float4* xr = (const float4*)(x + (size_t)row * CC);
    float4 v[2];
    float s = 0.f, s2 = 0.f;
#pragma unroll
    for (int it = 0; it < 2; it++) {
        float4 q = xr[threadIdx.x + it * 256];
        v[it] = q;
        s  += q.x + q.y + q.z + q.w;
        s2 += q.x*q.x + q.y*q.y + q.z*q.z + q.w*q.w;
    }
#pragma unroll
    for (int o = 16; o; o >>= 1) {
        s  += __shfl_xor_sync(0xffffffffu, s,  o);
        s2 += __shfl_xor_sync(0xffffffffu, s2, o);
    }
    const int wid = threadIdx.x >> 5, lane = threadIdx.x & 31;
    if (!lane) { sa[wid] = s; sb[wid] = s2; }
    __syncthreads();
    if (threadIdx.x == 0) {
        float ts = 0.f, ts2 = 0.f;
#pragma unroll
        for (int i = 0; i < 8; i++) { ts += sa[i]; ts2 += sb[i]; }
        sa[0] = ts; sb[0] = ts2;
    }
    __syncthreads();
    const float mean = sa[0] * (1.f / CC);
    const float var  = sb[0] * (1.f / CC) - mean * mean;
    const float rstd = rsqrtf(var + EPS_);
    float4* op = (float4*)(out + (size_t)row * CC);
#pragma unroll
    for (int it = 0; it < 2; it++) {
        const int i4 = threadIdx.x + it * 256;
        float4 q  = v[it];
        float4 gg = ((const float4*)g)[i4];
        float4 bq = ((const float4*)b)[i4];
        q.x = (q.x - mean) * rstd * gg.x + bq.x;
        q.y = (q.y - mean) * rstd * gg.y + bq.y;
        q.z = (q.z - mean) * rstd * gg.z + bq.z;
        q.w = (q.w - mean) * rstd * gg.w + bq.w;
        op[i4] = q;
    }
}

// ---------------- time-shift mixes ----------------
__global__ void mix4_kernel(const float* __restrict__ xl,
                            const float* __restrict__ mk, const float* __restrict__ mv,
                            const float* __restrict__ mr, const float* __restrict__ mg,
                            float* __restrict__ xk, float* __restrict__ xv,
                            float* __restrict__ xr, float* __restrict__ xg) {
    const size_t idx = (size_t)blockIdx.x * blockDim.x + threadIdx.x;
    const int c = (int)(idx & (CC - 1));
    const int t = (int)((idx >> 11) & (TT - 1));
    const float cur  = xl[idx];
    const float prev = (t > 0) ? xl[idx - CC] : 0.f;
    const float d = cur - prev;
    xk[idx] = prev + mk[c] * d;
    xv[idx] = prev + mv[c] * d;
    xr[idx] = prev + mr[c] * d;
    xg[idx] = prev + mg[c] * d;
}

__global__ void mix2_kernel(const float* __restrict__ xl,
                            const float* __restrict__ mk, const float* __restrict__ mr,
                            float* __restrict__ ck, float* __restrict__ cr) {
    const size_t idx = (size_t)blockIdx.x * blockDim.x + threadIdx.x;
    const int c = (int)(idx & (CC - 1));
    const int t = (int)((idx >> 11) & (TT - 1));
    const float cur  = xl[idx];
    const float prev = (t > 0) ? xl[idx - CC] : 0.f;
    const float d = cur - prev;
    ck[idx] = prev + mk[c] * d;
    cr[idx] = prev + mr[c] * d;
}

// ---------------- SGEMM: C[M,N] = A[M,K] @ B[K,N], fused epilogues ----------
// EPI: 0 none | 1 silu | 2 relu^2 | 3 out=aux1+acc | 4 out=aux1+sigmoid(acc)*aux2
template <int EPI>
__global__ __launch_bounds__(256)
void sgemm_k(const float* __restrict__ A, const float* __restrict__ B,
             float* __restrict__ C, int M, int N, int K,
             const float* __restrict__ aux1, const float* __restrict__ aux2) {
    __shared__ float As[2][8][128];
    __shared__ float Bs[2][8][128];

    const int tid  = threadIdx.x;
    const int tx   = tid & 15;   // 0..15  (N micro-tiles)
    const int ty   = tid >> 4;   // 0..15  (M micro-tiles)
    const int row0 = blockIdx.y * 128;
    const int col0 = blockIdx.x * 128;

    // A-tile load mapping: 128 rows x 8 k  (one float4 per thread)
    const int am = tid >> 1;
    const int ak = (tid & 1) * 4;
    // B-tile load mapping: 8 rows x 128 cols
    const int bk = tid >> 5;
    const int bn = (tid & 31) * 4;

    const float* Aptr = A + (size_t)(row0 + am) * K + ak;
    const float* Bptr = B + (size_t)bk * N + col0 + bn;

    float acc[8][8];
#pragma unroll
    for (int i = 0; i < 8; i++)
#pragma unroll
        for (int j = 0; j < 8; j++) acc[i][j] = 0.f;

    // prologue: stage k-block 0 into buffer 0
    {
        float4 a4 = *(const float4*)(Aptr);
        As[0][ak + 0][am] = a4.x; As[0][ak + 1][am] = a4.y;
        As[0][ak + 2][am] = a4.z; As[0][ak + 3][am] = a4.w;
        *(float4*)&Bs[0][bk][bn] = *(const float4*)(Bptr);
    }
    __syncthreads();

    int buf = 0;
#pragma unroll 1
    for (int kb = 0; kb < K; kb += 8) {
        float4 a4, b4;
        const bool pre = (kb + 8 < K);
        if (pre) {
            a4 = *(const float4*)(Aptr + kb + 8);
            b4 = *(const float4*)(Bptr + (size_t)(kb + 8) * N);
        }
#pragma unroll
        for (int kk = 0; kk < 8; kk++) {
            float ra[8], rb[8];
            *(float4*)&ra[0] = *(const float4*)&As[buf][kk][ty * 8];
            *(float4*)&ra[4] = *(const float4*)&As[buf][kk][ty * 8 + 4];
            *(float4*)&rb[0] = *(const float4*)&Bs[buf][kk][tx * 8];
            *(float4*)&rb[4] = *(const float4*)&Bs[buf][kk][tx * 8 + 4];
#pragma unroll
            for (int i = 0; i < 8; i++)
#pragma unroll
                for (int j = 0; j < 8; j++)
                    acc[i][j] += ra[i] * rb[j];
        }
        if (pre) {
            const int nxt = buf ^ 1;
            As[nxt][ak + 0][am] = a4.x; As[nxt][ak + 1][am] = a4.y;
            As[nxt][ak + 2][am] = a4.z; As[nxt][ak + 3][am] = a4.w;
            *(float4*)&Bs[nxt][bk][bn] = b4;
            __syncthreads();
            buf = nxt;
        }
    }

    // epilogue
#pragma unroll
    for (int i = 0; i < 8; i++) {
        const size_t r = (size_t)(row0 + ty * 8 + i);
#pragma unroll
        for (int j = 0; j < 8; j += 4) {
            const size_t idx = r * N + (col0 + tx * 8 + j);
            float4 v;
            v.x = acc[i][j + 0]; v.y = acc[i][j + 1];
            v.z = acc[i][j + 2]; v.w = acc[i][j + 3];
            if (EPI == 1) {
                v.x = v.x / (1.f + expf(-v.x)); v.y = v.y / (1.f + expf(-v.y));
                v.z = v.z / (1.f + expf(-v.z)); v.w = v.w / (1.f + expf(-v.w));
            } else if (EPI == 2) {
                float t0 = fmaxf(v.x, 0.f), t1 = fmaxf(v.y, 0.f);
                float t2 = fmaxf(v.z, 0.f), t3 = fmaxf(v.w, 0.f);
                v.x = t0 * t0; v.y = t1 * t1; v.z = t2 * t2; v.w = t3 * t3;
            } else if (EPI == 3) {
                v.x += aux1[idx + 0]; v.y += aux1[idx + 1];
                v.z += aux1[idx + 2]; v.w += aux1[idx + 3];
            } else if (EPI == 4) {
                v.x = aux1[idx + 0] + aux2[idx + 0] / (1.f + expf(-v.x));
                v.y = aux1[idx + 1] + aux2[idx + 1] / (1.f + expf(-v.y));
                v.z = aux1[idx + 2] + aux2[idx + 2] / (1.f + expf(-v.z));
                v.w = aux1[idx + 3] + aux2[idx + 3] / (1.f + expf(-v.w));
            }
            *(float4*)&C[idx] = v;
        }
    }
}

// ---------------- a_t = sum_i r_i * u_i * k_i  (warp per (b,t,h)) ----------
__global__ void adot_kernel(const float* __restrict__ r, const float* __restrict__ k,
                            const float* __restrict__ u, float* __restrict__ ab) {
    const int gid  = blockIdx.x * 8 + (threadIdx.x >> 5);
    const int lane = threadIdx.x & 31;
    const int h = gid & (HH - 1);
    const size_t off = (size_t)gid * NN;
    float p = r[off + lane]      * u[h * NN + lane]      * k[off + lane]
            + r[off + lane + 32] * u[h * NN + lane + 32] * k[off + lane + 32];
#pragma unroll
    for (int o = 16; o; o >>= 1) p += __shfl_xor_sync(0xffffffffu, p, o);
    if (lane == 0) ab[gid] = p;
}

// ---------------- WKV5 recurrence: block per (b,h), 128 threads ------------
// thread = (j, p): owns state column j, i-range [32p, 32p+32)
__global__ __launch_bounds__(128)
void wkv_kernel(const float* __restrict__ r, const float* __restrict__ k,
                const float* __restrict__ v, const float* __restrict__ w,
                const float* __restrict__ ab, float* __restrict__ att) {
    const int bh = blockIdx.x;
    const int b = bh / HH, h = bh % HH;
    const int tid = threadIdx.x;
    const int j = tid >> 1;
    const int p = tid & 1;

    __shared__ float sh_r[64], sh_k[64];

    float S[32], dec[32];
#pragma unroll
    for (int ii = 0; ii < 32; ii++) S[ii] = 0.f;
#pragma unroll
    for (int ii = 0; ii < 32; ii++) {
        const float wv = w[h * NN + p * 32 + ii];
        dec[ii] = expf(-expf(wv));
    }

    for (int t = 0; t < TT; t++) {
        const size_t off = (((size_t)b * TT + t) * HH + h) * NN;
        __syncthreads();
        if (tid < 64) sh_r[tid] = r[off + tid];
        else          sh_k[tid - 64] = k[off + tid - 64];
        __syncthreads();
        const float vj = v[off + j];
        const float at = ab[((size_t)b * TT + t) * HH + h];
        float yp = 0.f;
#pragma unroll
        for (int ii = 0; ii < 32; ii++) {
            const int i = p * 32 + ii;
            const float ri = sh_r[i];
            const float ki = sh_k[i];
            yp += ri * S[ii];
            S[ii] = dec[ii] * S[ii] + ki * vj;
        }
        const float y = yp + __shfl_xor_sync(0xffffffffu, yp, 1);
        if (p == 0) att[off + j] = at * vj + y;
    }
}

// ---------------- GroupNorm(att/DIV) * lnx_g + lnx_b, then * gate ----------
__global__ void gn_gate_kernel(const float* __restrict__ att, const float* __restrict__ gq,
                               const float* __restrict__ gg, const float* __restrict__ gb,
                               float* __restrict__ out) {
    const int gid  = blockIdx.x * 8 + (threadIdx.x >> 5);
    const int lane = threadIdx.x & 31;
    const int h = gid & (HH - 1);
    const size_t off = (size_t)gid * NN;
    const float inv_div = 1.f / 8.f;
    const float v0 = att[off + lane]      * inv_div;
    const float v1 = att[off + lane + 32] * inv_div;
    float s = v0 + v1, s2 = v0 * v0 + v1 * v1;
#pragma unroll
    for (int o = 16; o; o >>= 1) {
        s  += __shfl_xor_sync(0xffffffffu, s,  o);
        s2 += __shfl_xor_sync(0xffffffffu, s2, o);
    }
    const float m = s * (1.f / NN);
    const float var = s2 * (1.f / NN) - m * m;
    const float rstd = rsqrtf(var + EPS_);
    const int c0 = h * NN + lane;
    out[off + lane]      = ((v0 - m) * rstd * gg[c0]      + gb[c0])      * gq[off + lane];
    out[off + lane + 32] = ((v1 - m) * rstd * gg[c0 + 32] + gb[c0 + 32]) * gq[off + lane + 32];
}

// ---------------- launch ----------------
extern "C" void kernel_launch(void* const* d_in, const int* in_sizes, int n_in,
                              void* d_out, int out_size) {
    (void)in_sizes; (void)n_in; (void)out_size;
    const float* x     = (const float*)d_in[0];
    const float* ln1_g = (const float*)d_in[1];
    const float* ln1_b = (const float*)d_in[2];
    const float* ln2_g = (const float*)d_in[3];
    const float* ln2_b = (const float*)d_in[4];
    const float* tm_k  = (const float*)d_in[5];
    const float* tm_v  = (const float*)d_in[6];
    const float* tm_r  = (const float*)d_in[7];
    const float* tm_g  = (const float*)d_in[8];
    const float* tdec  = (const float*)d_in[9];
    const float* tfaa  = (const float*)d_in[10];
    const float* Wr    = (const float*)d_in[11];
    const float* Wk    = (const float*)d_in[12];
    const float* Wv    = (const float*)d_in[13];
    const float* Wg    = (const float*)d_in[14];
    const float* Wo    = (const float*)d_in[15];
    const float* lnx_g = (const float*)d_in[16];
    const float* lnx_b = (const float*)d_in[17];
    const float* fm_k  = (const float*)d_in[18];
    const float* fm_r  = (const float*)d_in[19];
    const float* Wkey  = (const float*)d_in[20];
    const float* Wrec  = (const float*)d_in[21];
    const float* Wval  = (const float*)d_in[22];
    float* out = (float*)d_out;

    float *XL, *XK, *XV, *XR, *XG, *Rb, *Kb, *Vb, *Gb, *ATT, *AG, *X1, *XL2, *CK, *CR, *KV, *KK, *AB;
    cudaGetSymbolAddress((void**)&XL,  g_XL);
    cudaGetSymbolAddress((void**)&XK,  g_XK);
    cudaGetSymbolAddress((void**)&XV,  g_XV);
    cudaGetSymbolAddress((void**)&XR,  g_XR);
    cudaGetSymbolAddress((void**)&XG,  g_XG);
    cudaGetSymbolAddress((void**)&Rb,  g_R);
    cudaGetSymbolAddress((void**)&Kb,  g_K);
    cudaGetSymbolAddress((void**)&Vb,  g_V);
    cudaGetSymbolAddress((void**)&Gb,  g_G);
    cudaGetSymbolAddress((void**)&ATT, g_ATT);
    cudaGetSymbolAddress((void**)&AG,  g_AG);
    cudaGetSymbolAddress((void**)&X1,  g_X1);
    cudaGetSymbolAddress((void**)&XL2, g_XL2);
    cudaGetSymbolAddress((void**)&CK,  g_CK);
    cudaGetSymbolAddress((void**)&CR,  g_CR);
    cudaGetSymbolAddress((void**)&KV,  g_KV);
    cudaGetSymbolAddress((void**)&KK,  g_KK);
    cudaGetSymbolAddress((void**)&AB,  g_AB);

    const dim3 blk(256);
    const dim3 g22(CC / 128, BT / 128);
    const dim3 gkey(FFD / 128, BT / 128);

    // attention half
    ln_kernel<<<BT, 256>>>(x, ln1_g, ln1_b, XL);
    mix4_kernel<<<BT * CC / 256, 256>>>(XL, tm_k, tm_v, tm_r, tm_g, XK, XV, XR, XG);
    sgemm_k<0><<<g22, blk>>>(XR, Wr, Rb, BT, CC, CC, nullptr, nullptr);
    sgemm_k<0><<<g22, blk>>>(XK, Wk, Kb, BT, CC, CC, nullptr, nullptr);
    sgemm_k<0><<<g22, blk>>>(XV, Wv, Vb, BT, CC, CC, nullptr, nullptr);
    sgemm_k<1><<<g22, blk>>>(XG, Wg, Gb, BT, CC, CC, nullptr, nullptr);
    adot_kernel<<<BT * HH / 8, 256>>>(Rb, Kb, tfaa, AB);
    wkv_kernel<<<BB * HH, 128>>>(Rb, Kb, Vb, tdec, AB, ATT);
    gn_gate_kernel<<<BT * HH / 8, 256>>>(ATT, Gb, lnx_g, lnx_b, AG);
    sgemm_k<3><<<g22, blk>>>(AG, Wo, X1, BT, CC, CC, x, nullptr);

    // FFN half
    ln_kernel<<<BT, 256>>>(X1, ln2_g, ln2_b, XL2);
    mix2_kernel<<<BT * CC / 256, 256>>>(XL2, fm_k, fm_r, CK, CR);
    sgemm_k<2><<<gkey, blk>>>(CK, Wkey, KK, BT, FFD, CC, nullptr, nullptr);
    sgemm_k<0><<<g22, blk>>>(KK, Wval, KV, BT, CC, FFD, nullptr, nullptr);
    sgemm_k<4><<<g22, blk>>>(CR, Wrec, out, BT, CC, CC, X1, KV);
}

// round 7
// speedup vs baseline: 2.1768x; 2.1768x over previous
#include <cuda_runtime.h>
#include <cuda_bf16.h>
#include <math.h>
#include <stdint.h>

#define BB 2
#define TT 1024
#define CC 2048
#define HH 32
#define NNH 64
#define FFD 8192
#define BT (BB*TT)
#define EPS_ 1e-5f

typedef __nv_bfloat16 bf16;

// ---------------- scratch (device globals; allocation-free) ----------------
__device__ float g_XL [BT*CC];
__device__ float g_R  [BT*CC];
__device__ float g_K  [BT*CC];
__device__ float g_V  [BT*CC];
__device__ float g_G  [BT*CC];
__device__ float g_ATT[BT*CC];
__device__ float g_X1 [BT*CC];
__device__ float g_XL2[BT*CC];
__device__ float g_KV [BT*CC];
__device__ float g_AB [BT*HH];

__device__ bf16 g_XRh[BT*CC], g_XRl[BT*CC], g_XKh[BT*CC], g_XKl[BT*CC];
__device__ bf16 g_XVh[BT*CC], g_XVl[BT*CC], g_XGh[BT*CC], g_XGl[BT*CC];
__device__ bf16 g_AGh[BT*CC], g_AGl[BT*CC];
__device__ bf16 g_CKh[BT*CC], g_CKl[BT*CC], g_CRh[BT*CC], g_CRl[BT*CC];
__device__ bf16 g_KKh[(size_t)BT*FFD], g_KKl[(size_t)BT*FFD];

__device__ bf16 g_WrTh [CC*CC], g_WrTl [CC*CC];
__device__ bf16 g_WkTh [CC*CC], g_WkTl [CC*CC];
__device__ bf16 g_WvTh [CC*CC], g_WvTl [CC*CC];
__device__ bf16 g_WgTh [CC*CC], g_WgTl [CC*CC];
__device__ bf16 g_WoTh [CC*CC], g_WoTl [CC*CC];
__device__ bf16 g_WreTh[CC*CC], g_WreTl[CC*CC];
__device__ bf16 g_WkeyTh[(size_t)FFD*CC], g_WkeyTl[(size_t)FFD*CC];
__device__ bf16 g_WvalTh[(size_t)CC*FFD], g_WvalTl[(size_t)CC*FFD];

// ---------------- helpers ----------------
__device__ __forceinline__ uint32_t s2u(const void* p) {
    uint32_t r;
    asm("{ .reg .u64 t; cvta.to.shared.u64 t, %1; cvt.u32.u64 %0, t; }" : "=r"(r) : "l"(p));
    return r;
}
#define CP_COMMIT() asm volatile("cp.async.commit_group;" ::: "memory")
#define CP_WAIT(n)  asm volatile("cp.async.wait_group %0;" :: "n"(n) : "memory")
__device__ __forceinline__ void cp16(uint32_t s, const void* g) {
    asm volatile("cp.async.cg.shared.global [%0], [%1], 16;" :: "r"(s), "l"(g));
}
__device__ __forceinline__ void ldm4(uint32_t* r, uint32_t a) {
    asm volatile("ldmatrix.sync.aligned.m8n8.x4.shared.b16 {%0,%1,%2,%3}, [%4];"
        : "=r"(r[0]), "=r"(r[1]), "=r"(r[2]), "=r"(r[3]) : "r"(a));
}
__device__ __forceinline__ void mma16816(float* d, const uint32_t* a, const uint32_t* b) {
    asm volatile(
        "mma.sync.aligned.m16n8k16.row.col.f32.bf16.bf16.f32 "
        "{%0,%1,%2,%3}, {%4,%5,%6,%7}, {%8,%9}, {%0,%1,%2,%3};"
        : "+f"(d[0]), "+f"(d[1]), "+f"(d[2]), "+f"(d[3])
        : "r"(a[0]), "r"(a[1]), "r"(a[2]), "r"(a[3]), "r"(b[0]), "r"(b[1]));
}
// 64B-row swizzle: XOR 16B-unit index (bits 4-5) with row-pair (bits 7-8)
__device__ __forceinline__ uint32_t SW64(uint32_t o) { return o ^ ((o >> 3) & 0x30); }

__device__ __forceinline__ void split2(float v, bf16& h, bf16& l) {
    h = __float2bfloat16(v);
    l = __float2bfloat16(v - __bfloat162float(h));
}

// ---------------- transpose + bf16 split:  W[K,N] -> Wt_hi/lo[N,K] ----------
__global__ void transpose_split_k(const float* __restrict__ W, bf16* __restrict__ th,
                                  bf16* __restrict__ tl, int K, int N) {
    __shared__ float t[32][33];
    const int k0 = blockIdx.y * 32, n0 = blockIdx.x * 32;
#pragma unroll
    for (int i = 0; i < 4; i++)
        t[threadIdx.y + i * 8][threadIdx.x] =
            W[(size_t)(k0 + threadIdx.y + i * 8) * N + n0 + threadIdx.x];
    __syncthreads();
#pragma unroll
    for (int i = 0; i < 4; i++) {
        const float v = t[threadIdx.x][threadIdx.y + i * 8];
        bf16 h, l; split2(v, h, l);
        const size_t o = (size_t)(n0 + threadIdx.y + i * 8) * K + k0 + threadIdx.x;
        th[o] = h; tl[o] = l;
    }
}

// ---------------- mma.sync GEMM: D = A @ B^T via 3xBF16 --------------------
// A: [M,K] hi/lo bf16; B: [N,K] hi/lo bf16. Block 128x128, BK=32, 3 stages.
// 8 warps: wm = wid&1 (2 x 64 rows), wn = wid>>1 (4 x 32 cols).
// EPI: 0 fp32 | 1 silu | 2 relu^2 -> bf16 hi/lo | 3 aux1+acc | 4 aux1+sigmoid(acc)*aux2
#define OFF_AH 0
#define OFF_AL 8192
#define OFF_BH 16384
#define OFF_BL 24576
#define STG    32768
#define GEMM_SMEM (3 * STG)

template <int EPI>
__global__ __launch_bounds__(256, 1)
void mmagemm(const bf16* __restrict__ Ah, const bf16* __restrict__ Al,
             const bf16* __restrict__ Bh, const bf16* __restrict__ Bl,
             float* __restrict__ C, bf16* __restrict__ Ch, bf16* __restrict__ Cl,
             int M, int N, int K,
             const float* __restrict__ aux1, const float* __restrict__ aux2) {
    extern __shared__ __align__(1024) char smem[];
    const uint32_t sb = s2u(smem);
    const int tid = threadIdx.x;
    const int row0 = blockIdx.y * 128;
    const int col0 = blockIdx.x * 128;
    const int NK = K / 32;

    // ---- staging maps: 512 16B-transfers per 8KB matrix, 2 per thread ----
    const int r0 = tid >> 2, c0 = tid & 3;          // transfer tid
    const int r1 = (tid + 256) >> 2, c1 = tid & 3;  // transfer tid+256
    const uint32_t so0 = SW64((uint32_t)(r0 * 64 + c0 * 16));
    const uint32_t so1 = SW64((uint32_t)(r1 * 64 + c1 * 16));
    const bf16* pAh0 = Ah + (size_t)(row0 + r0) * K + c0 * 8;
    const bf16* pAh1 = Ah + (size_t)(row0 + r1) * K + c1 * 8;
    const bf16* pAl0 = Al + (size_t)(row0 + r0) * K + c0 * 8;
    const bf16* pAl1 = Al + (size_t)(row0 + r1) * K + c1 * 8;
    const bf16* pBh0 = Bh + (size_t)(col0 + r0) * K + c0 * 8;
    const bf16* pBh1 = Bh + (size_t)(col0 + r1) * K + c1 * 8;
    const bf16* pBl0 = Bl + (size_t)(col0 + r0) * K + c0 * 8;
    const bf16* pBl1 = Bl + (size_t)(col0 + r1) * K + c1 * 8;

    auto load_stage = [&](int kb, int st) {
        const uint32_t s = sb + (uint32_t)st * STG;
        const size_t ko = (size_t)kb * 32;
        cp16(s + OFF_AH + so0, pAh0 + ko); cp16(s + OFF_AH + so1, pAh1 + ko);
        cp16(s + OFF_AL + so0, pAl0 + ko); cp16(s + OFF_AL + so1, pAl1 + ko);
        cp16(s + OFF_BH + so0, pBh0 + ko); cp16(s + OFF_BH + so1, pBh1 + ko);
        cp16(s + OFF_BL + so0, pBl0 + ko); cp16(s + OFF_BL + so1, pBl1 + ko);
        CP_COMMIT();
    };

    // ---- per-warp fragment addressing ----
    const int wid = tid >> 5, lane = tid & 31;
    const int wm = wid & 1, wn = wid >> 1;
    const int wmb = wm * 64, wnb = wn * 32;
    // A ldmatrix: lanes 0-15 rows, lanes 16-31 rows with +16B col
    const uint32_t a_row  = (uint32_t)(wmb + (lane & 15));
    const uint32_t a_csel = (uint32_t)((lane >> 4) << 4);
    // B ldmatrix: g=lane>>3: n += (g>>1)*8, col += (g&1)*16
    const uint32_t b_row  = (uint32_t)(wnb + ((lane >> 4) << 3) + (lane & 7));
    const uint32_t b_csel = (uint32_t)(((lane >> 3) & 1) << 4);

    float acc[4][4][4];
#pragma unroll
    for (int i = 0; i < 4; i++)
#pragma unroll
        for (int j = 0; j < 4; j++)
#pragma unroll
            for (int q = 0; q < 4; q++) acc[i][j][q] = 0.f;

    // ---- pipeline ----
    load_stage(0, 0);
    if (NK > 1) load_stage(1, 1);

#pragma unroll 1
    for (int kb = 0; kb < NK; kb++) {
        if (kb + 2 < NK) { load_stage(kb + 2, (kb + 2) % 3); CP_WAIT(2); }
        else if (kb + 1 < NK) { CP_WAIT(1); }
        else { CP_WAIT(0); }
        __syncthreads();

        const uint32_t us = sb + (uint32_t)(kb % 3) * STG;
#pragma unroll
        for (int ks = 0; ks < 2; ks++) {
            uint32_t ah[4][4], al[4][4], bh[2][4], bl[2][4];
#pragma unroll
            for (int mt = 0; mt < 4; mt++) {
                const uint32_t off = (a_row + mt * 16) * 64 + (uint32_t)(ks * 32) + a_csel;
                ldm4(ah[mt], us + OFF_AH + SW64(off));
                ldm4(al[mt], us + OFF_AL + SW64(off));
            }
#pragma unroll
            for (int bp = 0; bp < 2; bp++) {
                const uint32_t off = (b_row + bp * 16) * 64 + (uint32_t)(ks * 32) + b_csel;
                ldm4(bh[bp], us + OFF_BH + SW64(off));
                ldm4(bl[bp], us + OFF_BL + SW64(off));
            }
#pragma unroll
            for (int mt = 0; mt < 4; mt++)
#pragma unroll
                for (int nt = 0; nt < 4; nt++) {
                    const uint32_t* bhp = &bh[nt >> 1][(nt & 1) * 2];
                    const uint32_t* blp = &bl[nt >> 1][(nt & 1) * 2];
                    mma16816(acc[mt][nt], ah[mt], bhp);
                    mma16816(acc[mt][nt], al[mt], bhp);
                    mma16816(acc[mt][nt], ah[mt], blp);
                }
        }
        __syncthreads();
    }

    // ---- epilogue (register accumulators) ----
    const int mrow = row0 + wmb + (lane >> 2);
    const int ncol = col0 + wnb + (lane & 3) * 2;
#pragma unroll
    for (int mt = 0; mt < 4; mt++) {
#pragma unroll
        for (int half = 0; half < 2; half++) {
            const size_t m = (size_t)(mrow + mt * 16 + half * 8);
#pragma unroll
            for (int nt = 0; nt < 4; nt++) {
                float vx = acc[mt][nt][half * 2 + 0];
                float vy = acc[mt][nt][half * 2 + 1];
                const size_t idx = m * N + (ncol + nt * 8);
                if (EPI == 1) {
                    vx /= (1.f + expf(-vx)); vy /= (1.f + expf(-vy));
                } else if (EPI == 3) {
                    vx += aux1[idx]; vy += aux1[idx + 1];
                } else if (EPI == 4) {
                    vx = aux1[idx]     + aux2[idx]     / (1.f + expf(-vx));
                    vy = aux1[idx + 1] + aux2[idx + 1] / (1.f + expf(-vy));
                }
                if (EPI == 2) {
                    vx = fmaxf(vx, 0.f); vx *= vx;
                    vy = fmaxf(vy, 0.f); vy *= vy;
                    bf16 hx, lx, hy, ly;
                    split2(vx, hx, lx); split2(vy, hy, ly);
                    __nv_bfloat162 hp, lp;
                    hp.x = hx; hp.y = hy; lp.x = lx; lp.y = ly;
                    *(__nv_bfloat162*)&Ch[idx] = hp;
                    *(__nv_bfloat162*)&Cl[idx] = lp;
                } else {
                    float2 p; p.x = vx; p.y = vy;
                    *(float2*)&C[idx] = p;
                }
            }
        }
    }
}

// ---------------- LayerNorm over last dim (C=2048), one block per row ------
__global__ void ln_kernel(const float* __restrict__ x, const float* __restrict__ g,
                          const float* __restrict__ b, float* __restrict__ out) {
    __shared__ float sa[8], sb_[8];
    const int row = blockIdx.x;
    const float4* xr = (const float4*)(x + (size_t)row * CC);
    float4 v[2];
    float s = 0.f, s2 = 0.f;
#pragma unroll
    for (int it = 0; it < 2; it++) {
        float4 q = xr[threadIdx.x + it * 256];
        v[it] = q;
        s  += q.x + q.y + q.z + q.w;
        s2 += q.x*q.x + q.y*q.y + q.z*q.z + q.w*q.w;
    }
#pragma unroll
    for (int o = 16; o; o >>= 1) {
        s  += __shfl_xor_sync(0xffffffffu, s,  o);
        s2 += __shfl_xor_sync(0xffffffffu, s2, o);
    }
    const int wid = threadIdx.x >> 5, lane = threadIdx.x & 31;
    if (!lane) { sa[wid] = s; sb_[wid] = s2; }
    __syncthreads();
    if (threadIdx.x == 0) {
        float ts = 0.f, ts2 = 0.f;
#pragma unroll
        for (int i = 0; i < 8; i++) { ts += sa[i]; ts2 += sb_[i]; }
        sa[0] = ts; sb_[0] = ts2;
    }
    __syncthreads();
    const float mean = sa[0] * (1.f / CC);
    const float var  = sb_[0] * (1.f / CC) - mean * mean;
    const float rstd = rsqrtf(var + EPS_);
    float4* op = (float4*)(out + (size_t)row * CC);
#pragma unroll
    for (int it = 0; it < 2; it++) {
        const int i4 = threadIdx.x + it * 256;
        float4 q  = v[it];
        float4 gg = ((const float4*)g)[i4];
        float4 bq = ((const float4*)b)[i4];
        q.x = (q.x - mean) * rstd * gg.x + bq.x;
        q.y = (q.y - mean) * rstd * gg.y + bq.y;
        q.z = (q.z - mean) * rstd * gg.z + bq.z;
        q.w = (q.w - mean) * rstd * gg.w + bq.w;
        op[i4] = q;
    }
}

// ---------------- time-shift mixes (bf16 hi/lo outputs) ----------------
__global__ void mix4_kernel(const float* __restrict__ xl,
                            const float* __restrict__ mk, const float* __restrict__ mv,
                            const float* __restrict__ mr, const float* __restrict__ mg,
                            bf16* xkh, bf16* xkl, bf16* xvh, bf16* xvl,
                            bf16* xrh, bf16* xrl, bf16* xgh, bf16* xgl) {
    const size_t idx = (size_t)blockIdx.x * blockDim.x + threadIdx.x;
    const int c = (int)(idx & (CC - 1));
    const int t = (int)((idx >> 11) & (TT - 1));
    const float cur  = xl[idx];
    const float prev = (t > 0) ? xl[idx - CC] : 0.f;
    const float d = cur - prev;
    bf16 h, l;
    split2(prev + mk[c] * d, h, l); xkh[idx] = h; xkl[idx] = l;
    split2(prev + mv[c] * d, h, l); xvh[idx] = h; xvl[idx] = l;
    split2(prev + mr[c] * d, h, l); xrh[idx] = h; xrl[idx] = l;
    split2(prev + mg[c] * d, h, l); xgh[idx] = h; xgl[idx] = l;
}

__global__ void mix2_kernel(const float* __restrict__ xl,
                            const float* __restrict__ mk, const float* __restrict__ mr,
                            bf16* ckh, bf16* ckl, bf16* crh, bf16* crl) {
    const size_t idx = (size_t)blockIdx.x * blockDim.x + threadIdx.x;
    const int c = (int)(idx & (CC - 1));
    const int t = (int)((idx >> 11) & (TT - 1));
    const float cur  = xl[idx];
    const float prev = (t > 0) ? xl[idx - CC] : 0.f;
    const float d = cur - prev;
    bf16 h, l;
    split2(prev + mk[c] * d, h, l); ckh[idx] = h; ckl[idx] = l;
    split2(prev + mr[c] * d, h, l); crh[idx] = h; crl[idx] = l;
}

// ---------------- a_t = sum_i r_i * u_i * k_i ----------------
__global__ void adot_kernel(const float* __restrict__ r, const float* __restrict__ k,
                            const float* __restrict__ u, float* __restrict__ ab) {
    const int gid  = blockIdx.x * 8 + (threadIdx.x >> 5);
    const int lane = threadIdx.x & 31;
    const int h = gid & (HH - 1);
    const size_t off = (size_t)gid * NNH;
    float p = r[off + lane]      * u[h * NNH + lane]      * k[off + lane]
            + r[off + lane + 32] * u[h * NNH + lane + 32] * k[off + lane + 32];
#pragma unroll
    for (int o = 16; o; o >>= 1) p += __shfl_xor_sync(0xffffffffu, p, o);
    if (lane == 0) ab[gid] = p;
}

// ---------------- WKV5 recurrence ----------------
__global__ __launch_bounds__(128)
void wkv_kernel(const float* __restrict__ r, const float* __restrict__ k,
                const float* __restrict__ v, const float* __restrict__ w,
                const float* __restrict__ ab, float* __restrict__ att) {
    const int bh = blockIdx.x;
    const int b = bh / HH, h = bh % HH;
    const int tid = threadIdx.x;
    const int j = tid >> 1;
    const int p = tid & 1;
    __shared__ float sh_r[64], sh_k[64];
    float S[32], dec[32];
#pragma unroll
    for (int ii = 0; ii < 32; ii++) S[ii] = 0.f;
#pragma unroll
    for (int ii = 0; ii < 32; ii++) {
        const float wv = w[h * NNH + p * 32 + ii];
        dec[ii] = expf(-expf(wv));
    }
    for (int t = 0; t < TT; t++) {
        const size_t off = (((size_t)b * TT + t) * HH + h) * NNH;
        __syncthreads();
        if (tid < 64) sh_r[tid] = r[off + tid];
        else          sh_k[tid - 64] = k[off + tid - 64];
        __syncthreads();
        const float vj = v[off + j];
        const float at = ab[((size_t)b * TT + t) * HH + h];
        float yp = 0.f;
#pragma unroll
        for (int ii = 0; ii < 32; ii++) {
            const int i = p * 32 + ii;
            yp += sh_r[i] * S[ii];
            S[ii] = dec[ii] * S[ii] + sh_k[i] * vj;
        }
        const float y = yp + __shfl_xor_sync(0xffffffffu, yp, 1);
        if (p == 0) att[off + j] = at * vj + y;
    }
}

// ---------------- GroupNorm(att/DIV)*g+b, * gate, bf16 hi/lo out ----------
__global__ void gn_gate_kernel(const float* __restrict__ att, const float* __restrict__ gq,
                               const float* __restrict__ gg, const float* __restrict__ gb,
                               bf16* __restrict__ oh, bf16* __restrict__ ol) {
    const int gid  = blockIdx.x * 8 + (threadIdx.x >> 5);
    const int lane = threadIdx.x & 31;
    const int h = gid & (HH - 1);
    const size_t off = (size_t)gid * NNH;
    const float inv_div = 1.f / 8.f;
    const float v0 = att[off + lane]      * inv_div;
    const float v1 = att[off + lane + 32] * inv_div;
    float s = v0 + v1, s2 = v0 * v0 + v1 * v1;
#pragma unroll
    for (int o = 16; o; o >>= 1) {
        s  += __shfl_xor_sync(0xffffffffu, s,  o);
        s2 += __shfl_xor_sync(0xffffffffu, s2, o);
    }
    const float m = s * (1.f / NNH);
    const float var = s2 * (1.f / NNH) - m * m;
    const float rstd = rsqrtf(var + EPS_);
    const int c0 = h * NNH + lane;
    const float o0 = ((v0 - m) * rstd * gg[c0]      + gb[c0])      * gq[off + lane];
    const float o1 = ((v1 - m) * rstd * gg[c0 + 32] + gb[c0 + 32]) * gq[off + lane + 32];
    bf16 hh, ll;
    split2(o0, hh, ll); oh[off + lane]      = hh; ol[off + lane]      = ll;
    split2(o1, hh, ll); oh[off + lane + 32] = hh; ol[off + lane + 32] = ll;
}

// ---------------- launch ----------------
extern "C" void kernel_launch(void* const* d_in, const int* in_sizes, int n_in,
                              void* d_out, int out_size) {
    (void)in_sizes; (void)n_in; (void)out_size;
    const float* x     = (const float*)d_in[0];
    const float* ln1_g = (const float*)d_in[1];
    const float* ln1_b = (const float*)d_in[2];
    const float* ln2_g = (const float*)d_in[3];
    const float* ln2_b = (const float*)d_in[4];
    const float* tm_k  = (const float*)d_in[5];
    const float* tm_v  = (const float*)d_in[6];
    const float* tm_r  = (const float*)d_in[7];
    const float* tm_g  = (const float*)d_in[8];
    const float* tdec  = (const float*)d_in[9];
    const float* tfaa  = (const float*)d_in[10];
    const float* Wr    = (const float*)d_in[11];
    const float* Wk    = (const float*)d_in[12];
    const float* Wv    = (const float*)d_in[13];
    const float* Wg    = (const float*)d_in[14];
    const float* Wo    = (const float*)d_in[15];
    const float* lnx_g = (const float*)d_in[16];
    const float* lnx_b = (const float*)d_in[17];
    const float* fm_k  = (const float*)d_in[18];
    const float* fm_r  = (const float*)d_in[19];
    const float* Wkey  = (const float*)d_in[20];
    const float* Wrec  = (const float*)d_in[21];
    const float* Wval  = (const float*)d_in[22];
    float* out = (float*)d_out;

    float *XL, *Rb, *Kb, *Vb, *Gb, *ATT, *X1, *XL2, *KV, *AB;
    cudaGetSymbolAddress((void**)&XL,  g_XL);
    cudaGetSymbolAddress((void**)&Rb,  g_R);
    cudaGetSymbolAddress((void**)&Kb,  g_K);
    cudaGetSymbolAddress((void**)&Vb,  g_V);
    cudaGetSymbolAddress((void**)&Gb,  g_G);
    cudaGetSymbolAddress((void**)&ATT, g_ATT);
    cudaGetSymbolAddress((void**)&X1,  g_X1);
    cudaGetSymbolAddress((void**)&XL2, g_XL2);
    cudaGetSymbolAddress((void**)&KV,  g_KV);
    cudaGetSymbolAddress((void**)&AB,  g_AB);

    bf16 *XRh,*XRl,*XKh,*XKl,*XVh,*XVl,*XGh,*XGl,*AGh,*AGl,*CKh,*CKl,*CRh,*CRl,*KKh,*KKl;
    cudaGetSymbolAddress((void**)&XRh, g_XRh); cudaGetSymbolAddress((void**)&XRl, g_XRl);
    cudaGetSymbolAddress((void**)&XKh, g_XKh); cudaGetSymbolAddress((void**)&XKl, g_XKl);
    cudaGetSymbolAddress((void**)&XVh, g_XVh); cudaGetSymbolAddress((void**)&XVl, g_XVl);
    cudaGetSymbolAddress((void**)&XGh, g_XGh); cudaGetSymbolAddress((void**)&XGl, g_XGl);
    cudaGetSymbolAddress((void**)&AGh, g_AGh); cudaGetSymbolAddress((void**)&AGl, g_AGl);
    cudaGetSymbolAddress((void**)&CKh, g_CKh); cudaGetSymbolAddress((void**)&CKl, g_CKl);
    cudaGetSymbolAddress((void**)&CRh, g_CRh); cudaGetSymbolAddress((void**)&CRl, g_CRl);
    cudaGetSymbolAddress((void**)&KKh, g_KKh); cudaGetSymbolAddress((void**)&KKl, g_KKl);

    bf16 *WrTh,*WrTl,*WkTh,*WkTl,*WvTh,*WvTl,*WgTh,*WgTl,*WoTh,*WoTl,*WreTh,*WreTl,*WkeyTh,*WkeyTl,*WvalTh,*WvalTl;
    cudaGetSymbolAddress((void**)&WrTh, g_WrTh);   cudaGetSymbolAddress((void**)&WrTl, g_WrTl);
    cudaGetSymbolAddress((void**)&WkTh, g_WkTh);   cudaGetSymbolAddress((void**)&WkTl, g_WkTl);
    cudaGetSymbolAddress((void**)&WvTh, g_WvTh);   cudaGetSymbolAddress((void**)&WvTl, g_WvTl);
    cudaGetSymbolAddress((void**)&WgTh, g_WgTh);   cudaGetSymbolAddress((void**)&WgTl, g_WgTl);
    cudaGetSymbolAddress((void**)&WoTh, g_WoTh);   cudaGetSymbolAddress((void**)&WoTl, g_WoTl);
    cudaGetSymbolAddress((void**)&WreTh, g_WreTh); cudaGetSymbolAddress((void**)&WreTl, g_WreTl);
    cudaGetSymbolAddress((void**)&WkeyTh, g_WkeyTh); cudaGetSymbolAddress((void**)&WkeyTl, g_WkeyTl);
    cudaGetSymbolAddress((void**)&WvalTh, g_WvalTh); cudaGetSymbolAddress((void**)&WvalTl, g_WvalTl);

    cudaFuncSetAttribute(mmagemm<0>, cudaFuncAttributeMaxDynamicSharedMemorySize, GEMM_SMEM);
    cudaFuncSetAttribute(mmagemm<1>, cudaFuncAttributeMaxDynamicSharedMemorySize, GEMM_SMEM);
    cudaFuncSetAttribute(mmagemm<2>, cudaFuncAttributeMaxDynamicSharedMemorySize, GEMM_SMEM);
    cudaFuncSetAttribute(mmagemm<3>, cudaFuncAttributeMaxDynamicSharedMemorySize, GEMM_SMEM);
    cudaFuncSetAttribute(mmagemm<4>, cudaFuncAttributeMaxDynamicSharedMemorySize, GEMM_SMEM);

    const dim3 tb(32, 8);
    transpose_split_k<<<dim3(CC / 32,  CC / 32),  tb>>>(Wr,   WrTh,  WrTl,  CC,  CC);
    transpose_split_k<<<dim3(CC / 32,  CC / 32),  tb>>>(Wk,   WkTh,  WkTl,  CC,  CC);
    transpose_split_k<<<dim3(CC / 32,  CC / 32),  tb>>>(Wv,   WvTh,  WvTl,  CC,  CC);
    transpose_split_k<<<dim3(CC / 32,  CC / 32),  tb>>>(Wg,   WgTh,  WgTl,  CC,  CC);
    transpose_split_k<<<dim3(CC / 32,  CC / 32),  tb>>>(Wo,   WoTh,  WoTl,  CC,  CC);
    transpose_split_k<<<dim3(CC / 32,  CC / 32),  tb>>>(Wrec, WreTh, WreTl, CC,  CC);
    transpose_split_k<<<dim3(FFD / 32, CC / 32),  tb>>>(Wkey, WkeyTh, WkeyTl, CC,  FFD);
    transpose_split_k<<<dim3(CC / 32,  FFD / 32), tb>>>(Wval, WvalTh, WvalTl, FFD, CC);

    const dim3 gCC(CC / 128, BT / 128);    // (16,16)
    const dim3 gFF(FFD / 128, BT / 128);   // (64,16)

    // attention half
    ln_kernel<<<BT, 256>>>(x, ln1_g, ln1_b, XL);
    mix4_kernel<<<BT * CC / 256, 256>>>(XL, tm_k, tm_v, tm_r, tm_g,
                                        XKh, XKl, XVh, XVl, XRh, XRl, XGh, XGl);
    mmagemm<0><<<gCC, 256, GEMM_SMEM>>>(XRh, XRl, WrTh, WrTl, Rb, nullptr, nullptr, BT, CC, CC, nullptr, nullptr);
    mmagemm<0><<<gCC, 256, GEMM_SMEM>>>(XKh, XKl, WkTh, WkTl, Kb, nullptr, nullptr, BT, CC, CC, nullptr, nullptr);
    mmagemm<0><<<gCC, 256, GEMM_SMEM>>>(XVh, XVl, WvTh, WvTl, Vb, nullptr, nullptr, BT, CC, CC, nullptr, nullptr);
    mmagemm<1><<<gCC, 256, GEMM_SMEM>>>(XGh, XGl, WgTh, WgTl, Gb, nullptr, nullptr, BT, CC, CC, nullptr, nullptr);
    adot_kernel<<<BT * HH / 8, 256>>>(Rb, Kb, tfaa, AB);
    wkv_kernel<<<BB * HH, 128>>>(Rb, Kb, Vb, tdec, AB, ATT);
    gn_gate_kernel<<<BT * HH / 8, 256>>>(ATT, Gb, lnx_g, lnx_b, AGh, AGl);
    mmagemm<3><<<gCC, 256, GEMM_SMEM>>>(AGh, AGl, WoTh, WoTl, X1, nullptr, nullptr, BT, CC, CC, x, nullptr);

    // FFN half
    ln_kernel<<<BT, 256>>>(X1, ln2_g, ln2_b, XL2);
    mix2_kernel<<<BT * CC / 256, 256>>>(XL2, fm_k, fm_r, CKh, CKl, CRh, CRl);
    mmagemm<2><<<gFF, 256, GEMM_SMEM>>>(CKh, CKl, WkeyTh, WkeyTl, nullptr, KKh, KKl, BT, FFD, CC, nullptr, nullptr);
    mmagemm<0><<<gCC, 256, GEMM_SMEM>>>(KKh, KKl, WvalTh, WvalTl, KV, nullptr, nullptr, BT, CC, FFD, nullptr, nullptr);
    mmagemm<4><<<gCC, 256, GEMM_SMEM>>>(CRh, CRl, WreTh, WreTl, out, nullptr, nullptr, BT, CC, CC, X1, KV);
}

// round 8
// speedup vs baseline: 2.7906x; 1.2820x over previous
#include <cuda_runtime.h>
#include <cuda_fp16.h>
#include <math.h>
#include <stdint.h>

#define BB 2
#define TT 1024
#define CC 2048
#define HH 32
#define NNH 64
#define FFD 8192
#define BT (BB*TT)
#define EPS_ 1e-5f

typedef __half h16;

// ---------------- scratch (device globals; allocation-free) ----------------
__device__ float g_XL [BT*CC];
__device__ float g_R  [BT*CC];
__device__ float g_K  [BT*CC];
__device__ float g_V  [BT*CC];
__device__ float g_G  [BT*CC];
__device__ float g_ATT[BT*CC];
__device__ float g_X1 [BT*CC];
__device__ float g_XL2[BT*CC];
__device__ float g_KV [BT*CC];
__device__ float g_AB [BT*HH];

__device__ h16 g_XRh[BT*CC], g_XRl[BT*CC], g_XKh[BT*CC], g_XKl[BT*CC];
__device__ h16 g_XVh[BT*CC], g_XVl[BT*CC], g_XGh[BT*CC], g_XGl[BT*CC];
__device__ h16 g_AGh[BT*CC], g_AGl[BT*CC];
__device__ h16 g_CKh[BT*CC], g_CKl[BT*CC], g_CRh[BT*CC], g_CRl[BT*CC];
__device__ h16 g_KKh[(size_t)BT*FFD], g_KKl[(size_t)BT*FFD];

__device__ h16 g_WrT [CC*CC];
__device__ h16 g_WkT [CC*CC];
__device__ h16 g_WvT [CC*CC];
__device__ h16 g_WgT [CC*CC];
__device__ h16 g_WoT [CC*CC];
__device__ h16 g_WreT[CC*CC];
__device__ h16 g_WkeyT[(size_t)FFD*CC];
__device__ h16 g_WvalT[(size_t)CC*FFD];

// ---------------- helpers ----------------
__device__ __forceinline__ uint32_t s2u(const void* p) {
    uint32_t r;
    asm("{ .reg .u64 t; cvta.to.shared.u64 t, %1; cvt.u32.u64 %0, t; }" : "=r"(r) : "l"(p));
    return r;
}
#define CP_COMMIT() asm volatile("cp.async.commit_group;" ::: "memory")
#define CP_WAIT(n)  asm volatile("cp.async.wait_group %0;" :: "n"(n) : "memory")
__device__ __forceinline__ void cp16(uint32_t s, const void* g) {
    asm volatile("cp.async.cg.shared.global [%0], [%1], 16;" :: "r"(s), "l"(g));
}
__device__ __forceinline__ void ldm4(uint32_t* r, uint32_t a) {
    asm volatile("ldmatrix.sync.aligned.m8n8.x4.shared.b16 {%0,%1,%2,%3}, [%4];"
        : "=r"(r[0]), "=r"(r[1]), "=r"(r[2]), "=r"(r[3]) : "r"(a));
}
__device__ __forceinline__ void mma16816(float* d, const uint32_t* a, const uint32_t* b) {
    asm volatile(
        "mma.sync.aligned.m16n8k16.row.col.f32.f16.f16.f32 "
        "{%0,%1,%2,%3}, {%4,%5,%6,%7}, {%8,%9}, {%0,%1,%2,%3};"
        : "+f"(d[0]), "+f"(d[1]), "+f"(d[2]), "+f"(d[3])
        : "r"(a[0]), "r"(a[1]), "r"(a[2]), "r"(a[3]), "r"(b[0]), "r"(b[1]));
}
// 64B-row swizzle: XOR 16B-unit index (bits 4-5) with row-pair (bits 7-8)
__device__ __forceinline__ uint32_t SW64(uint32_t o) { return o ^ ((o >> 3) & 0x30); }

__device__ __forceinline__ void split2h(float v, h16& h, h16& l) {
    h = __float2half_rn(v);
    l = __float2half_rn(v - __half2float(h));
}

// ---------------- transpose + fp16 round:  W[K,N] -> Wt[N,K] ----------------
__global__ void transpose_h_k(const float* __restrict__ W, h16* __restrict__ th,
                              int K, int N) {
    __shared__ float t[32][33];
    const int k0 = blockIdx.y * 32, n0 = blockIdx.x * 32;
#pragma unroll
    for (int i = 0; i < 4; i++)
        t[threadIdx.y + i * 8][threadIdx.x] =
            W[(size_t)(k0 + threadIdx.y + i * 8) * N + n0 + threadIdx.x];
    __syncthreads();
#pragma unroll
    for (int i = 0; i < 4; i++) {
        const float v = t[threadIdx.x][threadIdx.y + i * 8];
        const size_t o = (size_t)(n0 + threadIdx.y + i * 8) * K + k0 + threadIdx.x;
        th[o] = __float2half_rn(v);
    }
}

// ---------------- mma.sync GEMM: D = A @ B^T, 2-pass FP16 ------------------
// A: [M,K] hi/lo fp16 (exact sum); B: [N,K] single fp16.
// Block 128x128, BK=32, 3 cp.async stages. 8 warps: 2x4, warp tile 64x32.
// EPI: 0 fp32 | 1 silu | 2 relu^2 -> fp16 hi/lo | 3 aux1+acc | 4 aux1+sigmoid(acc)*aux2
#define OFF_AH 0
#define OFF_AL 8192
#define OFF_BH 16384
#define STG    24576
#define GEMM_SMEM (3 * STG)

template <int EPI>
__global__ __launch_bounds__(256, 1)
void mmagemm(const h16* __restrict__ Ah, const h16* __restrict__ Al,
             const h16* __restrict__ Bh,
             float* __restrict__ C, h16* __restrict__ Ch, h16* __restrict__ Cl,
             int M, int N, int K,
             const float* __restrict__ aux1, const float* __restrict__ aux2) {
    extern __shared__ __align__(1024) char smem[];
    const uint32_t sb = s2u(smem);
    const int tid = threadIdx.x;
    const int row0 = blockIdx.y * 128;
    const int col0 = blockIdx.x * 128;
    const int NK = K / 32;

    // ---- staging maps: 512 16B-transfers per 8KB matrix, 2 per thread ----
    const int r0 = tid >> 2, c0 = tid & 3;
    const int r1 = (tid + 256) >> 2, c1 = tid & 3;
    const uint32_t so0 = SW64((uint32_t)(r0 * 64 + c0 * 16));
    const uint32_t so1 = SW64((uint32_t)(r1 * 64 + c1 * 16));
    const h16* pAh0 = Ah + (size_t)(row0 + r0) * K + c0 * 8;
    const h16* pAh1 = Ah + (size_t)(row0 + r1) * K + c1 * 8;
    const h16* pAl0 = Al + (size_t)(row0 + r0) * K + c0 * 8;
    const h16* pAl1 = Al + (size_t)(row0 + r1) * K + c1 * 8;
    const h16* pBh0 = Bh + (size_t)(col0 + r0) * K + c0 * 8;
    const h16* pBh1 = Bh + (size_t)(col0 + r1) * K + c1 * 8;

    auto load_stage = [&](int kb, int st) {
        const uint32_t s = sb + (uint32_t)st * STG;
        const size_t ko = (size_t)kb * 32;
        cp16(s + OFF_AH + so0, pAh0 + ko); cp16(s + OFF_AH + so1, pAh1 + ko);
        cp16(s + OFF_AL + so0, pAl0 + ko); cp16(s + OFF_AL + so1, pAl1 + ko);
        cp16(s + OFF_BH + so0, pBh0 + ko); cp16(s + OFF_BH + so1, pBh1 + ko);
        CP_COMMIT();
    };

    // ---- per-warp fragment addressing ----
    const int wid = tid >> 5, lane = tid & 31;
    const int wm = wid & 1, wn = wid >> 1;
    const int wmb = wm * 64, wnb = wn * 32;
    const uint32_t a_row  = (uint32_t)(wmb + (lane & 15));
    const uint32_t a_csel = (uint32_t)((lane >> 4) << 4);
    const uint32_t b_row  = (uint32_t)(wnb + ((lane >> 4) << 3) + (lane & 7));
    const uint32_t b_csel = (uint32_t)(((lane >> 3) & 1) << 4);

    float acc[4][4][4];
#pragma unroll
    for (int i = 0; i < 4; i++)
#pragma unroll
        for (int j = 0; j < 4; j++)
#pragma unroll
            for (int q = 0; q < 4; q++) acc[i][j][q] = 0.f;

    // ---- pipeline ----
    load_stage(0, 0);
    if (NK > 1) load_stage(1, 1);

#pragma unroll 1
    for (int kb = 0; kb < NK; kb++) {
        if (kb + 2 < NK) { load_stage(kb + 2, (kb + 2) % 3); CP_WAIT(2); }
        else if (kb + 1 < NK) { CP_WAIT(1); }
        else { CP_WAIT(0); }
        __syncthreads();

        const uint32_t us = sb + (uint32_t)(kb % 3) * STG;
#pragma unroll
        for (int ks = 0; ks < 2; ks++) {
            uint32_t ah[4][4], al[4][4], bh[2][4];
#pragma unroll
            for (int mt = 0; mt < 4; mt++) {
                const uint32_t off = (a_row + mt * 16) * 64 + (uint32_t)(ks * 32) + a_csel;
                ldm4(ah[mt], us + OFF_AH + SW64(off));
                ldm4(al[mt], us + OFF_AL + SW64(off));
            }
#pragma unroll
            for (int bp = 0; bp < 2; bp++) {
                const uint32_t off = (b_row + bp * 16) * 64 + (uint32_t)(ks * 32) + b_csel;
                ldm4(bh[bp], us + OFF_BH + SW64(off));
            }
#pragma unroll
            for (int mt = 0; mt < 4; mt++)
#pragma unroll
                for (int nt = 0; nt < 4; nt++) {
                    const uint32_t* bhp = &bh[nt >> 1][(nt & 1) * 2];
                    mma16816(acc[mt][nt], ah[mt], bhp);
                    mma16816(acc[mt][nt], al[mt], bhp);
                }
        }
        __syncthreads();
    }

    // ---- epilogue (register accumulators) ----
    const int mrow = row0 + wmb + (lane >> 2);
    const int ncol = col0 + wnb + (lane & 3) * 2;
#pragma unroll
    for (int mt = 0; mt < 4; mt++) {
#pragma unroll
        for (int half = 0; half < 2; half++) {
            const size_t m = (size_t)(mrow + mt * 16 + half * 8);
#pragma unroll
            for (int nt = 0; nt < 4; nt++) {
                float vx = acc[mt][nt][half * 2 + 0];
                float vy = acc[mt][nt][half * 2 + 1];
                const size_t idx = m * N + (ncol + nt * 8);
                if (EPI == 1) {
                    vx /= (1.f + expf(-vx)); vy /= (1.f + expf(-vy));
                } else if (EPI == 3) {
                    vx += aux1[idx]; vy += aux1[idx + 1];
                } else if (EPI == 4) {
                    vx = aux1[idx]     + aux2[idx]     / (1.f + expf(-vx));
                    vy = aux1[idx + 1] + aux2[idx + 1] / (1.f + expf(-vy));
                }
                if (EPI == 2) {
                    vx = fmaxf(vx, 0.f); vx *= vx;
                    vy = fmaxf(vy, 0.f); vy *= vy;
                    h16 hx, lx, hy, ly;
                    split2h(vx, hx, lx); split2h(vy, hy, ly);
                    __half2 hp, lp;
                    hp.x = hx; hp.y = hy; lp.x = lx; lp.y = ly;
                    *(__half2*)&Ch[idx] = hp;
                    *(__half2*)&Cl[idx] = lp;
                } else {
                    float2 p; p.x = vx; p.y = vy;
                    *(float2*)&C[idx] = p;
                }
            }
        }
    }
}

// ---------------- LayerNorm over last dim (C=2048), one block per row ------
__global__ void ln_kernel(const float* __restrict__ x, const float* __restrict__ g,
                          const float* __restrict__ b, float* __restrict__ out) {
    __shared__ float sa[8], sb_[8];
    const int row = blockIdx.x;
    const float4* xr = (const float4*)(x + (size_t)row * CC);
    float4 v[2];
    float s = 0.f, s2 = 0.f;
#pragma unroll
    for (int it = 0; it < 2; it++) {
        float4 q = xr[threadIdx.x + it * 256];
        v[it] = q;
        s  += q.x + q.y + q.z + q.w;
        s2 += q.x*q.x + q.y*q.y + q.z*q.z + q.w*q.w;
    }
#pragma unroll
    for (int o = 16; o; o >>= 1) {
        s  += __shfl_xor_sync(0xffffffffu, s,  o);
        s2 += __shfl_xor_sync(0xffffffffu, s2, o);
    }
    const int wid = threadIdx.x >> 5, lane = threadIdx.x & 31;
    if (!lane) { sa[wid] = s; sb_[wid] = s2; }
    __syncthreads();
    if (threadIdx.x == 0) {
        float ts = 0.f, ts2 = 0.f;
#pragma unroll
        for (int i = 0; i < 8; i++) { ts += sa[i]; ts2 += sb_[i]; }
        sa[0] = ts; sb_[0] = ts2;
    }
    __syncthreads();
    const float mean = sa[0] * (1.f / CC);
    const float var  = sb_[0] * (1.f / CC) - mean * mean;
    const float rstd = rsqrtf(var + EPS_);
    float4* op = (float4*)(out + (size_t)row * CC);
#pragma unroll
    for (int it = 0; it < 2; it++) {
        const int i4 = threadIdx.x + it * 256;
        float4 q  = v[it];
        float4 gg = ((const float4*)g)[i4];
        float4 bq = ((const float4*)b)[i4];
        q.x = (q.x - mean) * rstd * gg.x + bq.x;
        q.y = (q.y - mean) * rstd * gg.y + bq.y;
        q.z = (q.z - mean) * rstd * gg.z + bq.z;
        q.w = (q.w - mean) * rstd * gg.w + bq.w;
        op[i4] = q;
    }
}

// ---------------- time-shift mixes (fp16 hi/lo outputs) ----------------
__global__ void mix4_kernel(const float* __restrict__ xl,
                            const float* __restrict__ mk, const float* __restrict__ mv,
                            const float* __restrict__ mr, const float* __restrict__ mg,
                            h16* xkh, h16* xkl, h16* xvh, h16* xvl,
                            h16* xrh, h16* xrl, h16* xgh, h16* xgl) {
    const size_t idx = (size_t)blockIdx.x * blockDim.x + threadIdx.x;
    const int c = (int)(idx & (CC - 1));
    const int t = (int)((idx >> 11) & (TT - 1));
    const float cur  = xl[idx];
    const float prev = (t > 0) ? xl[idx - CC] : 0.f;
    const float d = cur - prev;
    h16 h, l;
    split2h(prev + mk[c] * d, h, l); xkh[idx] = h; xkl[idx] = l;
    split2h(prev + mv[c] * d, h, l); xvh[idx] = h; xvl[idx] = l;
    split2h(prev + mr[c] * d, h, l); xrh[idx] = h; xrl[idx] = l;
    split2h(prev + mg[c] * d, h, l); xgh[idx] = h; xgl[idx] = l;
}

__global__ void mix2_kernel(const float* __restrict__ xl,
                            const float* __restrict__ mk, const float* __restrict__ mr,
                            h16* ckh, h16* ckl, h16* crh, h16* crl) {
    const size_t idx = (size_t)blockIdx.x * blockDim.x + threadIdx.x;
    const int c = (int)(idx & (CC - 1));
    const int t = (int)((idx >> 11) & (TT - 1));
    const float cur  = xl[idx];
    const float prev = (t > 0) ? xl[idx - CC] : 0.f;
    const float d = cur - prev;
    h16 h, l;
    split2h(prev + mk[c] * d, h, l); ckh[idx] = h; ckl[idx] = l;
    split2h(prev + mr[c] * d, h, l); crh[idx] = h; crl[idx] = l;
}

// ---------------- a_t = sum_i r_i * u_i * k_i ----------------
__global__ void adot_kernel(const float* __restrict__ r, const float* __restrict__ k,
                            const float* __restrict__ u, float* __restrict__ ab) {
    const int gid  = blockIdx.x * 8 + (threadIdx.x >> 5);
    const int lane = threadIdx.x & 31;
    const int h = gid & (HH - 1);
    const size_t off = (size_t)gid * NNH;
    float p = r[off + lane]      * u[h * NNH + lane]      * k[off + lane]
            + r[off + lane + 32] * u[h * NNH + lane + 32] * k[off + lane + 32];
#pragma unroll
    for (int o = 16; o; o >>= 1) p += __shfl_xor_sync(0xffffffffu, p, o);
    if (lane == 0) ab[gid] = p;
}

// ---------------- WKV5 recurrence ----------------
__global__ __launch_bounds__(128)
void wkv_kernel(const float* __restrict__ r, const float* __restrict__ k,
                const float* __restrict__ v, const float* __restrict__ w,
                const float* __restrict__ ab, float* __restrict__ att) {
    const int bh = blockIdx.x;
    const int b = bh / HH, h = bh % HH;
    const int tid = threadIdx.x;
    const int j = tid >> 1;
    const int p = tid & 1;
    __shared__ float sh_r[64], sh_k[64];
    float S[32], dec[32];
#pragma unroll
    for (int ii = 0; ii < 32; ii++) S[ii] = 0.f;
#pragma unroll
    for (int ii = 0; ii < 32; ii++) {
        const float wv = w[h * NNH + p * 32 + ii];
        dec[ii] = expf(-expf(wv));
    }
    for (int t = 0; t < TT; t++) {
        const size_t off = (((size_t)b * TT + t) * HH + h) * NNH;
        __syncthreads();
        if (tid < 64) sh_r[tid] = r[off + tid];
        else          sh_k[tid - 64] = k[off + tid - 64];
        __syncthreads();
        const float vj = v[off + j];
        const float at = ab[((size_t)b * TT + t) * HH + h];
        float yp = 0.f;
#pragma unroll
        for (int ii = 0; ii < 32; ii++) {
            const int i = p * 32 + ii;
            yp += sh_r[i] * S[ii];
            S[ii] = dec[ii] * S[ii] + sh_k[i] * vj;
        }
        const float y = yp + __shfl_xor_sync(0xffffffffu, yp, 1);
        if (p == 0) att[off + j] = at * vj + y;
    }
}

// ---------------- GroupNorm(att/DIV)*g+b, * gate, fp16 hi/lo out ----------
__global__ void gn_gate_kernel(const float* __restrict__ att, const float* __restrict__ gq,
                               const float* __restrict__ gg, const float* __restrict__ gb,
                               h16* __restrict__ oh, h16* __restrict__ ol) {
    const int gid  = blockIdx.x * 8 + (threadIdx.x >> 5);
    const int lane = threadIdx.x & 31;
    const int h = gid & (HH - 1);
    const size_t off = (size_t)gid * NNH;
    const float inv_div = 1.f / 8.f;
    const float v0 = att[off + lane]      * inv_div;
    const float v1 = att[off + lane + 32] * inv_div;
    float s = v0 + v1, s2 = v0 * v0 + v1 * v1;
#pragma unroll
    for (int o = 16; o; o >>= 1) {
        s  += __shfl_xor_sync(0xffffffffu, s,  o);
        s2 += __shfl_xor_sync(0xffffffffu, s2, o);
    }
    const float m = s * (1.f / NNH);
    const float var = s2 * (1.f / NNH) - m * m;
    const float rstd = rsqrtf(var + EPS_);
    const int c0 = h * NNH + lane;
    const float o0 = ((v0 - m) * rstd * gg[c0]      + gb[c0])      * gq[off + lane];
    const float o1 = ((v1 - m) * rstd * gg[c0 + 32] + gb[c0 + 32]) * gq[off + lane + 32];
    h16 hh, ll;
    split2h(o0, hh, ll); oh[off + lane]      = hh; ol[off + lane]      = ll;
    split2h(o1, hh, ll); oh[off + lane + 32] = hh; ol[off + lane + 32] = ll;
}

// ---------------- launch ----------------
extern "C" void kernel_launch(void* const* d_in, const int* in_sizes, int n_in,
                              void* d_out, int out_size) {
    (void)in_sizes; (void)n_in; (void)out_size;
    const float* x     = (const float*)d_in[0];
    const float* ln1_g = (const float*)d_in[1];
    const float* ln1_b = (const float*)d_in[2];
    const float* ln2_g = (const float*)d_in[3];
    const float* ln2_b = (const float*)d_in[4];
    const float* tm_k  = (const float*)d_in[5];
    const float* tm_v  = (const float*)d_in[6];
    const float* tm_r  = (const float*)d_in[7];
    const float* tm_g  = (const float*)d_in[8];
    const float* tdec  = (const float*)d_in[9];
    const float* tfaa  = (const float*)d_in[10];
    const float* Wr    = (const float*)d_in[11];
    const float* Wk    = (const float*)d_in[12];
    const float* Wv    = (const float*)d_in[13];
    const float* Wg    = (const float*)d_in[14];
    const float* Wo    = (const float*)d_in[15];
    const float* lnx_g = (const float*)d_in[16];
    const float* lnx_b = (const float*)d_in[17];
    const float* fm_k  = (const float*)d_in[18];
    const float* fm_r  = (const float*)d_in[19];
    const float* Wkey  = (const float*)d_in[20];
    const float* Wrec  = (const float*)d_in[21];
    const float* Wval  = (const float*)d_in[22];
    float* out = (float*)d_out;

    float *XL, *Rb, *Kb, *Vb, *Gb, *ATT, *X1, *XL2, *KV, *AB;
    cudaGetSymbolAddress((void**)&XL,  g_XL);
    cudaGetSymbolAddress((void**)&Rb,  g_R);
    cudaGetSymbolAddress((void**)&Kb,  g_K);
    cudaGetSymbolAddress((void**)&Vb,  g_V);
    cudaGetSymbolAddress((void**)&Gb,  g_G);
    cudaGetSymbolAddress((void**)&ATT, g_ATT);
    cudaGetSymbolAddress((void**)&X1,  g_X1);
    cudaGetSymbolAddress((void**)&XL2, g_XL2);
    cudaGetSymbolAddress((void**)&KV,  g_KV);
    cudaGetSymbolAddress((void**)&AB,  g_AB);

    h16 *XRh,*XRl,*XKh,*XKl,*XVh,*XVl,*XGh,*XGl,*AGh,*AGl,*CKh,*CKl,*CRh,*CRl,*KKh,*KKl;
    cudaGetSymbolAddress((void**)&XRh, g_XRh); cudaGetSymbolAddress((void**)&XRl, g_XRl);
    cudaGetSymbolAddress((void**)&XKh, g_XKh); cudaGetSymbolAddress((void**)&XKl, g_XKl);
    cudaGetSymbolAddress((void**)&XVh, g_XVh); cudaGetSymbolAddress((void**)&XVl, g_XVl);
    cudaGetSymbolAddress((void**)&XGh, g_XGh); cudaGetSymbolAddress((void**)&XGl, g_XGl);
    cudaGetSymbolAddress((void**)&AGh, g_AGh); cudaGetSymbolAddress((void**)&AGl, g_AGl);
    cudaGetSymbolAddress((void**)&CKh, g_CKh); cudaGetSymbolAddress((void**)&CKl, g_CKl);
    cudaGetSymbolAddress((void**)&CRh, g_CRh); cudaGetSymbolAddress((void**)&CRl, g_CRl);
    cudaGetSymbolAddress((void**)&KKh, g_KKh); cudaGetSymbolAddress((void**)&KKl, g_KKl);

    h16 *WrT,*WkT,*WvT,*WgT,*WoT,*WreT,*WkeyT,*WvalT;
    cudaGetSymbolAddress((void**)&WrT,   g_WrT);
    cudaGetSymbolAddress((void**)&WkT,   g_WkT);
    cudaGetSymbolAddress((void**)&WvT,   g_WvT);
    cudaGetSymbolAddress((void**)&WgT,   g_WgT);
    cudaGetSymbolAddress((void**)&WoT,   g_WoT);
    cudaGetSymbolAddress((void**)&WreT,  g_WreT);
    cudaGetSymbolAddress((void**)&WkeyT, g_WkeyT);
    cudaGetSymbolAddress((void**)&WvalT, g_WvalT);

    cudaFuncSetAttribute(mmagemm<0>, cudaFuncAttributeMaxDynamicSharedMemorySize, GEMM_SMEM);
    cudaFuncSetAttribute(mmagemm<1>, cudaFuncAttributeMaxDynamicSharedMemorySize, GEMM_SMEM);
    cudaFuncSetAttribute(mmagemm<2>, cudaFuncAttributeMaxDynamicSharedMemorySize, GEMM_SMEM);
    cudaFuncSetAttribute(mmagemm<3>, cudaFuncAttributeMaxDynamicSharedMemorySize, GEMM_SMEM);
    cudaFuncSetAttribute(mmagemm<4>, cudaFuncAttributeMaxDynamicSharedMemorySize, GEMM_SMEM);

    const dim3 tb(32, 8);
    transpose_h_k<<<dim3(CC / 32,  CC / 32),  tb>>>(Wr,   WrT,   CC,  CC);
    transpose_h_k<<<dim3(CC / 32,  CC / 32),  tb>>>(Wk,   WkT,   CC,  CC);
    transpose_h_k<<<dim3(CC / 32,  CC / 32),  tb>>>(Wv,   WvT,   CC,  CC);
    transpose_h_k<<<dim3(CC / 32,  CC / 32),  tb>>>(Wg,   WgT,   CC,  CC);
    transpose_h_k<<<dim3(CC / 32,  CC / 32),  tb>>>(Wo,   WoT,   CC,  CC);
    transpose_h_k<<<dim3(CC / 32,  CC / 32),  tb>>>(Wrec, WreT,  CC,  CC);
    transpose_h_k<<<dim3(FFD / 32, CC / 32),  tb>>>(Wkey, WkeyT, CC,  FFD);
    transpose_h_k<<<dim3(CC / 32,  FFD / 32), tb>>>(Wval, WvalT, FFD, CC);

    const dim3 gCC(CC / 128, BT / 128);    // (16,16)
    const dim3 gFF(FFD / 128, BT / 128);   // (64,16)

    // attention half
    ln_kernel<<<BT, 256>>>(x, ln1_g, ln1_b, XL);
    mix4_kernel<<<BT * CC / 256, 256>>>(XL, tm_k, tm_v, tm_r, tm_g,
                                        XKh, XKl, XVh, XVl, XRh, XRl, XGh, XGl);
    mmagemm<0><<<gCC, 256, GEMM_SMEM>>>(XRh, XRl, WrT, Rb, nullptr, nullptr, BT, CC, CC, nullptr, nullptr);
    mmagemm<0><<<gCC, 256, GEMM_SMEM>>>(XKh, XKl, WkT, Kb, nullptr, nullptr, BT, CC, CC, nullptr, nullptr);
    mmagemm<0><<<gCC, 256, GEMM_SMEM>>>(XVh, XVl, WvT, Vb, nullptr, nullptr, BT, CC, CC, nullptr, nullptr);
    mmagemm<1><<<gCC, 256, GEMM_SMEM>>>(XGh, XGl, WgT, Gb, nullptr, nullptr, BT, CC, CC, nullptr, nullptr);
    adot_kernel<<<BT * HH / 8, 256>>>(Rb, Kb, tfaa, AB);
    wkv_kernel<<<BB * HH, 128>>>(Rb, Kb, Vb, tdec, AB, ATT);
    gn_gate_kernel<<<BT * HH / 8, 256>>>(ATT, Gb, lnx_g, lnx_b, AGh, AGl);
    mmagemm<3><<<gCC, 256, GEMM_SMEM>>>(AGh, AGl, WoT, X1, nullptr, nullptr, BT, CC, CC, x, nullptr);

    // FFN half
    ln_kernel<<<BT, 256>>>(X1, ln2_g, ln2_b, XL2);
    mix2_kernel<<<BT * CC / 256, 256>>>(XL2, fm_k, fm_r, CKh, CKl, CRh, CRl);
    mmagemm<2><<<gFF, 256, GEMM_SMEM>>>(CKh, CKl, WkeyT, nullptr, KKh, KKl, BT, FFD, CC, nullptr, nullptr);
    mmagemm<0><<<gCC, 256, GEMM_SMEM>>>(KKh, KKl, WvalT, KV, nullptr, nullptr, BT, CC, FFD, nullptr, nullptr);
    mmagemm<4><<<gCC, 256, GEMM_SMEM>>>(CRh, CRl, WreT, out, nullptr, nullptr, BT, CC, CC, X1, KV);
}

// round 10
// speedup vs baseline: 3.7219x; 1.3337x over previous
#include <cuda_runtime.h>
#include <cuda_fp16.h>
#include <math.h>
#include <stdint.h>

#define BB 2
#define TT 1024
#define CC 2048
#define HH 32
#define NNH 64
#define FFD 8192
#define BT (BB*TT)
#define EPS_ 1e-5f

typedef __half h16;

// ---------------- scratch (device globals; allocation-free) ----------------
__device__ float g_XL [BT*CC];
__device__ float g_R  [BT*CC];
__device__ float g_K  [BT*CC];
__device__ float g_V  [BT*CC];
__device__ float g_G  [BT*CC];
__device__ float g_ATT[BT*CC];
__device__ float g_X1 [BT*CC];
__device__ float g_XL2[BT*CC];
__device__ float g_KV [BT*CC];
__device__ float g_AB [BT*HH];

__device__ h16 g_XR[BT*CC], g_XK[BT*CC], g_XV[BT*CC], g_XG[BT*CC];
__device__ h16 g_AG[BT*CC], g_CK[BT*CC], g_CR[BT*CC];
__device__ h16 g_KK[(size_t)BT*FFD];

__device__ h16 g_WrT [CC*CC];
__device__ h16 g_WkT [CC*CC];
__device__ h16 g_WvT [CC*CC];
__device__ h16 g_WgT [CC*CC];
__device__ h16 g_WoT [CC*CC];
__device__ h16 g_WreT[CC*CC];
__device__ h16 g_WkeyT[(size_t)FFD*CC];
__device__ h16 g_WvalT[(size_t)CC*FFD];

// ---------------- helpers ----------------
__device__ __forceinline__ uint32_t s2u(const void* p) {
    uint32_t r;
    asm("{ .reg .u64 t; cvta.to.shared.u64 t, %1; cvt.u32.u64 %0, t; }" : "=r"(r) : "l"(p));
    return r;
}
#define CP_COMMIT() asm volatile("cp.async.commit_group;" ::: "memory")
#define CP_WAIT(n)  asm volatile("cp.async.wait_group %0;" :: "n"(n) : "memory")
__device__ __forceinline__ void cp16(uint32_t s, const void* g) {
    asm volatile("cp.async.cg.shared.global [%0], [%1], 16;" :: "r"(s), "l"(g));
}
__device__ __forceinline__ void ldm4(uint32_t* r, uint32_t a) {
    asm volatile("ldmatrix.sync.aligned.m8n8.x4.shared.b16 {%0,%1,%2,%3}, [%4];"
        : "=r"(r[0]), "=r"(r[1]), "=r"(r[2]), "=r"(r[3]) : "r"(a));
}
__device__ __forceinline__ void mma16816(float* d, const uint32_t* a, const uint32_t* b) {
    asm volatile(
        "mma.sync.aligned.m16n8k16.row.col.f32.f16.f16.f32 "
        "{%0,%1,%2,%3}, {%4,%5,%6,%7}, {%8,%9}, {%0,%1,%2,%3};"
        : "+f"(d[0]), "+f"(d[1]), "+f"(d[2]), "+f"(d[3])
        : "r"(a[0]), "r"(a[1]), "r"(a[2]), "r"(a[3]), "r"(b[0]), "r"(b[1]));
}
// 64B-row swizzle
__device__ __forceinline__ uint32_t SW64(uint32_t o) { return o ^ ((o >> 3) & 0x30); }

// ---------------- transpose + fp16 round:  W[K,N] -> Wt[N,K] ----------------
__global__ void transpose_h_k(const float* __restrict__ W, h16* __restrict__ th,
                              int K, int N) {
    __shared__ float t[32][33];
    const int k0 = blockIdx.y * 32, n0 = blockIdx.x * 32;
#pragma unroll
    for (int i = 0; i < 4; i++)
        t[threadIdx.y + i * 8][threadIdx.x] =
            W[(size_t)(k0 + threadIdx.y + i * 8) * N + n0 + threadIdx.x];
    __syncthreads();
#pragma unroll
    for (int i = 0; i < 4; i++) {
        const float v = t[threadIdx.x][threadIdx.y + i * 8];
        const size_t o = (size_t)(n0 + threadIdx.y + i * 8) * K + k0 + threadIdx.x;
        th[o] = __float2half_rn(v);
    }
}

// ---------------- mma.sync GEMM: D = A @ B^T, single-pass FP16 -------------
// A: [M,K] fp16; B: [N,K] fp16. Block 128x128, BK=32, 4 cp.async stages.
// 8 warps: 2x4, warp tile 64x32.
// EPI: 0 fp32 | 1 silu | 2 relu^2 -> fp16 | 3 aux1+acc | 4 aux1+sigmoid(acc)*aux2
#define OFF_A 0
#define OFF_B 8192
#define STG   16384
#define GEMM_SMEM (4 * STG)

template <int EPI>
__global__ __launch_bounds__(256, 1)
void mmagemm(const h16* __restrict__ Ah, const h16* __restrict__ Bh,
             float* __restrict__ C, h16* __restrict__ Ch,
             int M, int N, int K,
             const float* __restrict__ aux1, const float* __restrict__ aux2) {
    extern __shared__ __align__(1024) char smem[];
    const uint32_t sb = s2u(smem);
    const int tid = threadIdx.x;
    const int row0 = blockIdx.y * 128;
    const int col0 = blockIdx.x * 128;
    const int NK = K / 32;

    // ---- staging maps: 512 16B-transfers per 8KB matrix, 2 per thread ----
    const int r0 = tid >> 2, c0 = tid & 3;
    const int r1 = (tid + 256) >> 2, c1 = tid & 3;
    const uint32_t so0 = SW64((uint32_t)(r0 * 64 + c0 * 16));
    const uint32_t so1 = SW64((uint32_t)(r1 * 64 + c1 * 16));
    const h16* pA0 = Ah + (size_t)(row0 + r0) * K + c0 * 8;
    const h16* pA1 = Ah + (size_t)(row0 + r1) * K + c1 * 8;
    const h16* pB0 = Bh + (size_t)(col0 + r0) * K + c0 * 8;
    const h16* pB1 = Bh + (size_t)(col0 + r1) * K + c1 * 8;

    auto load_stage = [&](int kb, int st) {
        const uint32_t s = sb + (uint32_t)st * STG;
        const size_t ko = (size_t)kb * 32;
        cp16(s + OFF_A + so0, pA0 + ko); cp16(s + OFF_A + so1, pA1 + ko);
        cp16(s + OFF_B + so0, pB0 + ko); cp16(s + OFF_B + so1, pB1 + ko);
        CP_COMMIT();
    };

    // ---- per-warp fragment addressing ----
    const int wid = tid >> 5, lane = tid & 31;
    const int wm = wid & 1, wn = wid >> 1;
    const int wmb = wm * 64, wnb = wn * 32;
    const uint32_t a_row  = (uint32_t)(wmb + (lane & 15));
    const uint32_t a_csel = (uint32_t)((lane >> 4) << 4);
    const uint32_t b_row  = (uint32_t)(wnb + ((lane >> 4) << 3) + (lane & 7));
    const uint32_t b_csel = (uint32_t)(((lane >> 3) & 1) << 4);

    float acc[4][4][4];
#pragma unroll
    for (int i = 0; i < 4; i++)
#pragma unroll
        for (int j = 0; j < 4; j++)
#pragma unroll
            for (int q = 0; q < 4; q++) acc[i][j][q] = 0.f;

    // ---- pipeline (4 stages) ----
    load_stage(0, 0);
    if (NK > 1) load_stage(1, 1);
    if (NK > 2) load_stage(2, 2);

#pragma unroll 1
    for (int kb = 0; kb < NK; kb++) {
        if (kb + 3 < NK) { load_stage(kb + 3, (kb + 3) & 3); CP_WAIT(3); }
        else if (kb + 2 < NK) { CP_WAIT(2); }
        else if (kb + 1 < NK) { CP_WAIT(1); }
        else { CP_WAIT(0); }
        __syncthreads();

        const uint32_t us = sb + (uint32_t)(kb & 3) * STG;
#pragma unroll
        for (int ks = 0; ks < 2; ks++) {
            uint32_t a[4][4], bfr[2][4];
#pragma unroll
            for (int mt = 0; mt < 4; mt++) {
                const uint32_t off = (a_row + mt * 16) * 64 + (uint32_t)(ks * 32) + a_csel;
                ldm4(a[mt], us + OFF_A + SW64(off));
            }
#pragma unroll
            for (int bp = 0; bp < 2; bp++) {
                const uint32_t off = (b_row + bp * 16) * 64 + (uint32_t)(ks * 32) + b_csel;
                ldm4(bfr[bp], us + OFF_B + SW64(off));
            }
#pragma unroll
            for (int mt = 0; mt < 4; mt++)
#pragma unroll
                for (int nt = 0; nt < 4; nt++)
                    mma16816(acc[mt][nt], a[mt], &bfr[nt >> 1][(nt & 1) * 2]);
        }
        __syncthreads();
    }

    // ---- epilogue (register accumulators) ----
    const int mrow = row0 + wmb + (lane >> 2);
    const int ncol = col0 + wnb + (lane & 3) * 2;
#pragma unroll
    for (int mt = 0; mt < 4; mt++) {
#pragma unroll
        for (int half = 0; half < 2; half++) {
            const size_t m = (size_t)(mrow + mt * 16 + half * 8);
#pragma unroll
            for (int nt = 0; nt < 4; nt++) {
                float vx = acc[mt][nt][half * 2 + 0];
                float vy = acc[mt][nt][half * 2 + 1];
                const size_t idx = m * N + (ncol + nt * 8);
                if (EPI == 1) {
                    vx /= (1.f + expf(-vx)); vy /= (1.f + expf(-vy));
                } else if (EPI == 3) {
                    vx += aux1[idx]; vy += aux1[idx + 1];
                } else if (EPI == 4) {
                    vx = aux1[idx]     + aux2[idx]     / (1.f + expf(-vx));
                    vy = aux1[idx + 1] + aux2[idx + 1] / (1.f + expf(-vy));
                }
                if (EPI == 2) {
                    vx = fmaxf(vx, 0.f); vx *= vx;
                    vy = fmaxf(vy, 0.f); vy *= vy;
                    __half2 hp;
                    hp.x = __float2half_rn(vx); hp.y = __float2half_rn(vy);
                    *(__half2*)&Ch[idx] = hp;
                } else {
                    float2 p; p.x = vx; p.y = vy;
                    *(float2*)&C[idx] = p;
                }
            }
        }
    }
}

// ---------------- LayerNorm over last dim (C=2048), one block per row ------
__global__ void ln_kernel(const float* __restrict__ x, const float* __restrict__ g,
                          const float* __restrict__ b, float* __restrict__ out) {
    __shared__ float sa[8], sb_[8];
    const int row = blockIdx.x;
    const float4* xr = (const float4*)(x + (size_t)row * CC);
    float4 v[2];
    float s = 0.f, s2 = 0.f;
#pragma unroll
    for (int it = 0; it < 2; it++) {
        float4 q = xr[threadIdx.x + it * 256];
        v[it] = q;
        s  += q.x + q.y + q.z + q.w;
        s2 += q.x*q.x + q.y*q.y + q.z*q.z + q.w*q.w;
    }
#pragma unroll
    for (int o = 16; o; o >>= 1) {
        s  += __shfl_xor_sync(0xffffffffu, s,  o);
        s2 += __shfl_xor_sync(0xffffffffu, s2, o);
    }
    const int wid = threadIdx.x >> 5, lane = threadIdx.x & 31;
    if (!lane) { sa[wid] = s; sb_[wid] = s2; }
    __syncthreads();
    if (threadIdx.x == 0) {
        float ts = 0.f, ts2 = 0.f;
#pragma unroll
        for (int i = 0; i < 8; i++) { ts += sa[i]; ts2 += sb_[i]; }
        sa[0] = ts; sb_[0] = ts2;
    }
    __syncthreads();
    const float mean = sa[0] * (1.f / CC);
    const float var  = sb_[0] * (1.f / CC) - mean * mean;
    const float rstd = rsqrtf(var + EPS_);
    float4* op = (float4*)(out + (size_t)row * CC);
#pragma unroll
    for (int it = 0; it < 2; it++) {
        const int i4 = threadIdx.x + it * 256;
        float4 q  = v[it];
        float4 gg = ((const float4*)g)[i4];
        float4 bq = ((const float4*)b)[i4];
        q.x = (q.x - mean) * rstd * gg.x + bq.x;
        q.y = (q.y - mean) * rstd * gg.y + bq.y;
        q.z = (q.z - mean) * rstd * gg.z + bq.z;
        q.w = (q.w - mean) * rstd * gg.w + bq.w;
        op[i4] = q;
    }
}

// ---------------- time-shift mixes (fp16 outputs) ----------------
__global__ void mix4_kernel(const float* __restrict__ xl,
                            const float* __restrict__ mk, const float* __restrict__ mv,
                            const float* __restrict__ mr, const float* __restrict__ mg,
                            h16* xk, h16* xv, h16* xr, h16* xg) {
    const size_t idx = (size_t)blockIdx.x * blockDim.x + threadIdx.x;
    const int c = (int)(idx & (CC - 1));
    const int t = (int)((idx >> 11) & (TT - 1));
    const float cur  = xl[idx];
    const float prev = (t > 0) ? xl[idx - CC] : 0.f;
    const float d = cur - prev;
    xk[idx] = __float2half_rn(prev + mk[c] * d);
    xv[idx] = __float2half_rn(prev + mv[c] * d);
    xr[idx] = __float2half_rn(prev + mr[c] * d);
    xg[idx] = __float2half_rn(prev + mg[c] * d);
}

__global__ void mix2_kernel(const float* __restrict__ xl,
                            const float* __restrict__ mk, const float* __restrict__ mr,
                            h16* ck, h16* cr) {
    const size_t idx = (size_t)blockIdx.x * blockDim.x + threadIdx.x;
    const int c = (int)(idx & (CC - 1));
    const int t = (int)((idx >> 11) & (TT - 1));
    const float cur  = xl[idx];
    const float prev = (t > 0) ? xl[idx - CC] : 0.f;
    const float d = cur - prev;
    ck[idx] = __float2half_rn(prev + mk[c] * d);
    cr[idx] = __float2half_rn(prev + mr[c] * d);
}

// ---------------- a_t = sum_i r_i * u_i * k_i ----------------
__global__ void adot_kernel(const float* __restrict__ r, const float* __restrict__ k,
                            const float* __restrict__ u, float* __restrict__ ab) {
    const int gid  = blockIdx.x * 8 + (threadIdx.x >> 5);
    const int lane = threadIdx.x & 31;
    const int h = gid & (HH - 1);
    const size_t off = (size_t)gid * NNH;
    float p = r[off + lane]      * u[h * NNH + lane]      * k[off + lane]
            + r[off + lane + 32] * u[h * NNH + lane + 32] * k[off + lane + 32];
#pragma unroll
    for (int o = 16; o; o >>= 1) p += __shfl_xor_sync(0xffffffffu, p, o);
    if (lane == 0) ab[gid] = p;
}

// ---------------- WKV5 recurrence: block per (b,h,jc), 128 threads ---------
// thread = (j, p): j = jc*32 + tid>>2 (state column), p = tid&3 (i-range 16)
__global__ __launch_bounds__(128)
void wkv_kernel(const float* __restrict__ r, const float* __restrict__ k,
                const float* __restrict__ v, const float* __restrict__ w,
                const float* __restrict__ ab, float* __restrict__ att) {
    const int blk = blockIdx.x;
    const int jc = blk & 1;
    const int bh = blk >> 1;
    const int b = bh / HH, h = bh % HH;
    const int tid = threadIdx.x;
    const int j = jc * 32 + (tid >> 2);
    const int p = tid & 3;
    __shared__ float sh_r[64], sh_k[64];
    float S[16], dec[16];
#pragma unroll
    for (int ii = 0; ii < 16; ii++) S[ii] = 0.f;
#pragma unroll
    for (int ii = 0; ii < 16; ii++) {
        const float wv = w[h * NNH + p * 16 + ii];
        dec[ii] = expf(-expf(wv));
    }
    for (int t = 0; t < TT; t++) {
        const size_t off = (((size_t)b * TT + t) * HH + h) * NNH;
        __syncthreads();
        if (tid < 64) sh_r[tid] = r[off + tid];
        else          sh_k[tid - 64] = k[off + tid - 64];
        __syncthreads();
        const float vj = v[off + j];
        const float at = ab[((size_t)b * TT + t) * HH + h];
        float yp = 0.f;
#pragma unroll
        for (int ii = 0; ii < 16; ii++) {
            const int i = p * 16 + ii;
            yp += sh_r[i] * S[ii];
            S[ii] = dec[ii] * S[ii] + sh_k[i] * vj;
        }
        float y = yp + __shfl_xor_sync(0xffffffffu, yp, 1);
        y += __shfl_xor_sync(0xffffffffu, y, 2);
        if (p == 0) att[off + j] = at * vj + y;
    }
}

// ---------------- GroupNorm(att/DIV)*g+b, * gate, fp16 out ----------
__global__ void gn_gate_kernel(const float* __restrict__ att, const float* __restrict__ gq,
                               const float* __restrict__ gg, const float* __restrict__ gb,
                               h16* __restrict__ oh) {
    const int gid  = blockIdx.x * 8 + (threadIdx.x >> 5);
    const int lane = threadIdx.x & 31;
    const int h = gid & (HH - 1);
    const size_t off = (size_t)gid * NNH;
    const float inv_div = 1.f / 8.f;
    const float v0 = att[off + lane]      * inv_div;
    const float v1 = att[off + lane + 32] * inv_div;
    float s = v0 + v1, s2 = v0 * v0 + v1 * v1;
#pragma unroll
    for (int o = 16; o; o >>= 1) {
        s  += __shfl_xor_sync(0xffffffffu, s,  o);
        s2 += __shfl_xor_sync(0xffffffffu, s2, o);
    }
    const float m = s * (1.f / NNH);
    const float var = s2 * (1.f / NNH) - m * m;
    const float rstd = rsqrtf(var + EPS_);
    const int c0 = h * NNH + lane;
    const float o0 = ((v0 - m) * rstd * gg[c0]      + gb[c0])      * gq[off + lane];
    const float o1 = ((v1 - m) * rstd * gg[c0 + 32] + gb[c0 + 32]) * gq[off + lane + 32];
    oh[off + lane]      = __float2half_rn(o0);
    oh[off + lane + 32] = __float2half_rn(o1);
}

// ---------------- launch ----------------
extern "C" void kernel_launch(void* const* d_in, const int* in_sizes, int n_in,
                              void* d_out, int out_size) {
    (void)in_sizes; (void)n_in; (void)out_size;
    const float* x     = (const float*)d_in[0];
    const float* ln1_g = (const float*)d_in[1];
    const float* ln1_b = (const float*)d_in[2];
    const float* ln2_g = (const float*)d_in[3];
    const float* ln2_b = (const float*)d_in[4];
    const float* tm_k  = (const float*)d_in[5];
    const float* tm_v  = (const float*)d_in[6];
    const float* tm_r  = (const float*)d_in[7];
    const float* tm_g  = (const float*)d_in[8];
    const float* tdec  = (const float*)d_in[9];
    const float* tfaa  = (const float*)d_in[10];
    const float* Wr    = (const float*)d_in[11];
    const float* Wk    = (const float*)d_in[12];
    const float* Wv    = (const float*)d_in[13];
    const float* Wg    = (const float*)d_in[14];
    const float* Wo    = (const float*)d_in[15];
    const float* lnx_g = (const float*)d_in[16];
    const float* lnx_b = (const float*)d_in[17];
    const float* fm_k  = (const float*)d_in[18];
    const float* fm_r  = (const float*)d_in[19];
    const float* Wkey  = (const float*)d_in[20];
    const float* Wrec  = (const float*)d_in[21];
    const float* Wval  = (const float*)d_in[22];
    float* out = (float*)d_out;

    float *XL, *Rb, *Kb, *Vb, *Gb, *ATT, *X1, *XL2, *KV, *AB;
    cudaGetSymbolAddress((void**)&XL,  g_XL);
    cudaGetSymbolAddress((void**)&Rb,  g_R);
    cudaGetSymbolAddress((void**)&Kb,  g_K);
    cudaGetSymbolAddress((void**)&Vb,  g_V);
    cudaGetSymbolAddress((void**)&Gb,  g_G);
    cudaGetSymbolAddress((void**)&ATT, g_ATT);
    cudaGetSymbolAddress((void**)&X1,  g_X1);
    cudaGetSymbolAddress((void**)&XL2, g_XL2);
    cudaGetSymbolAddress((void**)&KV,  g_KV);
    cudaGetSymbolAddress((void**)&AB,  g_AB);

    h16 *XR,*XK,*XV,*XG,*AG,*CK,*CR,*KK;
    cudaGetSymbolAddress((void**)&XR, g_XR);
    cudaGetSymbolAddress((void**)&XK, g_XK);
    cudaGetSymbolAddress((void**)&XV, g_XV);
    cudaGetSymbolAddress((void**)&XG, g_XG);
    cudaGetSymbolAddress((void**)&AG, g_AG);
    cudaGetSymbolAddress((void**)&CK, g_CK);
    cudaGetSymbolAddress((void**)&CR, g_CR);
    cudaGetSymbolAddress((void**)&KK, g_KK);

    h16 *WrT,*WkT,*WvT,*WgT,*WoT,*WreT,*WkeyT,*WvalT;
    cudaGetSymbolAddress((void**)&WrT,   g_WrT);
    cudaGetSymbolAddress((void**)&WkT,   g_WkT);
    cudaGetSymbolAddress((void**)&WvT,   g_WvT);
    cudaGetSymbolAddress((void**)&WgT,   g_WgT);
    cudaGetSymbolAddress((void**)&WoT,   g_WoT);
    cudaGetSymbolAddress((void**)&WreT,  g_WreT);
    cudaGetSymbolAddress((void**)&WkeyT, g_WkeyT);
    cudaGetSymbolAddress((void**)&WvalT, g_WvalT);

    cudaFuncSetAttribute(mmagemm<0>, cudaFuncAttributeMaxDynamicSharedMemorySize, GEMM_SMEM);
    cudaFuncSetAttribute(mmagemm<1>, cudaFuncAttributeMaxDynamicSharedMemorySize, GEMM_SMEM);
    cudaFuncSetAttribute(mmagemm<2>, cudaFuncAttributeMaxDynamicSharedMemorySize, GEMM_SMEM);
    cudaFuncSetAttribute(mmagemm<3>, cudaFuncAttributeMaxDynamicSharedMemorySize, GEMM_SMEM);
    cudaFuncSetAttribute(mmagemm<4>, cudaFuncAttributeMaxDynamicSharedMemorySize, GEMM_SMEM);

    const dim3 tb(32, 8);
    transpose_h_k<<<dim3(CC / 32,  CC / 32),  tb>>>(Wr,   WrT,   CC,  CC);
    transpose_h_k<<<dim3(CC / 32,  CC / 32),  tb>>>(Wk,   WkT,   CC,  CC);
    transpose_h_k<<<dim3(CC / 32,  CC / 32),  tb>>>(Wv,   WvT,   CC,  CC);
    transpose_h_k<<<dim3(CC / 32,  CC / 32),  tb>>>(Wg,   WgT,   CC,  CC);
    transpose_h_k<<<dim3(CC / 32,  CC / 32),  tb>>>(Wo,   WoT,   CC,  CC);
    transpose_h_k<<<dim3(CC / 32,  CC / 32),  tb>>>(Wrec, WreT,  CC,  CC);
    transpose_h_k<<<dim3(FFD / 32, CC / 32),  tb>>>(Wkey, WkeyT, CC,  FFD);
    transpose_h_k<<<dim3(CC / 32,  FFD / 32), tb>>>(Wval, WvalT, FFD, CC);

    const dim3 gCC(CC / 128, BT / 128);    // (16,16)
    const dim3 gFF(FFD / 128, BT / 128);   // (64,16)

    // attention half
    ln_kernel<<<BT, 256>>>(x, ln1_g, ln1_b, XL);
    mix4_kernel<<<BT * CC / 256, 256>>>(XL, tm_k, tm_v, tm_r, tm_g, XK, XV, XR, XG);
    mmagemm<0><<<gCC, 256, GEMM_SMEM>>>(XR, WrT, Rb, nullptr, BT, CC, CC, nullptr, nullptr);
    mmagemm<0><<<gCC, 256, GEMM_SMEM>>>(XK, WkT, Kb, nullptr, BT, CC, CC, nullptr, nullptr);
    mmagemm<0><<<gCC, 256, GEMM_SMEM>>>(XV, WvT, Vb, nullptr, BT, CC, CC, nullptr, nullptr);
    mmagemm<1><<<gCC, 256, GEMM_SMEM>>>(XG, WgT, Gb, nullptr, BT, CC, CC, nullptr, nullptr);
    adot_kernel<<<BT * HH / 8, 256>>>(Rb, Kb, tfaa, AB);
    wkv_kernel<<<BB * HH * 2, 128>>>(Rb, Kb, Vb, tdec, AB, ATT);
    gn_gate_kernel<<<BT * HH / 8, 256>>>(ATT, Gb, lnx_g, lnx_b, AG);
    mmagemm<3><<<gCC, 256, GEMM_SMEM>>>(AG, WoT, X1, nullptr, BT, CC, CC, x, nullptr);

    // FFN half
    ln_kernel<<<BT, 256>>>(X1, ln2_g, ln2_b, XL2);
    mix2_kernel<<<BT * CC / 256, 256>>>(XL2, fm_k, fm_r, CK, CR);
    mmagemm<2><<<gFF, 256, GEMM_SMEM>>>(CK, WkeyT, nullptr, KK, BT, FFD, CC, nullptr, nullptr);
    mmagemm<0><<<gCC, 256, GEMM_SMEM>>>(KK, WvalT, KV, nullptr, BT, CC, FFD, nullptr, nullptr);
    mmagemm<4><<<gCC, 256, GEMM_SMEM>>>(CR, WreT, out, nullptr, BT, CC, CC, X1, KV);
}

// round 11
// speedup vs baseline: 4.1113x; 1.1046x over previous
#include <cuda_runtime.h>
#include <cuda_fp16.h>
#include <math.h>
#include <stdint.h>

#define BB 2
#define TT 1024
#define CC 2048
#define HH 32
#define NNH 64
#define FFD 8192
#define BT (BB*TT)
#define EPS_ 1e-5f

typedef __half h16;

// ---------------- scratch (device globals; allocation-free) ----------------
__device__ float g_XL [BT*CC];
__device__ float g_R  [BT*CC];
__device__ float g_K  [BT*CC];
__device__ float g_V  [BT*CC];
__device__ float g_G  [BT*CC];
__device__ float g_ATT[BT*CC];
__device__ float g_X1 [BT*CC];
__device__ float g_XL2[BT*CC];
__device__ float g_KV [BT*CC];

__device__ h16 g_XR[BT*CC], g_XK[BT*CC], g_XV[BT*CC], g_XG[BT*CC];
__device__ h16 g_AG[BT*CC], g_CK[BT*CC], g_CR[BT*CC];
__device__ h16 g_KK[(size_t)BT*FFD];

__device__ h16 g_WrT [CC*CC];
__device__ h16 g_WkT [CC*CC];
__device__ h16 g_WvT [CC*CC];
__device__ h16 g_WgT [CC*CC];
__device__ h16 g_WoT [CC*CC];
__device__ h16 g_WreT[CC*CC];
__device__ h16 g_WkeyT[(size_t)FFD*CC];
__device__ h16 g_WvalT[(size_t)CC*FFD];

// ---------------- helpers ----------------
__device__ __forceinline__ uint32_t s2u(const void* p) {
    uint32_t r;
    asm("{ .reg .u64 t; cvta.to.shared.u64 t, %1; cvt.u32.u64 %0, t; }" : "=r"(r) : "l"(p));
    return r;
}
#define CP_COMMIT() asm volatile("cp.async.commit_group;" ::: "memory")
#define CP_WAIT(n)  asm volatile("cp.async.wait_group %0;" :: "n"(n) : "memory")
__device__ __forceinline__ void cp16(uint32_t s, const void* g) {
    asm volatile("cp.async.cg.shared.global [%0], [%1], 16;" :: "r"(s), "l"(g));
}
__device__ __forceinline__ void ldm4(uint32_t* r, uint32_t a) {
    asm volatile("ldmatrix.sync.aligned.m8n8.x4.shared.b16 {%0,%1,%2,%3}, [%4];"
        : "=r"(r[0]), "=r"(r[1]), "=r"(r[2]), "=r"(r[3]) : "r"(a));
}
__device__ __forceinline__ void mma16816(float* d, const uint32_t* a, const uint32_t* b) {
    asm volatile(
        "mma.sync.aligned.m16n8k16.row.col.f32.f16.f16.f32 "
        "{%0,%1,%2,%3}, {%4,%5,%6,%7}, {%8,%9}, {%0,%1,%2,%3};"
        : "+f"(d[0]), "+f"(d[1]), "+f"(d[2]), "+f"(d[3])
        : "r"(a[0]), "r"(a[1]), "r"(a[2]), "r"(a[3]), "r"(b[0]), "r"(b[1]));
}
// 64B-row swizzle
__device__ __forceinline__ uint32_t SW64(uint32_t o) { return o ^ ((o >> 3) & 0x30); }

// ---------------- transpose + fp16 round:  W[K,N] -> Wt[N,K] ----------------
__global__ void transpose_h_k(const float* __restrict__ W, h16* __restrict__ th,
                              int K, int N) {
    __shared__ float t[32][33];
    const int k0 = blockIdx.y * 32, n0 = blockIdx.x * 32;
#pragma unroll
    for (int i = 0; i < 4; i++)
        t[threadIdx.y + i * 8][threadIdx.x] =
            W[(size_t)(k0 + threadIdx.y + i * 8) * N + n0 + threadIdx.x];
    __syncthreads();
#pragma unroll
    for (int i = 0; i < 4; i++) {
        const float v = t[threadIdx.x][threadIdx.y + i * 8];
        const size_t o = (size_t)(n0 + threadIdx.y + i * 8) * K + k0 + threadIdx.x;
        th[o] = __float2half_rn(v);
    }
}

// ---------------- mma.sync GEMM: D = A @ B^T, single-pass FP16 -------------
// A: [M,K] fp16; B: [N,K] fp16. Block 128x128, BK=32, 3 cp.async stages,
// ONE barrier per k-iter, 2 CTAs/SM. 8 warps: 2x4, warp tile 64x32.
// EPI: 0 fp32 | 1 silu | 2 relu^2 -> fp16 | 3 aux1+acc | 4 aux1+sigmoid(acc)*aux2
#define OFF_A 0
#define OFF_B 8192
#define STG   16384
#define GEMM_SMEM (3 * STG)

template <int EPI>
__global__ __launch_bounds__(256, 2)
void mmagemm(const h16* __restrict__ Ah, const h16* __restrict__ Bh,
             float* __restrict__ C, h16* __restrict__ Ch,
             int M, int N, int K,
             const float* __restrict__ aux1, const float* __restrict__ aux2) {
    extern __shared__ __align__(1024) char smem[];
    const uint32_t sb = s2u(smem);
    const int tid = threadIdx.x;
    const int row0 = blockIdx.y * 128;
    const int col0 = blockIdx.x * 128;
    const int NK = K / 32;

    // ---- staging maps: 512 16B-transfers per 8KB matrix, 2 per thread ----
    const int r0 = tid >> 2, c0 = tid & 3;
    const int r1 = (tid + 256) >> 2, c1 = tid & 3;
    const uint32_t so0 = SW64((uint32_t)(r0 * 64 + c0 * 16));
    const uint32_t so1 = SW64((uint32_t)(r1 * 64 + c1 * 16));
    const h16* pA0 = Ah + (size_t)(row0 + r0) * K + c0 * 8;
    const h16* pA1 = Ah + (size_t)(row0 + r1) * K + c1 * 8;
    const h16* pB0 = Bh + (size_t)(col0 + r0) * K + c0 * 8;
    const h16* pB1 = Bh + (size_t)(col0 + r1) * K + c1 * 8;

    auto load_stage = [&](int kb, int st) {
        const uint32_t s = sb + (uint32_t)st * STG;
        const size_t ko = (size_t)kb * 32;
        cp16(s + OFF_A + so0, pA0 + ko); cp16(s + OFF_A + so1, pA1 + ko);
        cp16(s + OFF_B + so0, pB0 + ko); cp16(s + OFF_B + so1, pB1 + ko);
        CP_COMMIT();
    };

    // ---- per-warp fragment addressing ----
    const int wid = tid >> 5, lane = tid & 31;
    const int wm = wid & 1, wn = wid >> 1;
    const int wmb = wm * 64, wnb = wn * 32;
    const uint32_t a_row  = (uint32_t)(wmb + (lane & 15));
    const uint32_t a_csel = (uint32_t)((lane >> 4) << 4);
    const uint32_t b_row  = (uint32_t)(wnb + ((lane >> 4) << 3) + (lane & 7));
    const uint32_t b_csel = (uint32_t)(((lane >> 3) & 1) << 4);

    float acc[4][4][4];
#pragma unroll
    for (int i = 0; i < 4; i++)
#pragma unroll
        for (int j = 0; j < 4; j++)
#pragma unroll
            for (int q = 0; q < 4; q++) acc[i][j][q] = 0.f;

    // ---- pipeline (3 stages, 1 barrier/iter) ----
    load_stage(0, 0);
    if (NK > 1) load_stage(1, 1);

#pragma unroll 1
    for (int kb = 0; kb < NK; kb++) {
        if (kb + 1 < NK) { CP_WAIT(1); } else { CP_WAIT(0); }
        __syncthreads();

        const uint32_t us = sb + (uint32_t)(kb % 3) * STG;
#pragma unroll
        for (int ks = 0; ks < 2; ks++) {
            uint32_t a[4][4], bfr[2][4];
#pragma unroll
            for (int mt = 0; mt < 4; mt++) {
                const uint32_t off = (a_row + mt * 16) * 64 + (uint32_t)(ks * 32) + a_csel;
                ldm4(a[mt], us + OFF_A + SW64(off));
            }
#pragma unroll
            for (int bp = 0; bp < 2; bp++) {
                const uint32_t off = (b_row + bp * 16) * 64 + (uint32_t)(ks * 32) + b_csel;
                ldm4(bfr[bp], us + OFF_B + SW64(off));
            }
#pragma unroll
            for (int mt = 0; mt < 4; mt++)
#pragma unroll
                for (int nt = 0; nt < 4; nt++)
                    mma16816(acc[mt][nt], a[mt], &bfr[nt >> 1][(nt & 1) * 2]);
        }
        // tail-load: stage (kb+2)%3 was fully consumed in iteration kb-1,
        // and every thread passed this iteration's barrier after those reads.
        if (kb + 2 < NK) load_stage(kb + 2, (kb + 2) % 3);
    }

    // ---- epilogue (register accumulators) ----
    const int mrow = row0 + wmb + (lane >> 2);
    const int ncol = col0 + wnb + (lane & 3) * 2;
#pragma unroll
    for (int mt = 0; mt < 4; mt++) {
#pragma unroll
        for (int half = 0; half < 2; half++) {
            const size_t m = (size_t)(mrow + mt * 16 + half * 8);
#pragma unroll
            for (int nt = 0; nt < 4; nt++) {
                float vx = acc[mt][nt][half * 2 + 0];
                float vy = acc[mt][nt][half * 2 + 1];
                const size_t idx = m * N + (ncol + nt * 8);
                if (EPI == 1) {
                    vx /= (1.f + expf(-vx)); vy /= (1.f + expf(-vy));
                } else if (EPI == 3) {
                    vx += aux1[idx]; vy += aux1[idx + 1];
                } else if (EPI == 4) {
                    vx = aux1[idx]     + aux2[idx]     / (1.f + expf(-vx));
                    vy = aux1[idx + 1] + aux2[idx + 1] / (1.f + expf(-vy));
                }
                if (EPI == 2) {
                    vx = fmaxf(vx, 0.f); vx *= vx;
                    vy = fmaxf(vy, 0.f); vy *= vy;
                    __half2 hp;
                    hp.x = __float2half_rn(vx); hp.y = __float2half_rn(vy);
                    *(__half2*)&Ch[idx] = hp;
                } else {
                    float2 p; p.x = vx; p.y = vy;
                    *(float2*)&C[idx] = p;
                }
            }
        }
    }
}

// ---------------- LayerNorm over last dim (C=2048), one block per row ------
__global__ void ln_kernel(const float* __restrict__ x, const float* __restrict__ g,
                          const float* __restrict__ b, float* __restrict__ out) {
    __shared__ float sa[8], sb_[8];
    const int row = blockIdx.x;
    const float4* xr = (const float4*)(x + (size_t)row * CC);
    float4 v[2];
    float s = 0.f, s2 = 0.f;
#pragma unroll
    for (int it = 0; it < 2; it++) {
        float4 q = xr[threadIdx.x + it * 256];
        v[it] = q;
        s  += q.x + q.y + q.z + q.w;
        s2 += q.x*q.x + q.y*q.y + q.z*q.z + q.w*q.w;
    }
#pragma unroll
    for (int o = 16; o; o >>= 1) {
        s  += __shfl_xor_sync(0xffffffffu, s,  o);
        s2 += __shfl_xor_sync(0xffffffffu, s2, o);
    }
    const int wid = threadIdx.x >> 5, lane = threadIdx.x & 31;
    if (!lane) { sa[wid] = s; sb_[wid] = s2; }
    __syncthreads();
    if (threadIdx.x == 0) {
        float ts = 0.f, ts2 = 0.f;
#pragma unroll
        for (int i = 0; i < 8; i++) { ts += sa[i]; ts2 += sb_[i]; }
        sa[0] = ts; sb_[0] = ts2;
    }
    __syncthreads();
    const float mean = sa[0] * (1.f / CC);
    const float var  = sb_[0] * (1.f / CC) - mean * mean;
    const float rstd = rsqrtf(var + EPS_);
    float4* op = (float4*)(out + (size_t)row * CC);
#pragma unroll
    for (int it = 0; it < 2; it++) {
        const int i4 = threadIdx.x + it * 256;
        float4 q  = v[it];
        float4 gg = ((const float4*)g)[i4];
        float4 bq = ((const float4*)b)[i4];
        q.x = (q.x - mean) * rstd * gg.x + bq.x;
        q.y = (q.y - mean) * rstd * gg.y + bq.y;
        q.z = (q.z - mean) * rstd * gg.z + bq.z;
        q.w = (q.w - mean) * rstd * gg.w + bq.w;
        op[i4] = q;
    }
}

// ---------------- time-shift mixes (fp16 outputs) ----------------
__global__ void mix4_kernel(const float* __restrict__ xl,
                            const float* __restrict__ mk, const float* __restrict__ mv,
                            const float* __restrict__ mr, const float* __restrict__ mg,
                            h16* xk, h16* xv, h16* xr, h16* xg) {
    const size_t idx = (size_t)blockIdx.x * blockDim.x + threadIdx.x;
    const int c = (int)(idx & (CC - 1));
    const int t = (int)((idx >> 11) & (TT - 1));
    const float cur  = xl[idx];
    const float prev = (t > 0) ? xl[idx - CC] : 0.f;
    const float d = cur - prev;
    xk[idx] = __float2half_rn(prev + mk[c] * d);
    xv[idx] = __float2half_rn(prev + mv[c] * d);
    xr[idx] = __float2half_rn(prev + mr[c] * d);
    xg[idx] = __float2half_rn(prev + mg[c] * d);
}

__global__ void mix2_kernel(const float* __restrict__ xl,
                            const float* __restrict__ mk, const float* __restrict__ mr,
                            h16* ck, h16* cr) {
    const size_t idx = (size_t)blockIdx.x * blockDim.x + threadIdx.x;
    const int c = (int)(idx & (CC - 1));
    const int t = (int)((idx >> 11) & (TT - 1));
    const float cur  = xl[idx];
    const float prev = (t > 0) ? xl[idx - CC] : 0.f;
    const float d = cur - prev;
    ck[idx] = __float2half_rn(prev + mk[c] * d);
    cr[idx] = __float2half_rn(prev + mr[c] * d);
}

// ---------------- WKV5 recurrence (adot fused): block per (b,h,jc) ---------
// thread = (j, p): j = jc*32 + tid>>2 (state column), p = tid&3 (i-range 16)
// y_j = sum_i r_i * (u_i*k_i*v_j + S[i][j]);  S = dec*S + k_i*v_j
__global__ __launch_bounds__(128)
void wkv_kernel(const float* __restrict__ r, const float* __restrict__ k,
                const float* __restrict__ v, const float* __restrict__ w,
                const float* __restrict__ u, float* __restrict__ att) {
    const int blk = blockIdx.x;
    const int jc = blk & 1;
    const int bh = blk >> 1;
    const int b = bh / HH, h = bh % HH;
    const int tid = threadIdx.x;
    const int j = jc * 32 + (tid >> 2);
    const int p = tid & 3;
    __shared__ float sh_r[64], sh_k[64];
    float S[16], dec[16], uu[16];
#pragma unroll
    for (int ii = 0; ii < 16; ii++) S[ii] = 0.f;
#pragma unroll
    for (int ii = 0; ii < 16; ii++) {
        const float wv = w[h * NNH + p * 16 + ii];
        dec[ii] = expf(-expf(wv));
        uu[ii]  = u[h * NNH + p * 16 + ii];
    }
    for (int t = 0; t < TT; t++) {
        const size_t off = (((size_t)b * TT + t) * HH + h) * NNH;
        __syncthreads();
        if (tid < 64) sh_r[tid] = r[off + tid];
        else          sh_k[tid - 64] = k[off + tid - 64];
        __syncthreads();
        const float vj = v[off + j];
        float yp = 0.f;
#pragma unroll
        for (int ii = 0; ii < 16; ii++) {
            const int i = p * 16 + ii;
            const float kv = sh_k[i] * vj;
            yp = fmaf(sh_r[i], fmaf(uu[ii], kv, S[ii]), yp);
            S[ii] = fmaf(dec[ii], S[ii], kv);
        }
        float y = yp + __shfl_xor_sync(0xffffffffu, yp, 1);
        y += __shfl_xor_sync(0xffffffffu, y, 2);
        if (p == 0) att[off + j] = y;
    }
}

// ---------------- GroupNorm(att/DIV)*g+b, * gate, fp16 out ----------
__global__ void gn_gate_kernel(const float* __restrict__ att, const float* __restrict__ gq,
                               const float* __restrict__ gg, const float* __restrict__ gb,
                               h16* __restrict__ oh) {
    const int gid  = blockIdx.x * 8 + (threadIdx.x >> 5);
    const int lane = threadIdx.x & 31;
    const int h = gid & (HH - 1);
    const size_t off = (size_t)gid * NNH;
    const float inv_div = 1.f / 8.f;
    const float v0 = att[off + lane]      * inv_div;
    const float v1 = att[off + lane + 32] * inv_div;
    float s = v0 + v1, s2 = v0 * v0 + v1 * v1;
#pragma unroll
    for (int o = 16; o; o >>= 1) {
        s  += __shfl_xor_sync(0xffffffffu, s,  o);
        s2 += __shfl_xor_sync(0xffffffffu, s2, o);
    }
    const float m = s * (1.f / NNH);
    const float var = s2 * (1.f / NNH) - m * m;
    const float rstd = rsqrtf(var + EPS_);
    const int c0 = h * NNH + lane;
    const float o0 = ((v0 - m) * rstd * gg[c0]      + gb[c0])      * gq[off + lane];
    const float o1 = ((v1 - m) * rstd * gg[c0 + 32] + gb[c0 + 32]) * gq[off + lane + 32];
    oh[off + lane]      = __float2half_rn(o0);
    oh[off + lane + 32] = __float2half_rn(o1);
}

// ---------------- launch ----------------
extern "C" void kernel_launch(void* const* d_in, const int* in_sizes, int n_in,
                              void* d_out, int out_size) {
    (void)in_sizes; (void)n_in; (void)out_size;
    const float* x     = (const float*)d_in[0];
    const float* ln1_g = (const float*)d_in[1];
    const float* ln1_b = (const float*)d_in[2];
    const float* ln2_g = (const float*)d_in[3];
    const float* ln2_b = (const float*)d_in[4];
    const float* tm_k  = (const float*)d_in[5];
    const float* tm_v  = (const float*)d_in[6];
    const float* tm_r  = (const float*)d_in[7];
    const float* tm_g  = (const float*)d_in[8];
    const float* tdec  = (const float*)d_in[9];
    const float* tfaa  = (const float*)d_in[10];
    const float* Wr    = (const float*)d_in[11];
    const float* Wk    = (const float*)d_in[12];
    const float* Wv    = (const float*)d_in[13];
    const float* Wg    = (const float*)d_in[14];
    const float* Wo    = (const float*)d_in[15];
    const float* lnx_g = (const float*)d_in[16];
    const float* lnx_b = (const float*)d_in[17];
    const float* fm_k  = (const float*)d_in[18];
    const float* fm_r  = (const float*)d_in[19];
    const float* Wkey  = (const float*)d_in[20];
    const float* Wrec  = (const float*)d_in[21];
    const float* Wval  = (const float*)d_in[22];
    float* out = (float*)d_out;

    float *XL, *Rb, *Kb, *Vb, *Gb, *ATT, *X1, *XL2, *KV;
    cudaGetSymbolAddress((void**)&XL,  g_XL);
    cudaGetSymbolAddress((void**)&Rb,  g_R);
    cudaGetSymbolAddress((void**)&Kb,  g_K);
    cudaGetSymbolAddress((void**)&Vb,  g_V);
    cudaGetSymbolAddress((void**)&Gb,  g_G);
    cudaGetSymbolAddress((void**)&ATT, g_ATT);
    cudaGetSymbolAddress((void**)&X1,  g_X1);
    cudaGetSymbolAddress((void**)&XL2, g_XL2);
    cudaGetSymbolAddress((void**)&KV,  g_KV);

    h16 *XR,*XK,*XV,*XG,*AG,*CK,*CR,*KK;
    cudaGetSymbolAddress((void**)&XR, g_XR);
    cudaGetSymbolAddress((void**)&XK, g_XK);
    cudaGetSymbolAddress((void**)&XV, g_XV);
    cudaGetSymbolAddress((void**)&XG, g_XG);
    cudaGetSymbolAddress((void**)&AG, g_AG);
    cudaGetSymbolAddress((void**)&CK, g_CK);
    cudaGetSymbolAddress((void**)&CR, g_CR);
    cudaGetSymbolAddress((void**)&KK, g_KK);

    h16 *WrT,*WkT,*WvT,*WgT,*WoT,*WreT,*WkeyT,*WvalT;
    cudaGetSymbolAddress((void**)&WrT,   g_WrT);
    cudaGetSymbolAddress((void**)&WkT,   g_WkT);
    cudaGetSymbolAddress((void**)&WvT,   g_WvT);
    cudaGetSymbolAddress((void**)&WgT,   g_WgT);
    cudaGetSymbolAddress((void**)&WoT,   g_WoT);
    cudaGetSymbolAddress((void**)&WreT,  g_WreT);
    cudaGetSymbolAddress((void**)&WkeyT, g_WkeyT);
    cudaGetSymbolAddress((void**)&WvalT, g_WvalT);

    cudaFuncSetAttribute(mmagemm<0>, cudaFuncAttributeMaxDynamicSharedMemorySize, GEMM_SMEM);
    cudaFuncSetAttribute(mmagemm<1>, cudaFuncAttributeMaxDynamicSharedMemorySize, GEMM_SMEM);
    cudaFuncSetAttribute(mmagemm<2>, cudaFuncAttributeMaxDynamicSharedMemorySize, GEMM_SMEM);
    cudaFuncSetAttribute(mmagemm<3>, cudaFuncAttributeMaxDynamicSharedMemorySize, GEMM_SMEM);
    cudaFuncSetAttribute(mmagemm<4>, cudaFuncAttributeMaxDynamicSharedMemorySize, GEMM_SMEM);

    const dim3 tb(32, 8);
    transpose_h_k<<<dim3(CC / 32,  CC / 32),  tb>>>(Wr,   WrT,   CC,  CC);
    transpose_h_k<<<dim3(CC / 32,  CC / 32),  tb>>>(Wk,   WkT,   CC,  CC);
    transpose_h_k<<<dim3(CC / 32,  CC / 32),  tb>>>(Wv,   WvT,   CC,  CC);
    transpose_h_k<<<dim3(CC / 32,  CC / 32),  tb>>>(Wg,   WgT,   CC,  CC);
    transpose_h_k<<<dim3(CC / 32,  CC / 32),  tb>>>(Wo,   WoT,   CC,  CC);
    transpose_h_k<<<dim3(CC / 32,  CC / 32),  tb>>>(Wrec, WreT,  CC,  CC);
    transpose_h_k<<<dim3(FFD / 32, CC / 32),  tb>>>(Wkey, WkeyT, CC,  FFD);
    transpose_h_k<<<dim3(CC / 32,  FFD / 32), tb>>>(Wval, WvalT, FFD, CC);

    const dim3 gCC(CC / 128, BT / 128);    // (16,16)
    const dim3 gFF(FFD / 128, BT / 128);   // (64,16)

    // attention half
    ln_kernel<<<BT, 256>>>(x, ln1_g, ln1_b, XL);
    mix4_kernel<<<BT * CC / 256, 256>>>(XL, tm_k, tm_v, tm_r, tm_g, XK, XV, XR, XG);
    mmagemm<0><<<gCC, 256, GEMM_SMEM>>>(XR, WrT, Rb, nullptr, BT, CC, CC, nullptr, nullptr);
    mmagemm<0><<<gCC, 256, GEMM_SMEM>>>(XK, WkT, Kb, nullptr, BT, CC, CC, nullptr, nullptr);
    mmagemm<0><<<gCC, 256, GEMM_SMEM>>>(XV, WvT, Vb, nullptr, BT, CC, CC, nullptr, nullptr);
    mmagemm<1><<<gCC, 256, GEMM_SMEM>>>(XG, WgT, Gb, nullptr, BT, CC, CC, nullptr, nullptr);
    wkv_kernel<<<BB * HH * 2, 128>>>(Rb, Kb, Vb, tdec, tfaa, ATT);
    gn_gate_kernel<<<BT * HH / 8, 256>>>(ATT, Gb, lnx_g, lnx_b, AG);
    mmagemm<3><<<gCC, 256, GEMM_SMEM>>>(AG, WoT, X1, nullptr, BT, CC, CC, x, nullptr);

    // FFN half
    ln_kernel<<<BT, 256>>>(X1, ln2_g, ln2_b, XL2);
    mix2_kernel<<<BT * CC / 256, 256>>>(XL2, fm_k, fm_r, CK, CR);
    mmagemm<2><<<gFF, 256, GEMM_SMEM>>>(CK, WkeyT, nullptr, KK, BT, FFD, CC, nullptr, nullptr);
    mmagemm<0><<<gCC, 256, GEMM_SMEM>>>(KK, WvalT, KV, nullptr, BT, CC, FFD, nullptr, nullptr);
    mmagemm<4><<<gCC, 256, GEMM_SMEM>>>(CR, WreT, out, nullptr, BT, CC, CC, X1, KV);
}

// round 14
// speedup vs baseline: 6.4457x; 1.5678x over previous
#include <cuda_runtime.h>
#include <cuda_fp16.h>
#include <math.h>
#include <stdint.h>

#define BB 2
#define TT 1024
#define CC 2048
#define HH 32
#define NNH 64
#define FFD 8192
#define BT (BB*TT)
#define EPS_ 1e-5f

typedef __half h16;

// ---------------- scratch (device globals; allocation-free) ----------------
__device__ float g_XL [BT*CC];
__device__ float g_R  [BT*CC];
__device__ float g_K  [BT*CC];
__device__ float g_V  [BT*CC];
__device__ float g_G  [BT*CC];
__device__ float g_ATT[BT*CC];
__device__ float g_X1 [BT*CC];
__device__ float g_XL2[BT*CC];
__device__ float g_KV [BT*CC];

__device__ h16 g_XR[BT*CC], g_XK[BT*CC], g_XV[BT*CC], g_XG[BT*CC];
__device__ h16 g_AG[BT*CC], g_CK[BT*CC], g_CR[BT*CC];
__device__ h16 g_KK[(size_t)BT*FFD];

__device__ h16 g_WrT [CC*CC];
__device__ h16 g_WkT [CC*CC];
__device__ h16 g_WvT [CC*CC];
__device__ h16 g_WgT [CC*CC];
__device__ h16 g_WoT [CC*CC];
__device__ h16 g_WreT[CC*CC];
__device__ h16 g_WkeyT[(size_t)FFD*CC];
__device__ h16 g_WvalT[(size_t)CC*FFD];

// ---------------- helpers ----------------
__device__ __forceinline__ uint32_t s2u(const void* p) {
    uint32_t r;
    asm("{ .reg .u64 t; cvta.to.shared.u64 t, %1; cvt.u32.u64 %0, t; }" : "=r"(r) : "l"(p));
    return r;
}
#define CP_COMMIT() asm volatile("cp.async.commit_group;" ::: "memory")
#define CP_WAIT(n)  asm volatile("cp.async.wait_group %0;" :: "n"(n) : "memory")
__device__ __forceinline__ void cp16(uint32_t s, const void* g) {
    asm volatile("cp.async.cg.shared.global [%0], [%1], 16;" :: "r"(s), "l"(g));
}
__device__ __forceinline__ void ldm4(uint32_t* r, uint32_t a) {
    asm volatile("ldmatrix.sync.aligned.m8n8.x4.shared.b16 {%0,%1,%2,%3}, [%4];"
        : "=r"(r[0]), "=r"(r[1]), "=r"(r[2]), "=r"(r[3]) : "r"(a));
}
__device__ __forceinline__ void mma16816(float* d, const uint32_t* a, const uint32_t* b) {
    asm volatile(
        "mma.sync.aligned.m16n8k16.row.col.f32.f16.f16.f32 "
        "{%0,%1,%2,%3}, {%4,%5,%6,%7}, {%8,%9}, {%0,%1,%2,%3};"
        : "+f"(d[0]), "+f"(d[1]), "+f"(d[2]), "+f"(d[3])
        : "r"(a[0]), "r"(a[1]), "r"(a[2]), "r"(a[3]), "r"(b[0]), "r"(b[1]));
}
// 64B-row swizzle
__device__ __forceinline__ uint32_t SW64(uint32_t o) { return o ^ ((o >> 3) & 0x30); }

// ---------------- fused transpose + fp16:  W[K,N] -> Wt[N,K], 8 jobs -------
struct TransArgs {
    const float* src[8];
    h16* dst[8];
};
// jobs 0-5: 2048x2048 (1024 tiles) | job 6: Wkey K=2048,N=8192 (4096 tiles)
// job 7: Wval K=8192,N=2048 (4096 tiles).  Tile = 64x64, block (16,16).
__global__ void trans_all(TransArgs a) {
    __shared__ float t[64][65];
    const int bid = blockIdx.x;
    int job, tile;
    if (bid < 6144)       { job = bid >> 10; tile = bid & 1023; }
    else if (bid < 10240) { job = 6; tile = bid - 6144; }
    else                  { job = 7; tile = bid - 10240; }
    const int K = (job == 7) ? FFD : CC;
    const int N = (job == 6) ? FFD : CC;
    const int tn = N >> 6;
    const int k0 = (tile / tn) << 6;
    const int n0 = (tile % tn) << 6;
    const int tx = threadIdx.x, ty = threadIdx.y;
    const float* W = a.src[job];
#pragma unroll
    for (int i = 0; i < 4; i++) {
        const float4 q = *(const float4*)&W[(size_t)(k0 + ty + i * 16) * N + n0 + tx * 4];
        t[ty + i * 16][tx * 4 + 0] = q.x;
        t[ty + i * 16][tx * 4 + 1] = q.y;
        t[ty + i * 16][tx * 4 + 2] = q.z;
        t[ty + i * 16][tx * 4 + 3] = q.w;
    }
    __syncthreads();
    h16* T = a.dst[job];
#pragma unroll
    for (int i = 0; i < 4; i++) {
        const int n = ty + i * 16;
        const __half2 h01 = __floats2half2_rn(t[tx * 4 + 0][n], t[tx * 4 + 1][n]);
        const __half2 h23 = __floats2half2_rn(t[tx * 4 + 2][n], t[tx * 4 + 3][n]);
        uint2 pk;
        pk.x = *(const uint32_t*)&h01;
        pk.y = *(const uint32_t*)&h23;
        *(uint2*)&T[(size_t)(n0 + n) * K + k0 + tx * 4] = pk;
    }
}

// ---------------- mma.sync GEMM: D = A @ B^T, single-pass FP16 -------------
// A: [M,K] fp16; B: [N,K] fp16. Block 128x128, BK=32, 3 cp.async stages,
// ONE barrier per k-iter, 2 CTAs/SM. 8 warps: 2x4, warp tile 64x32.
// EPI: 0 fp32 | 1 silu | 2 relu^2 -> fp16 | 3 aux1+acc | 4 aux1+sigmoid(acc)*aux2
#define OFF_A 0
#define OFF_B 8192
#define STG   16384
#define GEMM_SMEM (3 * STG)

template <int EPI>
__global__ __launch_bounds__(256, 2)
void mmagemm(const h16* __restrict__ Ah, const h16* __restrict__ Bh,
             float* __restrict__ C, h16* __restrict__ Ch,
             int M, int N, int K,
             const float* __restrict__ aux1, const float* __restrict__ aux2) {
    extern __shared__ __align__(1024) char smem[];
    const uint32_t sb = s2u(smem);
    const int tid = threadIdx.x;
    const int row0 = blockIdx.y * 128;
    const int col0 = blockIdx.x * 128;
    const int NK = K / 32;

    const int r0 = tid >> 2, c0 = tid & 3;
    const int r1 = (tid + 256) >> 2, c1 = tid & 3;
    const uint32_t so0 = SW64((uint32_t)(r0 * 64 + c0 * 16));
    const uint32_t so1 = SW64((uint32_t)(r1 * 64 + c1 * 16));
    const h16* pA0 = Ah + (size_t)(row0 + r0) * K + c0 * 8;
    const h16* pA1 = Ah + (size_t)(row0 + r1) * K + c1 * 8;
    const h16* pB0 = Bh + (size_t)(col0 + r0) * K + c0 * 8;
    const h16* pB1 = Bh + (size_t)(col0 + r1) * K + c1 * 8;

    auto load_stage = [&](int kb, int st) {
        const uint32_t s = sb + (uint32_t)st * STG;
        const size_t ko = (size_t)kb * 32;
        cp16(s + OFF_A + so0, pA0 + ko); cp16(s + OFF_A + so1, pA1 + ko);
        cp16(s + OFF_B + so0, pB0 + ko); cp16(s + OFF_B + so1, pB1 + ko);
        CP_COMMIT();
    };

    const int wid = tid >> 5, lane = tid & 31;
    const int wm = wid & 1, wn = wid >> 1;
    const int wmb = wm * 64, wnb = wn * 32;
    const uint32_t a_row  = (uint32_t)(wmb + (lane & 15));
    const uint32_t a_csel = (uint32_t)((lane >> 4) << 4);
    const uint32_t b_row  = (uint32_t)(wnb + ((lane >> 4) << 3) + (lane & 7));
    const uint32_t b_csel = (uint32_t)(((lane >> 3) & 1) << 4);

    float acc[4][4][4];
#pragma unroll
    for (int i = 0; i < 4; i++)
#pragma unroll
        for (int j = 0; j < 4; j++)
#pragma unroll
            for (int q = 0; q < 4; q++) acc[i][j][q] = 0.f;

    load_stage(0, 0);
    if (NK > 1) load_stage(1, 1);

#pragma unroll 1
    for (int kb = 0; kb < NK; kb++) {
        if (kb + 1 < NK) { CP_WAIT(1); } else { CP_WAIT(0); }
        __syncthreads();

        const uint32_t us = sb + (uint32_t)(kb % 3) * STG;
#pragma unroll
        for (int ks = 0; ks < 2; ks++) {
            uint32_t a[4][4], bfr[2][4];
#pragma unroll
            for (int mt = 0; mt < 4; mt++) {
                const uint32_t off = (a_row + mt * 16) * 64 + (uint32_t)(ks * 32) + a_csel;
                ldm4(a[mt], us + OFF_A + SW64(off));
            }
#pragma unroll
            for (int bp = 0; bp < 2; bp++) {
                const uint32_t off = (b_row + bp * 16) * 64 + (uint32_t)(ks * 32) + b_csel;
                ldm4(bfr[bp], us + OFF_B + SW64(off));
            }
#pragma unroll
            for (int mt = 0; mt < 4; mt++)
#pragma unroll
                for (int nt = 0; nt < 4; nt++)
                    mma16816(acc[mt][nt], a[mt], &bfr[nt >> 1][(nt & 1) * 2]);
        }
        if (kb + 2 < NK) load_stage(kb + 2, (kb + 2) % 3);
    }

    const int mrow = row0 + wmb + (lane >> 2);
    const int ncol = col0 + wnb + (lane & 3) * 2;
#pragma unroll
    for (int mt = 0; mt < 4; mt++) {
#pragma unroll
        for (int half = 0; half < 2; half++) {
            const size_t m = (size_t)(mrow + mt * 16 + half * 8);
#pragma unroll
            for (int nt = 0; nt < 4; nt++) {
                float vx = acc[mt][nt][half * 2 + 0];
                float vy = acc[mt][nt][half * 2 + 1];
                const size_t idx = m * N + (ncol + nt * 8);
                if (EPI == 1) {
                    vx /= (1.f + expf(-vx)); vy /= (1.f + expf(-vy));
                } else if (EPI == 3) {
                    vx += aux1[idx]; vy += aux1[idx + 1];
                } else if (EPI == 4) {
                    vx = aux1[idx]     + aux2[idx]     / (1.f + expf(-vx));
                    vy = aux1[idx + 1] + aux2[idx + 1] / (1.f + expf(-vy));
                }
                if (EPI == 2) {
                    vx = fmaxf(vx, 0.f); vx *= vx;
                    vy = fmaxf(vy, 0.f); vy *= vy;
                    __half2 hp;
                    hp.x = __float2half_rn(vx); hp.y = __float2half_rn(vy);
                    *(__half2*)&Ch[idx] = hp;
                } else {
                    float2 p; p.x = vx; p.y = vy;
                    *(float2*)&C[idx] = p;
                }
            }
        }
    }
}

// ---------------- LayerNorm over last dim (C=2048), one block per row ------
__global__ void ln_kernel(const float* __restrict__ x, const float* __restrict__ g,
                          const float* __restrict__ b, float* __restrict__ out) {
    __shared__ float sa[8], sb_[8];
    const int row = blockIdx.x;
    const float4* xr = (const float4*)(x + (size_t)row * CC);
    float4 v[2];
    float s = 0.f, s2 = 0.f;
#pragma unroll
    for (int it = 0; it < 2; it++) {
        float4 q = xr[threadIdx.x + it * 256];
        v[it] = q;
        s  += q.x + q.y + q.z + q.w;
        s2 += q.x*q.x + q.y*q.y + q.z*q.z + q.w*q.w;
    }
#pragma unroll
    for (int o = 16; o; o >>= 1) {
        s  += __shfl_xor_sync(0xffffffffu, s,  o);
        s2 += __shfl_xor_sync(0xffffffffu, s2, o);
    }
    const int wid = threadIdx.x >> 5, lane = threadIdx.x & 31;
    if (!lane) { sa[wid] = s; sb_[wid] = s2; }
    __syncthreads();
    if (threadIdx.x == 0) {
        float ts = 0.f, ts2 = 0.f;
#pragma unroll
        for (int i = 0; i < 8; i++) { ts += sa[i]; ts2 += sb_[i]; }
        sa[0] = ts; sb_[0] = ts2;
    }
    __syncthreads();
    const float mean = sa[0] * (1.f / CC);
    const float var  = sb_[0] * (1.f / CC) - mean * mean;
    const float rstd = rsqrtf(var + EPS_);
    float4* op = (float4*)(out + (size_t)row * CC);
#pragma unroll
    for (int it = 0; it < 2; it++) {
        const int i4 = threadIdx.x + it * 256;
        float4 q  = v[it];
        float4 gg = ((const float4*)g)[i4];
        float4 bq = ((const float4*)b)[i4];
        q.x = (q.x - mean) * rstd * gg.x + bq.x;
        q.y = (q.y - mean) * rstd * gg.y + bq.y;
        q.z = (q.z - mean) * rstd * gg.z + bq.z;
        q.w = (q.w - mean) * rstd * gg.w + bq.w;
        op[i4] = q;
    }
}

// ---------------- time-shift mixes (fp16 outputs) ----------------
__global__ void mix4_kernel(const float* __restrict__ xl,
                            const float* __restrict__ mk, const float* __restrict__ mv,
                            const float* __restrict__ mr, const float* __restrict__ mg,
                            h16* xk, h16* xv, h16* xr, h16* xg) {
    const size_t idx = (size_t)blockIdx.x * blockDim.x + threadIdx.x;
    const int c = (int)(idx & (CC - 1));
    const int t = (int)((idx >> 11) & (TT - 1));
    const float cur  = xl[idx];
    const float prev = (t > 0) ? xl[idx - CC] : 0.f;
    const float d = cur - prev;
    xk[idx] = __float2half_rn(prev + mk[c] * d);
    xv[idx] = __float2half_rn(prev + mv[c] * d);
    xr[idx] = __float2half_rn(prev + mr[c] * d);
    xg[idx] = __float2half_rn(prev + mg[c] * d);
}

__global__ void mix2_kernel(const float* __restrict__ xl,
                            const float* __restrict__ mk, const float* __restrict__ mr,
                            h16* ck, h16* cr) {
    const size_t idx = (size_t)blockIdx.x * blockDim.x + threadIdx.x;
    const int c = (int)(idx & (CC - 1));
    const int t = (int)((idx >> 11) & (TT - 1));
    const float cur  = xl[idx];
    const float prev = (t > 0) ? xl[idx - CC] : 0.f;
    const float d = cur - prev;
    ck[idx] = __float2half_rn(prev + mk[c] * d);
    cr[idx] = __float2half_rn(prev + mr[c] * d);
}

// ---------------- WKV5 recurrence, chunked cp.async staging ----------------
// block per (b,h,jc): 128 threads; thread = (j,p): j = jc*32 + tid>>2,
// p = tid&3 owns i-range [16p,16p+16).  Chunks of TC=32 timesteps double-
// buffered in smem -> ONE barrier per 32 steps, zero global latency in loop.
// Staging per chunk: r,k = 32t x 64ch = 2048 floats each -> 4 cp16/thread;
// v = 32t x 32ch = 1024 floats -> 2 cp16/thread.
// y_j = sum_i r_i*(u_i*k_i*v_j + S[i][j]);  S = dec*S + k_i*v_j
#define TC 32
#define WKV_SMEM (10240 * 4)   // sr 2*2048 + sk 2*2048 + sv 2*1024 floats

__global__ __launch_bounds__(128)
void wkv_kernel(const float* __restrict__ r, const float* __restrict__ k,
                const float* __restrict__ v, const float* __restrict__ w,
                const float* __restrict__ u, float* __restrict__ att) {
    extern __shared__ __align__(16) float sm[];
    // layout (floats): sr[buf][t][64] @ 0, sk @ 4096, sv[buf][t][32] @ 8192
    float* const srm = sm;
    float* const skm = sm + 4096;
    float* const svm = sm + 8192;
    const uint32_t sr_u = s2u(srm), sk_u = s2u(skm), sv_u = s2u(svm);

    const int blk = blockIdx.x;
    const int jc = blk & 1;
    const int bh = blk >> 1;
    const int b = bh / HH, h = bh % HH;
    const int tid = threadIdx.x;
    const int jl = tid >> 2;          // 0..31
    const int j = jc * 32 + jl;
    const int p = tid & 3;

    const size_t base = ((size_t)b * TT * HH + h) * NNH;   // t stride = 2048

    // staging maps
    const int srow = tid >> 2;                 // r/k timestep row 0..31
    const int scb  = (tid & 3) * 16;           // r/k channel base 0,16,32,48
    const uint32_t s_dst = (uint32_t)((srow * 64 + scb) * 4);
    const int vrow0 = tid >> 3, vunit0 = tid & 7;   // v: 2 ops
    const int vrow1 = (tid + 128) >> 3, vunit1 = tid & 7;
    const uint32_t v_dst0 = (uint32_t)((vrow0 * 32 + vunit0 * 4) * 4);
    const uint32_t v_dst1 = (uint32_t)((vrow1 * 32 + vunit1 * 4) * 4);

    auto stage = [&](int ch, int buf) {
        const int t0 = ch * TC;
        const uint32_t bo = (uint32_t)(buf * 2048 * 4);
        const uint32_t bv = (uint32_t)(buf * 1024 * 4);
        const float* rg = r + base + (size_t)(t0 + srow) * 2048 + scb;
        const float* kg = k + base + (size_t)(t0 + srow) * 2048 + scb;
#pragma unroll
        for (int q = 0; q < 4; q++) {
            cp16(sr_u + bo + s_dst + q * 16, rg + q * 4);
            cp16(sk_u + bo + s_dst + q * 16, kg + q * 4);
        }
        cp16(sv_u + bv + v_dst0, v + base + (size_t)(t0 + vrow0) * 2048 + jc * 32 + vunit0 * 4);
        cp16(sv_u + bv + v_dst1, v + base + (size_t)(t0 + vrow1) * 2048 + jc * 32 + vunit1 * 4);
        CP_COMMIT();
    };

    float S[16], dec[16], uu[16];
#pragma unroll
    for (int ii = 0; ii < 16; ii++) S[ii] = 0.f;
#pragma unroll
    for (int ii = 0; ii < 16; ii++) {
        const float wv = w[h * NNH + p * 16 + ii];
        dec[ii] = expf(-expf(wv));
        uu[ii]  = u[h * NNH + p * 16 + ii];
    }

    stage(0, 0);

    const int NC = TT / TC;   // 32
#pragma unroll 1
    for (int ch = 0; ch < NC; ch++) {
        CP_WAIT(0);
        __syncthreads();
        if (ch + 1 < NC) stage(ch + 1, (ch + 1) & 1);
        const int buf = ch & 1;
        const float* rp = srm + buf * 2048 + p * 16;
        const float* kp = skm + buf * 2048 + p * 16;
        const float* vp = svm + buf * 1024 + jl;
        const int t0 = ch * TC;
#pragma unroll 2
        for (int tt = 0; tt < TC; tt++) {
            float rr[16], kk[16];
            *(float4*)&rr[0]  = *(const float4*)(rp + tt * 64 + 0);
            *(float4*)&rr[4]  = *(const float4*)(rp + tt * 64 + 4);
            *(float4*)&rr[8]  = *(const float4*)(rp + tt * 64 + 8);
            *(float4*)&rr[12] = *(const float4*)(rp + tt * 64 + 12);
            *(float4*)&kk[0]  = *(const float4*)(kp + tt * 64 + 0);
            *(float4*)&kk[4]  = *(const float4*)(kp + tt * 64 + 4);
            *(float4*)&kk[8]  = *(const float4*)(kp + tt * 64 + 8);
            *(float4*)&kk[12] = *(const float4*)(kp + tt * 64 + 12);
            const float vj = vp[tt * 32];
            float yp = 0.f;
#pragma unroll
            for (int ii = 0; ii < 16; ii++) {
                const float kv = kk[ii] * vj;
                yp = fmaf(rr[ii], fmaf(uu[ii], kv, S[ii]), yp);
                S[ii] = fmaf(dec[ii], S[ii], kv);
            }
            float y = yp + __shfl_xor_sync(0xffffffffu, yp, 1);
            y += __shfl_xor_sync(0xffffffffu, y, 2);
            if (p == 0) att[base + (size_t)(t0 + tt) * 2048 + j] = y;
        }
    }
}

// ---------------- GroupNorm(att/DIV)*g+b, * gate, fp16 out ----------
__global__ void gn_gate_kernel(const float* __restrict__ att, const float* __restrict__ gq,
                               const float* __restrict__ gg, const float* __restrict__ gb,
                               h16* __restrict__ oh) {
    const int gid  = blockIdx.x * 8 + (threadIdx.x >> 5);
    const int lane = threadIdx.x & 31;
    const int h = gid & (HH - 1);
    const size_t off = (size_t)gid * NNH;
    const float inv_div = 1.f / 8.f;
    const float v0 = att[off + lane]      * inv_div;
    const float v1 = att[off + lane + 32] * inv_div;
    float s = v0 + v1, s2 = v0 * v0 + v1 * v1;
#pragma unroll
    for (int o = 16; o; o >>= 1) {
        s  += __shfl_xor_sync(0xffffffffu, s,  o);
        s2 += __shfl_xor_sync(0xffffffffu, s2, o);
    }
    const float m = s * (1.f / NNH);
    const float var = s2 * (1.f / NNH) - m * m;
    const float rstd = rsqrtf(var + EPS_);
    const int c0 = h * NNH + lane;
    const float o0 = ((v0 - m) * rstd * gg[c0]      + gb[c0])      * gq[off + lane];
    const float o1 = ((v1 - m) * rstd * gg[c0 + 32] + gb[c0 + 32]) * gq[off + lane + 32];
    oh[off + lane]      = __float2half_rn(o0);
    oh[off + lane + 32] = __float2half_rn(o1);
}

// ---------------- launch ----------------
extern "C" void kernel_launch(void* const* d_in, const int* in_sizes, int n_in,
                              void* d_out, int out_size) {
    (void)in_sizes; (void)n_in; (void)out_size;
    const float* x     = (const float*)d_in[0];
    const float* ln1_g = (const float*)d_in[1];
    const float* ln1_b = (const float*)d_in[2];
    const float* ln2_g = (const float*)d_in[3];
    const float* ln2_b = (const float*)d_in[4];
    const float* tm_k  = (const float*)d_in[5];
    const float* tm_v  = (const float*)d_in[6];
    const float* tm_r  = (const float*)d_in[7];
    const float* tm_g  = (const float*)d_in[8];
    const float* tdec  = (const float*)d_in[9];
    const float* tfaa  = (const float*)d_in[10];
    const float* Wr    = (const float*)d_in[11];
    const float* Wk    = (const float*)d_in[12];
    const float* Wv    = (const float*)d_in[13];
    const float* Wg    = (const float*)d_in[14];
    const float* Wo    = (const float*)d_in[15];
    const float* lnx_g = (const float*)d_in[16];
    const float* lnx_b = (const float*)d_in[17];
    const float* fm_k  = (const float*)d_in[18];
    const float* fm_r  = (const float*)d_in[19];
    const float* Wkey  = (const float*)d_in[20];
    const float* Wrec  = (const float*)d_in[21];
    const float* Wval  = (const float*)d_in[22];
    float* out = (float*)d_out;

    float *XL, *Rb, *Kb, *Vb, *Gb, *ATT, *X1, *XL2, *KV;
    cudaGetSymbolAddress((void**)&XL,  g_XL);
    cudaGetSymbolAddress((void**)&Rb,  g_R);
    cudaGetSymbolAddress((void**)&Kb,  g_K);
    cudaGetSymbolAddress((void**)&Vb,  g_V);
    cudaGetSymbolAddress((void**)&Gb,  g_G);
    cudaGetSymbolAddress((void**)&ATT, g_ATT);
    cudaGetSymbolAddress((void**)&X1,  g_X1);
    cudaGetSymbolAddress((void**)&XL2, g_XL2);
    cudaGetSymbolAddress((void**)&KV,  g_KV);

    h16 *XR,*XK,*XV,*XG,*AG,*CK,*CR,*KK;
    cudaGetSymbolAddress((void**)&XR, g_XR);
    cudaGetSymbolAddress((void**)&XK, g_XK);
    cudaGetSymbolAddress((void**)&XV, g_XV);
    cudaGetSymbolAddress((void**)&XG, g_XG);
    cudaGetSymbolAddress((void**)&AG, g_AG);
    cudaGetSymbolAddress((void**)&CK, g_CK);
    cudaGetSymbolAddress((void**)&CR, g_CR);
    cudaGetSymbolAddress((void**)&KK, g_KK);

    TransArgs ta;
    ta.src[0] = Wr;   cudaGetSymbolAddress((void**)&ta.dst[0], g_WrT);
    ta.src[1] = Wk;   cudaGetSymbolAddress((void**)&ta.dst[1], g_WkT);
    ta.src[2] = Wv;   cudaGetSymbolAddress((void**)&ta.dst[2], g_WvT);
    ta.src[3] = Wg;   cudaGetSymbolAddress((void**)&ta.dst[3], g_WgT);
    ta.src[4] = Wo;   cudaGetSymbolAddress((void**)&ta.dst[4], g_WoT);
    ta.src[5] = Wrec; cudaGetSymbolAddress((void**)&ta.dst[5], g_WreT);
    ta.src[6] = Wkey; cudaGetSymbolAddress((void**)&ta.dst[6], g_WkeyT);
    ta.src[7] = Wval; cudaGetSymbolAddress((void**)&ta.dst[7], g_WvalT);
    h16* WrT  = ta.dst[0]; h16* WkT  = ta.dst[1]; h16* WvT   = ta.dst[2];
    h16* WgT  = ta.dst[3]; h16* WoT  = ta.dst[4]; h16* WreT  = ta.dst[5];
    h16* WkeyT = ta.dst[6]; h16* WvalT = ta.dst[7];

    cudaFuncSetAttribute(mmagemm<0>, cudaFuncAttributeMaxDynamicSharedMemorySize, GEMM_SMEM);
    cudaFuncSetAttribute(mmagemm<1>, cudaFuncAttributeMaxDynamicSharedMemorySize, GEMM_SMEM);
    cudaFuncSetAttribute(mmagemm<2>, cudaFuncAttributeMaxDynamicSharedMemorySize, GEMM_SMEM);
    cudaFuncSetAttribute(mmagemm<3>, cudaFuncAttributeMaxDynamicSharedMemorySize, GEMM_SMEM);
    cudaFuncSetAttribute(mmagemm<4>, cudaFuncAttributeMaxDynamicSharedMemorySize, GEMM_SMEM);
    cudaFuncSetAttribute(wkv_kernel, cudaFuncAttributeMaxDynamicSharedMemorySize, WKV_SMEM);

    trans_all<<<14336, dim3(16, 16)>>>(ta);

    const dim3 gCC(CC / 128, BT / 128);    // (16,16)
    const dim3 gFF(FFD / 128, BT / 128);   // (64,16)

    // attention half
    ln_kernel<<<BT, 256>>>(x, ln1_g, ln1_b, XL);
    mix4_kernel<<<BT * CC / 256, 256>>>(XL, tm_k, tm_v, tm_r, tm_g, XK, XV, XR, XG);
    mmagemm<0><<<gCC, 256, GEMM_SMEM>>>(XR, WrT, Rb, nullptr, BT, CC, CC, nullptr, nullptr);
    mmagemm<0><<<gCC, 256, GEMM_SMEM>>>(XK, WkT, Kb, nullptr, BT, CC, CC, nullptr, nullptr);
    mmagemm<0><<<gCC, 256, GEMM_SMEM>>>(XV, WvT, Vb, nullptr, BT, CC, CC, nullptr, nullptr);
    mmagemm<1><<<gCC, 256, GEMM_SMEM>>>(XG, WgT, Gb, nullptr, BT, CC, CC, nullptr, nullptr);
    wkv_kernel<<<BB * HH * 2, 128, WKV_SMEM>>>(Rb, Kb, Vb, tdec, tfaa, ATT);
    gn_gate_kernel<<<BT * HH / 8, 256>>>(ATT, Gb, lnx_g, lnx_b, AG);
    mmagemm<3><<<gCC, 256, GEMM_SMEM>>>(AG, WoT, X1, nullptr, BT, CC, CC, x, nullptr);

    // FFN half
    ln_kernel<<<BT, 256>>>(X1, ln2_g, ln2_b, XL2);
    mix2_kernel<<<BT * CC / 256, 256>>>(XL2, fm_k, fm_r, CK, CR);
    mmagemm<2><<<gFF, 256, GEMM_SMEM>>>(CK, WkeyT, nullptr, KK, BT, FFD, CC, nullptr, nullptr);
    mmagemm<0><<<gCC, 256, GEMM_SMEM>>>(KK, WvalT, KV, nullptr, BT, CC, FFD, nullptr, nullptr);
    mmagemm<4><<<gCC, 256, GEMM_SMEM>>>(CR, WreT, out, nullptr, BT, CC, CC, X1, KV);
}

// round 15
// speedup vs baseline: 7.1469x; 1.1088x over previous
#include <cuda_runtime.h>
#include <cuda_fp16.h>
#include <math.h>
#include <stdint.h>

#define BB 2
#define TT 1024
#define CC 2048
#define HH 32
#define NNH 64
#define FFD 8192
#define BT (BB*TT)
#define EPS_ 1e-5f

typedef __half h16;

// ---------------- scratch (device globals; allocation-free) ----------------
__device__ float g_XL [BT*CC];
__device__ float g_R  [BT*CC];
__device__ float g_K  [BT*CC];
__device__ float g_V  [BT*CC];
__device__ float g_G  [BT*CC];
__device__ float g_ATT[BT*CC];
__device__ float g_X1 [BT*CC];
__device__ float g_XL2[BT*CC];
__device__ float g_KV [BT*CC];

__device__ h16 g_XR[BT*CC], g_XK[BT*CC], g_XV[BT*CC], g_XG[BT*CC];
__device__ h16 g_AG[BT*CC], g_CK[BT*CC], g_CR[BT*CC];
__device__ h16 g_KK[(size_t)BT*FFD];

__device__ h16 g_WrT [CC*CC];
__device__ h16 g_WkT [CC*CC];
__device__ h16 g_WvT [CC*CC];
__device__ h16 g_WgT [CC*CC];
__device__ h16 g_WoT [CC*CC];
__device__ h16 g_WreT[CC*CC];
__device__ h16 g_WkeyT[(size_t)FFD*CC];
__device__ h16 g_WvalT[(size_t)CC*FFD];

// ---------------- helpers ----------------
__device__ __forceinline__ uint32_t s2u(const void* p) {
    uint32_t r;
    asm("{ .reg .u64 t; cvta.to.shared.u64 t, %1; cvt.u32.u64 %0, t; }" : "=r"(r) : "l"(p));
    return r;
}
#define CP_COMMIT() asm volatile("cp.async.commit_group;" ::: "memory")
#define CP_WAIT(n)  asm volatile("cp.async.wait_group %0;" :: "n"(n) : "memory")
__device__ __forceinline__ void cp16(uint32_t s, const void* g) {
    asm volatile("cp.async.cg.shared.global [%0], [%1], 16;" :: "r"(s), "l"(g));
}
__device__ __forceinline__ void ldm4(uint32_t* r, uint32_t a) {
    asm volatile("ldmatrix.sync.aligned.m8n8.x4.shared.b16 {%0,%1,%2,%3}, [%4];"
        : "=r"(r[0]), "=r"(r[1]), "=r"(r[2]), "=r"(r[3]) : "r"(a));
}
__device__ __forceinline__ void mma16816(float* d, const uint32_t* a, const uint32_t* b) {
    asm volatile(
        "mma.sync.aligned.m16n8k16.row.col.f32.f16.f16.f32 "
        "{%0,%1,%2,%3}, {%4,%5,%6,%7}, {%8,%9}, {%0,%1,%2,%3};"
        : "+f"(d[0]), "+f"(d[1]), "+f"(d[2]), "+f"(d[3])
        : "r"(a[0]), "r"(a[1]), "r"(a[2]), "r"(a[3]), "r"(b[0]), "r"(b[1]));
}
// 128B-row swizzle: 16B-unit index (bits 4-6) XOR row&7 (bits 7-9)
__device__ __forceinline__ uint32_t SWZ(uint32_t o) { return o ^ ((o >> 3) & 0x70); }

// ---------------- fused transpose + fp16:  W[K,N] -> Wt[N,K], 8 jobs -------
struct TransArgs {
    const float* src[8];
    h16* dst[8];
};
__global__ void trans_all(TransArgs a) {
    __shared__ float t[64][65];
    const int bid = blockIdx.x;
    int job, tile;
    if (bid < 6144)       { job = bid >> 10; tile = bid & 1023; }
    else if (bid < 10240) { job = 6; tile = bid - 6144; }
    else                  { job = 7; tile = bid - 10240; }
    const int K = (job == 7) ? FFD : CC;
    const int N = (job == 6) ? FFD : CC;
    const int tn = N >> 6;
    const int k0 = (tile / tn) << 6;
    const int n0 = (tile % tn) << 6;
    const int tx = threadIdx.x, ty = threadIdx.y;
    const float* W = a.src[job];
#pragma unroll
    for (int i = 0; i < 4; i++) {
        const float4 q = *(const float4*)&W[(size_t)(k0 + ty + i * 16) * N + n0 + tx * 4];
        t[ty + i * 16][tx * 4 + 0] = q.x;
        t[ty + i * 16][tx * 4 + 1] = q.y;
        t[ty + i * 16][tx * 4 + 2] = q.z;
        t[ty + i * 16][tx * 4 + 3] = q.w;
    }
    __syncthreads();
    h16* T = a.dst[job];
#pragma unroll
    for (int i = 0; i < 4; i++) {
        const int n = ty + i * 16;
        const __half2 h01 = __floats2half2_rn(t[tx * 4 + 0][n], t[tx * 4 + 1][n]);
        const __half2 h23 = __floats2half2_rn(t[tx * 4 + 2][n], t[tx * 4 + 3][n]);
        uint2 pk;
        pk.x = *(const uint32_t*)&h01;
        pk.y = *(const uint32_t*)&h23;
        *(uint2*)&T[(size_t)(n0 + n) * K + k0 + tx * 4] = pk;
    }
}

// ---------------- mma.sync GEMM core: D = A @ B^T, fp16, BK=64 -------------
// Block 128x128, BK=64, 3 cp.async stages (96KB), one barrier per 64-K chunk,
// 2 CTAs/SM. 8 warps: 2x4, warp tile 64x32.
// EPI: 0 fp32 | 1 silu | 2 relu^2 -> fp16 | 3 aux1+acc | 4 aux1+sigmoid(acc)*aux2
#define OFF_A 0
#define OFF_B 16384
#define STG   32768
#define GEMM_SMEM (3 * STG)

template <int EPI>
__device__ __forceinline__ void gemm_body(
        const h16* __restrict__ Ah, const h16* __restrict__ Bh,
        float* __restrict__ C, h16* __restrict__ Ch,
        int M, int N, int K, int row0, int col0,
        const float* __restrict__ aux1, const float* __restrict__ aux2,
        char* smem) {
    const uint32_t sb = s2u(smem);
    const int tid = threadIdx.x;
    const int NK = K / 64;

    // staging: per matrix per chunk = 128 rows x 8 16B-units; 4 passes/thread
    const int sr = tid >> 3, su = tid & 7;
    uint32_t sdst[4];
#pragma unroll
    for (int p = 0; p < 4; p++) sdst[p] = SWZ((uint32_t)((sr + 32 * p) * 128 + su * 16));
    const h16* pA = Ah + (size_t)(row0 + sr) * K + su * 8;
    const h16* pB = Bh + (size_t)(col0 + sr) * K + su * 8;
    const size_t rs = (size_t)32 * K;

    auto load_stage = [&](int kb, int st) {
        const uint32_t s = sb + (uint32_t)st * STG;
        const size_t ko = (size_t)kb * 64;
#pragma unroll
        for (int p = 0; p < 4; p++) cp16(s + OFF_A + sdst[p], pA + p * rs + ko);
#pragma unroll
        for (int p = 0; p < 4; p++) cp16(s + OFF_B + sdst[p], pB + p * rs + ko);
        CP_COMMIT();
    };

    const int wid = tid >> 5, lane = tid & 31;
    const int wm = wid & 1, wn = wid >> 1;
    const int wmb = wm * 64, wnb = wn * 32;
    const uint32_t a_row  = (uint32_t)(wmb + (lane & 15));
    const uint32_t a_csel = (uint32_t)((lane >> 4) << 4);
    const uint32_t b_row  = (uint32_t)(wnb + ((lane >> 4) << 3) + (lane & 7));
    const uint32_t b_csel = (uint32_t)(((lane >> 3) & 1) << 4);

    float acc[4][4][4];
#pragma unroll
    for (int i = 0; i < 4; i++)
#pragma unroll
        for (int j = 0; j < 4; j++)
#pragma unroll
            for (int q = 0; q < 4; q++) acc[i][j][q] = 0.f;

    load_stage(0, 0);
    if (NK > 1) load_stage(1, 1);

#pragma unroll 1
    for (int kb = 0; kb < NK; kb++) {
        if (kb + 1 < NK) { CP_WAIT(1); } else { CP_WAIT(0); }
        __syncthreads();

        const uint32_t us = sb + (uint32_t)(kb % 3) * STG;
#pragma unroll
        for (int ks = 0; ks < 4; ks++) {
            uint32_t a[4][4], bfr[2][4];
#pragma unroll
            for (int mt = 0; mt < 4; mt++) {
                const uint32_t off = (a_row + mt * 16) * 128 + (uint32_t)(ks * 32) + a_csel;
                ldm4(a[mt], us + OFF_A + SWZ(off));
            }
#pragma unroll
            for (int bp = 0; bp < 2; bp++) {
                const uint32_t off = (b_row + bp * 16) * 128 + (uint32_t)(ks * 32) + b_csel;
                ldm4(bfr[bp], us + OFF_B + SWZ(off));
            }
#pragma unroll
            for (int mt = 0; mt < 4; mt++)
#pragma unroll
                for (int nt = 0; nt < 4; nt++)
                    mma16816(acc[mt][nt], a[mt], &bfr[nt >> 1][(nt & 1) * 2]);
        }
        if (kb + 2 < NK) load_stage(kb + 2, (kb + 2) % 3);
    }

    const int mrow = row0 + wmb + (lane >> 2);
    const int ncol = col0 + wnb + (lane & 3) * 2;
#pragma unroll
    for (int mt = 0; mt < 4; mt++) {
#pragma unroll
        for (int half = 0; half < 2; half++) {
            const size_t m = (size_t)(mrow + mt * 16 + half * 8);
#pragma unroll
            for (int nt = 0; nt < 4; nt++) {
                float vx = acc[mt][nt][half * 2 + 0];
                float vy = acc[mt][nt][half * 2 + 1];
                const size_t idx = m * N + (ncol + nt * 8);
                if (EPI == 1) {
                    vx /= (1.f + expf(-vx)); vy /= (1.f + expf(-vy));
                } else if (EPI == 3) {
                    vx += aux1[idx]; vy += aux1[idx + 1];
                } else if (EPI == 4) {
                    vx = aux1[idx]     + aux2[idx]     / (1.f + expf(-vx));
                    vy = aux1[idx + 1] + aux2[idx + 1] / (1.f + expf(-vy));
                }
                if (EPI == 2) {
                    vx = fmaxf(vx, 0.f); vx *= vx;
                    vy = fmaxf(vy, 0.f); vy *= vy;
                    __half2 hp;
                    hp.x = __float2half_rn(vx); hp.y = __float2half_rn(vy);
                    *(__half2*)&Ch[idx] = hp;
                } else {
                    float2 p; p.x = vx; p.y = vy;
                    *(float2*)&C[idx] = p;
                }
            }
        }
    }
}

template <int EPI>
__global__ __launch_bounds__(256, 2)
void mmagemm(const h16* __restrict__ Ah, const h16* __restrict__ Bh,
             float* __restrict__ C, h16* __restrict__ Ch,
             int M, int N, int K,
             const float* __restrict__ aux1, const float* __restrict__ aux2) {
    extern __shared__ __align__(1024) char smem[];
    gemm_body<EPI>(Ah, Bh, C, Ch, M, N, K,
                   blockIdx.y * 128, blockIdx.x * 128, aux1, aux2, smem);
}

// Batched QKVG: grid (16,16,4); job 3 (G) gets silu, others plain fp32 out.
struct G4Args {
    const h16* A[4];
    const h16* B[4];
    float* C[4];
};
__global__ __launch_bounds__(256, 2)
void gemm_qkvg(G4Args ga) {
    extern __shared__ __align__(1024) char smem[];
    const int job = blockIdx.z;
    if (job == 3)
        gemm_body<1>(ga.A[3], ga.B[3], ga.C[3], nullptr, BT, CC, CC,
                     blockIdx.y * 128, blockIdx.x * 128, nullptr, nullptr, smem);
    else
        gemm_body<0>(ga.A[job], ga.B[job], ga.C[job], nullptr, BT, CC, CC,
                     blockIdx.y * 128, blockIdx.x * 128, nullptr, nullptr, smem);
}

// ---------------- LayerNorm over last dim (C=2048), one block per row ------
__global__ void ln_kernel(const float* __restrict__ x, const float* __restrict__ g,
                          const float* __restrict__ b, float* __restrict__ out) {
    __shared__ float sa[8], sb_[8];
    const int row = blockIdx.x;
    const float4* xr = (const float4*)(x + (size_t)row * CC);
    float4 v[2];
    float s = 0.f, s2 = 0.f;
#pragma unroll
    for (int it = 0; it < 2; it++) {
        float4 q = xr[threadIdx.x + it * 256];
        v[it] = q;
        s  += q.x + q.y + q.z + q.w;
        s2 += q.x*q.x + q.y*q.y + q.z*q.z + q.w*q.w;
    }
#pragma unroll
    for (int o = 16; o; o >>= 1) {
        s  += __shfl_xor_sync(0xffffffffu, s,  o);
        s2 += __shfl_xor_sync(0xffffffffu, s2, o);
    }
    const int wid = threadIdx.x >> 5, lane = threadIdx.x & 31;
    if (!lane) { sa[wid] = s; sb_[wid] = s2; }
    __syncthreads();
    if (threadIdx.x == 0) {
        float ts = 0.f, ts2 = 0.f;
#pragma unroll
        for (int i = 0; i < 8; i++) { ts += sa[i]; ts2 += sb_[i]; }
        sa[0] = ts; sb_[0] = ts2;
    }
    __syncthreads();
    const float mean = sa[0] * (1.f / CC);
    const float var  = sb_[0] * (1.f / CC) - mean * mean;
    const float rstd = rsqrtf(var + EPS_);
    float4* op = (float4*)(out + (size_t)row * CC);
#pragma unroll
    for (int it = 0; it < 2; it++) {
        const int i4 = threadIdx.x + it * 256;
        float4 q  = v[it];
        float4 gg = ((const float4*)g)[i4];
        float4 bq = ((const float4*)b)[i4];
        q.x = (q.x - mean) * rstd * gg.x + bq.x;
        q.y = (q.y - mean) * rstd * gg.y + bq.y;
        q.z = (q.z - mean) * rstd * gg.z + bq.z;
        q.w = (q.w - mean) * rstd * gg.w + bq.w;
        op[i4] = q;
    }
}

// ---------------- time-shift mixes (fp16 outputs) ----------------
__global__ void mix4_kernel(const float* __restrict__ xl,
                            const float* __restrict__ mk, const float* __restrict__ mv,
                            const float* __restrict__ mr, const float* __restrict__ mg,
                            h16* xk, h16* xv, h16* xr, h16* xg) {
    const size_t idx = (size_t)blockIdx.x * blockDim.x + threadIdx.x;
    const int c = (int)(idx & (CC - 1));
    const int t = (int)((idx >> 11) & (TT - 1));
    const float cur  = xl[idx];
    const float prev = (t > 0) ? xl[idx - CC] : 0.f;
    const float d = cur - prev;
    xk[idx] = __float2half_rn(prev + mk[c] * d);
    xv[idx] = __float2half_rn(prev + mv[c] * d);
    xr[idx] = __float2half_rn(prev + mr[c] * d);
    xg[idx] = __float2half_rn(prev + mg[c] * d);
}

__global__ void mix2_kernel(const float* __restrict__ xl,
                            const float* __restrict__ mk, const float* __restrict__ mr,
                            h16* ck, h16* cr) {
    const size_t idx = (size_t)blockIdx.x * blockDim.x + threadIdx.x;
    const int c = (int)(idx & (CC - 1));
    const int t = (int)((idx >> 11) & (TT - 1));
    const float cur  = xl[idx];
    const float prev = (t > 0) ? xl[idx - CC] : 0.f;
    const float d = cur - prev;
    ck[idx] = __float2half_rn(prev + mk[c] * d);
    cr[idx] = __float2half_rn(prev + mr[c] * d);
}

// ---------------- WKV5 recurrence, chunked cp.async staging ----------------
#define TC 32
#define WKV_SMEM (10240 * 4)

__global__ __launch_bounds__(128)
void wkv_kernel(const float* __restrict__ r, const float* __restrict__ k,
                const float* __restrict__ v, const float* __restrict__ w,
                const float* __restrict__ u, float* __restrict__ att) {
    extern __shared__ __align__(16) float sm[];
    float* const srm = sm;
    float* const skm = sm + 4096;
    float* const svm = sm + 8192;
    const uint32_t sr_u = s2u(srm), sk_u = s2u(skm), sv_u = s2u(svm);

    const int blk = blockIdx.x;
    const int jc = blk & 1;
    const int bh = blk >> 1;
    const int b = bh / HH, h = bh % HH;
    const int tid = threadIdx.x;
    const int jl = tid >> 2;
    const int j = jc * 32 + jl;
    const int p = tid & 3;

    const size_t base = ((size_t)b * TT * HH + h) * NNH;

    const int srow = tid >> 2;
    const int scb  = (tid & 3) * 16;
    const uint32_t s_dst = (uint32_t)((srow * 64 + scb) * 4);
    const int vrow0 = tid >> 3, vunit0 = tid & 7;
    const int vrow1 = (tid + 128) >> 3, vunit1 = tid & 7;
    const uint32_t v_dst0 = (uint32_t)((vrow0 * 32 + vunit0 * 4) * 4);
    const uint32_t v_dst1 = (uint32_t)((vrow1 * 32 + vunit1 * 4) * 4);

    auto stage = [&](int ch, int buf) {
        const int t0 = ch * TC;
        const uint32_t bo = (uint32_t)(buf * 2048 * 4);
        const uint32_t bv = (uint32_t)(buf * 1024 * 4);
        const float* rg = r + base + (size_t)(t0 + srow) * 2048 + scb;
        const float* kg = k + base + (size_t)(t0 + srow) * 2048 + scb;
#pragma unroll
        for (int q = 0; q < 4; q++) {
            cp16(sr_u + bo + s_dst + q * 16, rg + q * 4);
            cp16(sk_u + bo + s_dst + q * 16, kg + q * 4);
        }
        cp16(sv_u + bv + v_dst0, v + base + (size_t)(t0 + vrow0) * 2048 + jc * 32 + vunit0 * 4);
        cp16(sv_u + bv + v_dst1, v + base + (size_t)(t0 + vrow1) * 2048 + jc * 32 + vunit1 * 4);
        CP_COMMIT();
    };

    float S[16], dec[16], uu[16];
#pragma unroll
    for (int ii = 0; ii < 16; ii++) S[ii] = 0.f;
#pragma unroll
    for (int ii = 0; ii < 16; ii++) {
        const float wv = w[h * NNH + p * 16 + ii];
        dec[ii] = expf(-expf(wv));
        uu[ii]  = u[h * NNH + p * 16 + ii];
    }

    stage(0, 0);

    const int NC = TT / TC;
#pragma unroll 1
    for (int ch = 0; ch < NC; ch++) {
        CP_WAIT(0);
        __syncthreads();
        if (ch + 1 < NC) stage(ch + 1, (ch + 1) & 1);
        const int buf = ch & 1;
        const float* rp = srm + buf * 2048 + p * 16;
        const float* kp = skm + buf * 2048 + p * 16;
        const float* vp = svm + buf * 1024 + jl;
        const int t0 = ch * TC;
#pragma unroll 2
        for (int tt = 0; tt < TC; tt++) {
            float rr[16], kk[16];
            *(float4*)&rr[0]  = *(const float4*)(rp + tt * 64 + 0);
            *(float4*)&rr[4]  = *(const float4*)(rp + tt * 64 + 4);
            *(float4*)&rr[8]  = *(const float4*)(rp + tt * 64 + 8);
            *(float4*)&rr[12] = *(const float4*)(rp + tt * 64 + 12);
            *(float4*)&kk[0]  = *(const float4*)(kp + tt * 64 + 0);
            *(float4*)&kk[4]  = *(const float4*)(kp + tt * 64 + 4);
            *(float4*)&kk[8]  = *(const float4*)(kp + tt * 64 + 8);
            *(float4*)&kk[12] = *(const float4*)(kp + tt * 64 + 12);
            const float vj = vp[tt * 32];
            float yp = 0.f;
#pragma unroll
            for (int ii = 0; ii < 16; ii++) {
                const float kv = kk[ii] * vj;
                yp = fmaf(rr[ii], fmaf(uu[ii], kv, S[ii]), yp);
                S[ii] = fmaf(dec[ii], S[ii], kv);
            }
            float y = yp + __shfl_xor_sync(0xffffffffu, yp, 1);
            y += __shfl_xor_sync(0xffffffffu, y, 2);
            if (p == 0) att[base + (size_t)(t0 + tt) * 2048 + j] = y;
        }
    }
}

// ---------------- GroupNorm(att/DIV)*g+b, * gate, fp16 out ----------
__global__ void gn_gate_kernel(const float* __restrict__ att, const float* __restrict__ gq,
                               const float* __restrict__ gg, const float* __restrict__ gb,
                               h16* __restrict__ oh) {
    const int gid  = blockIdx.x * 8 + (threadIdx.x >> 5);
    const int lane = threadIdx.x & 31;
    const int h = gid & (HH - 1);
    const size_t off = (size_t)gid * NNH;
    const float inv_div = 1.f / 8.f;
    const float v0 = att[off + lane]      * inv_div;
    const float v1 = att[off + lane + 32] * inv_div;
    float s = v0 + v1, s2 = v0 * v0 + v1 * v1;
#pragma unroll
    for (int o = 16; o; o >>= 1) {
        s  += __shfl_xor_sync(0xffffffffu, s,  o);
        s2 += __shfl_xor_sync(0xffffffffu, s2, o);
    }
    const float m = s * (1.f / NNH);
    const float var = s2 * (1.f / NNH) - m * m;
    const float rstd = rsqrtf(var + EPS_);
    const int c0 = h * NNH + lane;
    const float o0 = ((v0 - m) * rstd * gg[c0]      + gb[c0])      * gq[off + lane];
    const float o1 = ((v1 - m) * rstd * gg[c0 + 32] + gb[c0 + 32]) * gq[off + lane + 32];
    oh[off + lane]      = __float2half_rn(o0);
    oh[off + lane + 32] = __float2half_rn(o1);
}

// ---------------- launch ----------------
extern "C" void kernel_launch(void* const* d_in, const int* in_sizes, int n_in,
                              void* d_out, int out_size) {
    (void)in_sizes; (void)n_in; (void)out_size;
    const float* x     = (const float*)d_in[0];
    const float* ln1_g = (const float*)d_in[1];
    const float* ln1_b = (const float*)d_in[2];
    const float* ln2_g = (const float*)d_in[3];
    const float* ln2_b = (const float*)d_in[4];
    const float* tm_k  = (const float*)d_in[5];
    const float* tm_v  = (const float*)d_in[6];
    const float* tm_r  = (const float*)d_in[7];
    const float* tm_g  = (const float*)d_in[8];
    const float* tdec  = (const float*)d_in[9];
    const float* tfaa  = (const float*)d_in[10];
    const float* Wr    = (const float*)d_in[11];
    const float* Wk    = (const float*)d_in[12];
    const float* Wv    = (const float*)d_in[13];
    const float* Wg    = (const float*)d_in[14];
    const float* Wo    = (const float*)d_in[15];
    const float* lnx_g = (const float*)d_in[16];
    const float* lnx_b = (const float*)d_in[17];
    const float* fm_k  = (const float*)d_in[18];
    const float* fm_r  = (const float*)d_in[19];
    const float* Wkey  = (const float*)d_in[20];
    const float* Wrec  = (const float*)d_in[21];
    const float* Wval  = (const float*)d_in[22];
    float* out = (float*)d_out;

    float *XL, *Rb, *Kb, *Vb, *Gb, *ATT, *X1, *XL2, *KV;
    cudaGetSymbolAddress((void**)&XL,  g_XL);
    cudaGetSymbolAddress((void**)&Rb,  g_R);
    cudaGetSymbolAddress((void**)&Kb,  g_K);
    cudaGetSymbolAddress((void**)&Vb,  g_V);
    cudaGetSymbolAddress((void**)&Gb,  g_G);
    cudaGetSymbolAddress((void**)&ATT, g_ATT);
    cudaGetSymbolAddress((void**)&X1,  g_X1);
    cudaGetSymbolAddress((void**)&XL2, g_XL2);
    cudaGetSymbolAddress((void**)&KV,  g_KV);

    h16 *XR,*XK,*XV,*XG,*AG,*CK,*CR,*KK;
    cudaGetSymbolAddress((void**)&XR, g_XR);
    cudaGetSymbolAddress((void**)&XK, g_XK);
    cudaGetSymbolAddress((void**)&XV, g_XV);
    cudaGetSymbolAddress((void**)&XG, g_XG);
    cudaGetSymbolAddress((void**)&AG, g_AG);
    cudaGetSymbolAddress((void**)&CK, g_CK);
    cudaGetSymbolAddress((void**)&CR, g_CR);
    cudaGetSymbolAddress((void**)&KK, g_KK);

    TransArgs ta;
    ta.src[0] = Wr;   cudaGetSymbolAddress((void**)&ta.dst[0], g_WrT);
    ta.src[1] = Wk;   cudaGetSymbolAddress((void**)&ta.dst[1], g_WkT);
    ta.src[2] = Wv;   cudaGetSymbolAddress((void**)&ta.dst[2], g_WvT);
    ta.src[3] = Wg;   cudaGetSymbolAddress((void**)&ta.dst[3], g_WgT);
    ta.src[4] = Wo;   cudaGetSymbolAddress((void**)&ta.dst[4], g_WoT);
    ta.src[5] = Wrec; cudaGetSymbolAddress((void**)&ta.dst[5], g_WreT);
    ta.src[6] = Wkey; cudaGetSymbolAddress((void**)&ta.dst[6], g_WkeyT);
    ta.src[7] = Wval; cudaGetSymbolAddress((void**)&ta.dst[7], g_WvalT);
    h16* WrT  = ta.dst[0]; h16* WkT  = ta.dst[1]; h16* WvT   = ta.dst[2];
    h16* WgT  = ta.dst[3]; h16* WoT  = ta.dst[4]; h16* WreT  = ta.dst[5];
    h16* WkeyT = ta.dst[6]; h16* WvalT = ta.dst[7];

    cudaFuncSetAttribute(mmagemm<0>, cudaFuncAttributeMaxDynamicSharedMemorySize, GEMM_SMEM);
    cudaFuncSetAttribute(mmagemm<2>, cudaFuncAttributeMaxDynamicSharedMemorySize, GEMM_SMEM);
    cudaFuncSetAttribute(mmagemm<3>, cudaFuncAttributeMaxDynamicSharedMemorySize, GEMM_SMEM);
    cudaFuncSetAttribute(mmagemm<4>, cudaFuncAttributeMaxDynamicSharedMemorySize, GEMM_SMEM);
    cudaFuncSetAttribute(gemm_qkvg,  cudaFuncAttributeMaxDynamicSharedMemorySize, GEMM_SMEM);
    cudaFuncSetAttribute(wkv_kernel, cudaFuncAttributeMaxDynamicSharedMemorySize, WKV_SMEM);

    trans_all<<<14336, dim3(16, 16)>>>(ta);

    const dim3 gCC(CC / 128, BT / 128);        // (16,16)
    const dim3 gFF(FFD / 128, BT / 128);       // (64,16)
    const dim3 gQ4(CC / 128, BT / 128, 4);     // (16,16,4)

    // attention half
    ln_kernel<<<BT, 256>>>(x, ln1_g, ln1_b, XL);
    mix4_kernel<<<BT * CC / 256, 256>>>(XL, tm_k, tm_v, tm_r, tm_g, XK, XV, XR, XG);
    G4Args ga;
    ga.A[0] = XR; ga.B[0] = WrT; ga.C[0] = Rb;
    ga.A[1] = XK; ga.B[1] = WkT; ga.C[1] = Kb;
    ga.A[2] = XV; ga.B[2] = WvT; ga.C[2] = Vb;
    ga.A[3] = XG; ga.B[3] = WgT; ga.C[3] = Gb;
    gemm_qkvg<<<gQ4, 256, GEMM_SMEM>>>(ga);
    wkv_kernel<<<BB * HH * 2, 128, WKV_SMEM>>>(Rb, Kb, Vb, tdec, tfaa, ATT);
    gn_gate_kernel<<<BT * HH / 8, 256>>>(ATT, Gb, lnx_g, lnx_b, AG);
    mmagemm<3><<<gCC, 256, GEMM_SMEM>>>(AG, WoT, X1, nullptr, BT, CC, CC, x, nullptr);

    // FFN half
    ln_kernel<<<BT, 256>>>(X1, ln2_g, ln2_b, XL2);
    mix2_kernel<<<BT * CC / 256, 256>>>(XL2, fm_k, fm_r, CK, CR);
    mmagemm<2><<<gFF, 256, GEMM_SMEM>>>(CK, WkeyT, nullptr, KK, BT, FFD, CC, nullptr, nullptr);
    mmagemm<0><<<gCC, 256, GEMM_SMEM>>>(KK, WvalT, KV, nullptr, BT, CC, FFD, nullptr, nullptr);
    mmagemm<4><<<gCC, 256, GEMM_SMEM>>>(CR, WreT, out, nullptr, BT, CC, CC, X1, KV);
}

// round 16
// speedup vs baseline: 7.5412x; 1.0552x over previous
#include <cuda_runtime.h>
#include <cuda_fp16.h>
#include <math.h>
#include <stdint.h>

#define BB 2
#define TT 1024
#define CC 2048
#define HH 32
#define NNH 64
#define FFD 8192
#define BT (BB*TT)
#define EPS_ 1e-5f

typedef __half h16;

// ---------------- scratch (device globals; allocation-free) ----------------
__device__ float g_R  [BT*CC];
__device__ float g_K  [BT*CC];
__device__ float g_V  [BT*CC];
__device__ float g_ATT[BT*CC];
__device__ float g_X1 [BT*CC];
__device__ float g_KV [BT*CC];

__device__ h16 g_XR[BT*CC], g_XK[BT*CC], g_XV[BT*CC], g_XG[BT*CC];
__device__ h16 g_Gh[BT*CC];
__device__ h16 g_AG[BT*CC], g_CK[BT*CC], g_CR[BT*CC];
__device__ h16 g_KK[(size_t)BT*FFD];

__device__ h16 g_WrT [CC*CC];
__device__ h16 g_WkT [CC*CC];
__device__ h16 g_WvT [CC*CC];
__device__ h16 g_WgT [CC*CC];
__device__ h16 g_WoT [CC*CC];
__device__ h16 g_WreT[CC*CC];
__device__ h16 g_WkeyT[(size_t)FFD*CC];
__device__ h16 g_WvalT[(size_t)CC*FFD];

// ---------------- helpers ----------------
__device__ __forceinline__ uint32_t s2u(const void* p) {
    uint32_t r;
    asm("{ .reg .u64 t; cvta.to.shared.u64 t, %1; cvt.u32.u64 %0, t; }" : "=r"(r) : "l"(p));
    return r;
}
#define CP_COMMIT() asm volatile("cp.async.commit_group;" ::: "memory")
#define CP_WAIT(n)  asm volatile("cp.async.wait_group %0;" :: "n"(n) : "memory")
__device__ __forceinline__ void cp16(uint32_t s, const void* g) {
    asm volatile("cp.async.cg.shared.global [%0], [%1], 16;" :: "r"(s), "l"(g));
}
__device__ __forceinline__ void ldm4(uint32_t* r, uint32_t a) {
    asm volatile("ldmatrix.sync.aligned.m8n8.x4.shared.b16 {%0,%1,%2,%3}, [%4];"
        : "=r"(r[0]), "=r"(r[1]), "=r"(r[2]), "=r"(r[3]) : "r"(a));
}
__device__ __forceinline__ void mma16816(float* d, const uint32_t* a, const uint32_t* b) {
    asm volatile(
        "mma.sync.aligned.m16n8k16.row.col.f32.f16.f16.f32 "
        "{%0,%1,%2,%3}, {%4,%5,%6,%7}, {%8,%9}, {%0,%1,%2,%3};"
        : "+f"(d[0]), "+f"(d[1]), "+f"(d[2]), "+f"(d[3])
        : "r"(a[0]), "r"(a[1]), "r"(a[2]), "r"(a[3]), "r"(b[0]), "r"(b[1]));
}
// 128B-row swizzle
__device__ __forceinline__ uint32_t SWZ(uint32_t o) { return o ^ ((o >> 3) & 0x70); }

// ---------------- prep kernel: ln1+mix4 rows || weight transposes ----------
// blocks [0, 4096): ln1+mix4 for row bid.
// blocks [4096, 4096+14336): transpose tiles (jobs as before).
struct PrepArgs {
    const float* wsrc[8];
    h16* wdst[8];
    const float* x;
    const float* g;
    const float* b;
    const float* mk; const float* mv; const float* mr; const float* mg;
    h16* xk; h16* xv; h16* xr; h16* xg;
};

__device__ __forceinline__ void lnmix_stats(float s, float s2, float sp, float sp2,
                                            float4* red, float4& tot) {
    const int tid = threadIdx.x;
#pragma unroll
    for (int o = 16; o; o >>= 1) {
        s   += __shfl_xor_sync(0xffffffffu, s,   o);
        s2  += __shfl_xor_sync(0xffffffffu, s2,  o);
        sp  += __shfl_xor_sync(0xffffffffu, sp,  o);
        sp2 += __shfl_xor_sync(0xffffffffu, sp2, o);
    }
    if ((tid & 31) == 0) { red[tid >> 5] = make_float4(s, s2, sp, sp2); }
    __syncthreads();
    if (tid == 0) {
        float4 t = red[0];
#pragma unroll
        for (int i = 1; i < 8; i++) {
            t.x += red[i].x; t.y += red[i].y; t.z += red[i].z; t.w += red[i].w;
        }
        red[0] = t;
    }
    __syncthreads();
    tot = red[0];
}

__global__ __launch_bounds__(256)
void prep_kernel(PrepArgs a) {
    __shared__ float ts[64][65];   // transpose staging (union use)
    const int bid = blockIdx.x;
    const int tid = threadIdx.x;

    if (bid < BT) {
        // ---- ln1 + mix4 for row bid ----
        __shared__ float4 red[8];
        const int row = bid;
        const int t = row & (TT - 1);
        const float4* x4 = (const float4*)(a.x + (size_t)row * CC);
        float4 c0 = x4[tid], c1 = x4[tid + 256];
        float4 p0 = make_float4(0.f, 0.f, 0.f, 0.f), p1 = p0;
        if (t > 0) { p0 = x4[tid - 512]; p1 = x4[tid - 256]; }
        float s   = c0.x + c0.y + c0.z + c0.w + c1.x + c1.y + c1.z + c1.w;
        float s2  = c0.x*c0.x + c0.y*c0.y + c0.z*c0.z + c0.w*c0.w
                  + c1.x*c1.x + c1.y*c1.y + c1.z*c1.z + c1.w*c1.w;
        float sp  = p0.x + p0.y + p0.z + p0.w + p1.x + p1.y + p1.z + p1.w;
        float sp2 = p0.x*p0.x + p0.y*p0.y + p0.z*p0.z + p0.w*p0.w
                  + p1.x*p1.x + p1.y*p1.y + p1.z*p1.z + p1.w*p1.w;
        float4 T;
        lnmix_stats(s, s2, sp, sp2, red, T);
        const float mc  = T.x * (1.f / CC);
        const float rc  = rsqrtf(T.y * (1.f / CC) - mc * mc + EPS_);
        const float mp  = T.z * (1.f / CC);
        const float rp  = rsqrtf(T.w * (1.f / CC) - mp * mp + EPS_);
        const size_t ro = (size_t)row * CC;
#pragma unroll
        for (int half = 0; half < 2; half++) {
            const int c4 = tid + half * 256;       // float4 index
            const int c = c4 * 4;
            const float4 cv = half ? c1 : c0;
            const float4 pv = half ? p1 : p0;
            const float4 gg = ((const float4*)a.g)[c4];
            const float4 bb = ((const float4*)a.b)[c4];
            float xl[4], xx[4];
            xl[0] = (cv.x - mc) * rc * gg.x + bb.x;
            xl[1] = (cv.y - mc) * rc * gg.y + bb.y;
            xl[2] = (cv.z - mc) * rc * gg.z + bb.z;
            xl[3] = (cv.w - mc) * rc * gg.w + bb.w;
            if (t > 0) {
                xx[0] = (pv.x - mp) * rp * gg.x + bb.x;
                xx[1] = (pv.y - mp) * rp * gg.y + bb.y;
                xx[2] = (pv.z - mp) * rp * gg.z + bb.z;
                xx[3] = (pv.w - mp) * rp * gg.w + bb.w;
            } else { xx[0] = xx[1] = xx[2] = xx[3] = 0.f; }
            const float4 k4 = ((const float4*)a.mk)[c4];
            const float4 v4 = ((const float4*)a.mv)[c4];
            const float4 r4 = ((const float4*)a.mr)[c4];
            const float4 g4 = ((const float4*)a.mg)[c4];
            const float* km = &k4.x; const float* vm = &v4.x;
            const float* rm = &r4.x; const float* gm = &g4.x;
            h16 ok[4], ov[4], orr[4], og[4];
#pragma unroll
            for (int q = 0; q < 4; q++) {
                const float d = xl[q] - xx[q];
                ok[q]  = __float2half_rn(xx[q] + km[q] * d);
                ov[q]  = __float2half_rn(xx[q] + vm[q] * d);
                orr[q] = __float2half_rn(xx[q] + rm[q] * d);
                og[q]  = __float2half_rn(xx[q] + gm[q] * d);
            }
            *(uint2*)&a.xk[ro + c] = *(uint2*)ok;
            *(uint2*)&a.xv[ro + c] = *(uint2*)ov;
            *(uint2*)&a.xr[ro + c] = *(uint2*)orr;
            *(uint2*)&a.xg[ro + c] = *(uint2*)og;
        }
        return;
    }

    // ---- transpose tiles ----
    const int tb = bid - BT;
    int job, tile;
    if (tb < 6144)       { job = tb >> 10; tile = tb & 1023; }
    else if (tb < 10240) { job = 6; tile = tb - 6144; }
    else                 { job = 7; tile = tb - 10240; }
    const int K = (job == 7) ? FFD : CC;
    const int N = (job == 6) ? FFD : CC;
    const int tn = N >> 6;
    const int k0 = (tile / tn) << 6;
    const int n0 = (tile % tn) << 6;
    const int tx = tid & 15, ty = tid >> 4;
    const float* W = a.wsrc[job];
#pragma unroll
    for (int i = 0; i < 4; i++) {
        const float4 q = *(const float4*)&W[(size_t)(k0 + ty + i * 16) * N + n0 + tx * 4];
        ts[ty + i * 16][tx * 4 + 0] = q.x;
        ts[ty + i * 16][tx * 4 + 1] = q.y;
        ts[ty + i * 16][tx * 4 + 2] = q.z;
        ts[ty + i * 16][tx * 4 + 3] = q.w;
    }
    __syncthreads();
    h16* T = a.wdst[job];
#pragma unroll
    for (int i = 0; i < 4; i++) {
        const int n = ty + i * 16;
        const __half2 h01 = __floats2half2_rn(ts[tx * 4 + 0][n], ts[tx * 4 + 1][n]);
        const __half2 h23 = __floats2half2_rn(ts[tx * 4 + 2][n], ts[tx * 4 + 3][n]);
        uint2 pk;
        pk.x = *(const uint32_t*)&h01;
        pk.y = *(const uint32_t*)&h23;
        *(uint2*)&T[(size_t)(n0 + n) * K + k0 + tx * 4] = pk;
    }
}

// ---------------- ln2 + mix2 fused ----------------
__global__ __launch_bounds__(256)
void ln_mix2_kernel(const float* __restrict__ x, const float* __restrict__ g,
                    const float* __restrict__ b, const float* __restrict__ mk,
                    const float* __restrict__ mr, h16* ck, h16* cr) {
    __shared__ float4 red[8];
    const int row = blockIdx.x;
    const int tid = threadIdx.x;
    const int t = row & (TT - 1);
    const float4* x4 = (const float4*)(x + (size_t)row * CC);
    float4 c0 = x4[tid], c1 = x4[tid + 256];
    float4 p0 = make_float4(0.f, 0.f, 0.f, 0.f), p1 = p0;
    if (t > 0) { p0 = x4[tid - 512]; p1 = x4[tid - 256]; }
    float s   = c0.x + c0.y + c0.z + c0.w + c1.x + c1.y + c1.z + c1.w;
    float s2  = c0.x*c0.x + c0.y*c0.y + c0.z*c0.z + c0.w*c0.w
              + c1.x*c1.x + c1.y*c1.y + c1.z*c1.z + c1.w*c1.w;
    float sp  = p0.x + p0.y + p0.z + p0.w + p1.x + p1.y + p1.z + p1.w;
    float sp2 = p0.x*p0.x + p0.y*p0.y + p0.z*p0.z + p0.w*p0.w
              + p1.x*p1.x + p1.y*p1.y + p1.z*p1.z + p1.w*p1.w;
    float4 T;
    lnmix_stats(s, s2, sp, sp2, red, T);
    const float mc = T.x * (1.f / CC);
    const float rc = rsqrtf(T.y * (1.f / CC) - mc * mc + EPS_);
    const float mp = T.z * (1.f / CC);
    const float rp = rsqrtf(T.w * (1.f / CC) - mp * mp + EPS_);
    const size_t ro = (size_t)row * CC;
#pragma unroll
    for (int half = 0; half < 2; half++) {
        const int c4 = tid + half * 256;
        const int c = c4 * 4;
        const float4 cv = half ? c1 : c0;
        const float4 pv = half ? p1 : p0;
        const float4 gg = ((const float4*)g)[c4];
        const float4 bb = ((const float4*)b)[c4];
        float xl[4], xx[4];
        xl[0] = (cv.x - mc) * rc * gg.x + bb.x;
        xl[1] = (cv.y - mc) * rc * gg.y + bb.y;
        xl[2] = (cv.z - mc) * rc * gg.z + bb.z;
        xl[3] = (cv.w - mc) * rc * gg.w + bb.w;
        if (t > 0) {
            xx[0] = (pv.x - mp) * rp * gg.x + bb.x;
            xx[1] = (pv.y - mp) * rp * gg.y + bb.y;
            xx[2] = (pv.z - mp) * rp * gg.z + bb.z;
            xx[3] = (pv.w - mp) * rp * gg.w + bb.w;
        } else { xx[0] = xx[1] = xx[2] = xx[3] = 0.f; }
        const float4 k4 = ((const float4*)mk)[c4];
        const float4 r4 = ((const float4*)mr)[c4];
        const float* km = &k4.x; const float* rm = &r4.x;
        h16 ok[4], orr[4];
#pragma unroll
        for (int q = 0; q < 4; q++) {
            const float d = xl[q] - xx[q];
            ok[q]  = __float2half_rn(xx[q] + km[q] * d);
            orr[q] = __float2half_rn(xx[q] + rm[q] * d);
        }
        *(uint2*)&ck[ro + c] = *(uint2*)ok;
        *(uint2*)&cr[ro + c] = *(uint2*)orr;
    }
}

// ---------------- mma.sync GEMM core: D = A @ B^T, fp16, BK=64 -------------
// EPI: 0 fp32 | 1 silu->fp16 | 2 relu^2->fp16 | 3 aux1+acc | 4 aux1+sigmoid(acc)*aux2
#define OFF_A 0
#define OFF_B 16384
#define STG   32768
#define GEMM_SMEM (3 * STG)

template <int EPI>
__device__ __forceinline__ void gemm_body(
        const h16* __restrict__ Ah, const h16* __restrict__ Bh,
        float* __restrict__ C, h16* __restrict__ Ch,
        int M, int N, int K, int row0, int col0,
        const float* __restrict__ aux1, const float* __restrict__ aux2,
        char* smem) {
    const uint32_t sb = s2u(smem);
    const int tid = threadIdx.x;
    const int NK = K / 64;

    const int sr = tid >> 3, su = tid & 7;
    uint32_t sdst[4];
#pragma unroll
    for (int p = 0; p < 4; p++) sdst[p] = SWZ((uint32_t)((sr + 32 * p) * 128 + su * 16));
    const h16* pA = Ah + (size_t)(row0 + sr) * K + su * 8;
    const h16* pB = Bh + (size_t)(col0 + sr) * K + su * 8;
    const size_t rs = (size_t)32 * K;

    auto load_stage = [&](int kb, int st) {
        const uint32_t s = sb + (uint32_t)st * STG;
        const size_t ko = (size_t)kb * 64;
#pragma unroll
        for (int p = 0; p < 4; p++) cp16(s + OFF_A + sdst[p], pA + p * rs + ko);
#pragma unroll
        for (int p = 0; p < 4; p++) cp16(s + OFF_B + sdst[p], pB + p * rs + ko);
        CP_COMMIT();
    };

    const int wid = tid >> 5, lane = tid & 31;
    const int wm = wid & 1, wn = wid >> 1;
    const int wmb = wm * 64, wnb = wn * 32;
    const uint32_t a_row  = (uint32_t)(wmb + (lane & 15));
    const uint32_t a_csel = (uint32_t)((lane >> 4) << 4);
    const uint32_t b_row  = (uint32_t)(wnb + ((lane >> 4) << 3) + (lane & 7));
    const uint32_t b_csel = (uint32_t)(((lane >> 3) & 1) << 4);

    float acc[4][4][4];
#pragma unroll
    for (int i = 0; i < 4; i++)
#pragma unroll
        for (int j = 0; j < 4; j++)
#pragma unroll
            for (int q = 0; q < 4; q++) acc[i][j][q] = 0.f;

    load_stage(0, 0);
    if (NK > 1) load_stage(1, 1);

#pragma unroll 1
    for (int kb = 0; kb < NK; kb++) {
        if (kb + 1 < NK) { CP_WAIT(1); } else { CP_WAIT(0); }
        __syncthreads();

        const uint32_t us = sb + (uint32_t)(kb % 3) * STG;
#pragma unroll
        for (int ks = 0; ks < 4; ks++) {
            uint32_t a[4][4], bfr[2][4];
#pragma unroll
            for (int mt = 0; mt < 4; mt++) {
                const uint32_t off = (a_row + mt * 16) * 128 + (uint32_t)(ks * 32) + a_csel;
                ldm4(a[mt], us + OFF_A + SWZ(off));
            }
#pragma unroll
            for (int bp = 0; bp < 2; bp++) {
                const uint32_t off = (b_row + bp * 16) * 128 + (uint32_t)(ks * 32) + b_csel;
                ldm4(bfr[bp], us + OFF_B + SWZ(off));
            }
#pragma unroll
            for (int mt = 0; mt < 4; mt++)
#pragma unroll
                for (int nt = 0; nt < 4; nt++)
                    mma16816(acc[mt][nt], a[mt], &bfr[nt >> 1][(nt & 1) * 2]);
        }
        if (kb + 2 < NK) load_stage(kb + 2, (kb + 2) % 3);
    }

    const int mrow = row0 + wmb + (lane >> 2);
    const int ncol = col0 + wnb + (lane & 3) * 2;
#pragma unroll
    for (int mt = 0; mt < 4; mt++) {
#pragma unroll
        for (int half = 0; half < 2; half++) {
            const size_t m = (size_t)(mrow + mt * 16 + half * 8);
#pragma unroll
            for (int nt = 0; nt < 4; nt++) {
                float vx = acc[mt][nt][half * 2 + 0];
                float vy = acc[mt][nt][half * 2 + 1];
                const size_t idx = m * N + (ncol + nt * 8);
                if (EPI == 1 || EPI == 2) {
                    if (EPI == 1) {
                        vx /= (1.f + expf(-vx)); vy /= (1.f + expf(-vy));
                    } else {
                        vx = fmaxf(vx, 0.f); vx *= vx;
                        vy = fmaxf(vy, 0.f); vy *= vy;
                    }
                    __half2 hp;
                    hp.x = __float2half_rn(vx); hp.y = __float2half_rn(vy);
                    *(__half2*)&Ch[idx] = hp;
                } else {
                    if (EPI == 3) {
                        const float2 a2 = *(const float2*)&aux1[idx];
                        vx += a2.x; vy += a2.y;
                    } else if (EPI == 4) {
                        const float2 a2 = *(const float2*)&aux1[idx];
                        const float2 b2 = *(const float2*)&aux2[idx];
                        vx = a2.x + b2.x / (1.f + expf(-vx));
                        vy = a2.y + b2.y / (1.f + expf(-vy));
                    }
                    float2 p; p.x = vx; p.y = vy;
                    *(float2*)&C[idx] = p;
                }
            }
        }
    }
}

template <int EPI>
__global__ __launch_bounds__(256, 2)
void mmagemm(const h16* __restrict__ Ah, const h16* __restrict__ Bh,
             float* __restrict__ C, h16* __restrict__ Ch,
             int M, int N, int K,
             const float* __restrict__ aux1, const float* __restrict__ aux2) {
    extern __shared__ __align__(1024) char smem[];
    gemm_body<EPI>(Ah, Bh, C, Ch, M, N, K,
                   blockIdx.y * 128, blockIdx.x * 128, aux1, aux2, smem);
}

// Batched QKVG: grid (16,16,4); job 3 (G) = silu -> fp16, others fp32.
struct G4Args {
    const h16* A[4];
    const h16* B[4];
    float* C[3];
    h16* Ch3;
};
__global__ __launch_bounds__(256, 2)
void gemm_qkvg(G4Args ga) {
    extern __shared__ __align__(1024) char smem[];
    const int job = blockIdx.z;
    if (job == 3)
        gemm_body<1>(ga.A[3], ga.B[3], nullptr, ga.Ch3, BT, CC, CC,
                     blockIdx.y * 128, blockIdx.x * 128, nullptr, nullptr, smem);
    else
        gemm_body<0>(ga.A[job], ga.B[job], ga.C[job], nullptr, BT, CC, CC,
                     blockIdx.y * 128, blockIdx.x * 128, nullptr, nullptr, smem);
}

// ---------------- WKV5 recurrence, chunked cp.async staging ----------------
#define TC 32
#define WKV_SMEM (10240 * 4)

__global__ __launch_bounds__(128)
void wkv_kernel(const float* __restrict__ r, const float* __restrict__ k,
                const float* __restrict__ v, const float* __restrict__ w,
                const float* __restrict__ u, float* __restrict__ att) {
    extern __shared__ __align__(16) float sm[];
    float* const srm = sm;
    float* const skm = sm + 4096;
    float* const svm = sm + 8192;
    const uint32_t sr_u = s2u(srm), sk_u = s2u(skm), sv_u = s2u(svm);

    const int blk = blockIdx.x;
    const int jc = blk & 1;
    const int bh = blk >> 1;
    const int b = bh / HH, h = bh % HH;
    const int tid = threadIdx.x;
    const int jl = tid >> 2;
    const int j = jc * 32 + jl;
    const int p = tid & 3;

    const size_t base = ((size_t)b * TT * HH + h) * NNH;

    const int srow = tid >> 2;
    const int scb  = (tid & 3) * 16;
    const uint32_t s_dst = (uint32_t)((srow * 64 + scb) * 4);
    const int vrow0 = tid >> 3, vunit0 = tid & 7;
    const int vrow1 = (tid + 128) >> 3, vunit1 = tid & 7;
    const uint32_t v_dst0 = (uint32_t)((vrow0 * 32 + vunit0 * 4) * 4);
    const uint32_t v_dst1 = (uint32_t)((vrow1 * 32 + vunit1 * 4) * 4);

    auto stage = [&](int ch, int buf) {
        const int t0 = ch * TC;
        const uint32_t bo = (uint32_t)(buf * 2048 * 4);
        const uint32_t bv = (uint32_t)(buf * 1024 * 4);
        const float* rg = r + base + (size_t)(t0 + srow) * 2048 + scb;
        const float* kg = k + base + (size_t)(t0 + srow) * 2048 + scb;
#pragma unroll
        for (int q = 0; q < 4; q++) {
            cp16(sr_u + bo + s_dst + q * 16, rg + q * 4);
            cp16(sk_u + bo + s_dst + q * 16, kg + q * 4);
        }
        cp16(sv_u + bv + v_dst0, v + base + (size_t)(t0 + vrow0) * 2048 + jc * 32 + vunit0 * 4);
        cp16(sv_u + bv + v_dst1, v + base + (size_t)(t0 + vrow1) * 2048 + jc * 32 + vunit1 * 4);
        CP_COMMIT();
    };

    float S[16], dec[16], uu[16];
#pragma unroll
    for (int ii = 0; ii < 16; ii++) S[ii] = 0.f;
#pragma unroll
    for (int ii = 0; ii < 16; ii++) {
        const float wv = w[h * NNH + p * 16 + ii];
        dec[ii] = expf(-expf(wv));
        uu[ii]  = u[h * NNH + p * 16 + ii];
    }

    stage(0, 0);

    const int NC = TT / TC;
#pragma unroll 1
    for (int ch = 0; ch < NC; ch++) {
        CP_WAIT(0);
        __syncthreads();
        if (ch + 1 < NC) stage(ch + 1, (ch + 1) & 1);
        const int buf = ch & 1;
        const float* rp = srm + buf * 2048 + p * 16;
        const float* kp = skm + buf * 2048 + p * 16;
        const float* vp = svm + buf * 1024 + jl;
        const int t0 = ch * TC;
#pragma unroll 2
        for (int tt = 0; tt < TC; tt++) {
            float rr[16], kk[16];
            *(float4*)&rr[0]  = *(const float4*)(rp + tt * 64 + 0);
            *(float4*)&rr[4]  = *(const float4*)(rp + tt * 64 + 4);
            *(float4*)&rr[8]  = *(const float4*)(rp + tt * 64 + 8);
            *(float4*)&rr[12] = *(const float4*)(rp + tt * 64 + 12);
            *(float4*)&kk[0]  = *(const float4*)(kp + tt * 64 + 0);
            *(float4*)&kk[4]  = *(const float4*)(kp + tt * 64 + 4);
            *(float4*)&kk[8]  = *(const float4*)(kp + tt * 64 + 8);
            *(float4*)&kk[12] = *(const float4*)(kp + tt * 64 + 12);
            const float vj = vp[tt * 32];
            float yp = 0.f;
#pragma unroll
            for (int ii = 0; ii < 16; ii++) {
                const float kv = kk[ii] * vj;
                yp = fmaf(rr[ii], fmaf(uu[ii], kv, S[ii]), yp);
                S[ii] = fmaf(dec[ii], S[ii], kv);
            }
            float y = yp + __shfl_xor_sync(0xffffffffu, yp, 1);
            y += __shfl_xor_sync(0xffffffffu, y, 2);
            if (p == 0) att[base + (size_t)(t0 + tt) * 2048 + j] = y;
        }
    }
}

// ---------------- GroupNorm(att/DIV)*g+b, * gate(fp16), fp16 out ----------
__global__ void gn_gate_kernel(const float* __restrict__ att, const h16* __restrict__ gq,
                               const float* __restrict__ gg, const float* __restrict__ gb,
                               h16* __restrict__ oh) {
    const int gid  = blockIdx.x * 8 + (threadIdx.x >> 5);
    const int lane = threadIdx.x & 31;
    const int h = gid & (HH - 1);
    const size_t off = (size_t)gid * NNH;
    const float inv_div = 1.f / 8.f;
    const float v0 = att[off + lane]      * inv_div;
    const float v1 = att[off + lane + 32] * inv_div;
    float s = v0 + v1, s2 = v0 * v0 + v1 * v1;
#pragma unroll
    for (int o = 16; o; o >>= 1) {
        s  += __shfl_xor_sync(0xffffffffu, s,  o);
        s2 += __shfl_xor_sync(0xffffffffu, s2, o);
    }
    const float m = s * (1.f / NNH);
    const float var = s2 * (1.f / NNH) - m * m;
    const float rstd = rsqrtf(var + EPS_);
    const int c0 = h * NNH + lane;
    const float g0 = __half2float(gq[off + lane]);
    const float g1 = __half2float(gq[off + lane + 32]);
    const float o0 = ((v0 - m) * rstd * gg[c0]      + gb[c0])      * g0;
    const float o1 = ((v1 - m) * rstd * gg[c0 + 32] + gb[c0 + 32]) * g1;
    oh[off + lane]      = __float2half_rn(o0);
    oh[off + lane + 32] = __float2half_rn(o1);
}

// ---------------- launch ----------------
extern "C" void kernel_launch(void* const* d_in, const int* in_sizes, int n_in,
                              void* d_out, int out_size) {
    (void)in_sizes; (void)n_in; (void)out_size;
    const float* x     = (const float*)d_in[0];
    const float* ln1_g = (const float*)d_in[1];
    const float* ln1_b = (const float*)d_in[2];
    const float* ln2_g = (const float*)d_in[3];
    const float* ln2_b = (const float*)d_in[4];
    const float* tm_k  = (const float*)d_in[5];
    const float* tm_v  = (const float*)d_in[6];
    const float* tm_r  = (const float*)d_in[7];
    const float* tm_g  = (const float*)d_in[8];
    const float* tdec  = (const float*)d_in[9];
    const float* tfaa  = (const float*)d_in[10];
    const float* Wr    = (const float*)d_in[11];
    const float* Wk    = (const float*)d_in[12];
    const float* Wv    = (const float*)d_in[13];
    const float* Wg    = (const float*)d_in[14];
    const float* Wo    = (const float*)d_in[15];
    const float* lnx_g = (const float*)d_in[16];
    const float* lnx_b = (const float*)d_in[17];
    const float* fm_k  = (const float*)d_in[18];
    const float* fm_r  = (const float*)d_in[19];
    const float* Wkey  = (const float*)d_in[20];
    const float* Wrec  = (const float*)d_in[21];
    const float* Wval  = (const float*)d_in[22];
    float* out = (float*)d_out;

    float *Rb, *Kb, *Vb, *ATT, *X1, *KV;
    cudaGetSymbolAddress((void**)&Rb,  g_R);
    cudaGetSymbolAddress((void**)&Kb,  g_K);
    cudaGetSymbolAddress((void**)&Vb,  g_V);
    cudaGetSymbolAddress((void**)&ATT, g_ATT);
    cudaGetSymbolAddress((void**)&X1,  g_X1);
    cudaGetSymbolAddress((void**)&KV,  g_KV);

    h16 *XR,*XK,*XV,*XG,*Gh,*AG,*CK,*CR,*KK;
    cudaGetSymbolAddress((void**)&XR, g_XR);
    cudaGetSymbolAddress((void**)&XK, g_XK);
    cudaGetSymbolAddress((void**)&XV, g_XV);
    cudaGetSymbolAddress((void**)&XG, g_XG);
    cudaGetSymbolAddress((void**)&Gh, g_Gh);
    cudaGetSymbolAddress((void**)&AG, g_AG);
    cudaGetSymbolAddress((void**)&CK, g_CK);
    cudaGetSymbolAddress((void**)&CR, g_CR);
    cudaGetSymbolAddress((void**)&KK, g_KK);

    PrepArgs pa;
    pa.wsrc[0] = Wr;   cudaGetSymbolAddress((void**)&pa.wdst[0], g_WrT);
    pa.wsrc[1] = Wk;   cudaGetSymbolAddress((void**)&pa.wdst[1], g_WkT);
    pa.wsrc[2] = Wv;   cudaGetSymbolAddress((void**)&pa.wdst[2], g_WvT);
    pa.wsrc[3] = Wg;   cudaGetSymbolAddress((void**)&pa.wdst[3], g_WgT);
    pa.wsrc[4] = Wo;   cudaGetSymbolAddress((void**)&pa.wdst[4], g_WoT);
    pa.wsrc[5] = Wrec; cudaGetSymbolAddress((void**)&pa.wdst[5], g_WreT);
    pa.wsrc[6] = Wkey; cudaGetSymbolAddress((void**)&pa.wdst[6], g_WkeyT);
    pa.wsrc[7] = Wval; cudaGetSymbolAddress((void**)&pa.wdst[7], g_WvalT);
    pa.x = x; pa.g = ln1_g; pa.b = ln1_b;
    pa.mk = tm_k; pa.mv = tm_v; pa.mr = tm_r; pa.mg = tm_g;
    pa.xk = XK; pa.xv = XV; pa.xr = XR; pa.xg = XG;
    h16* WrT   = pa.wdst[0]; h16* WkT   = pa.wdst[1]; h16* WvT  = pa.wdst[2];
    h16* WgT   = pa.wdst[3]; h16* WoT   = pa.wdst[4]; h16* WreT = pa.wdst[5];
    h16* WkeyT = pa.wdst[6]; h16* WvalT = pa.wdst[7];

    cudaFuncSetAttribute(mmagemm<0>, cudaFuncAttributeMaxDynamicSharedMemorySize, GEMM_SMEM);
    cudaFuncSetAttribute(mmagemm<2>, cudaFuncAttributeMaxDynamicSharedMemorySize, GEMM_SMEM);
    cudaFuncSetAttribute(mmagemm<3>, cudaFuncAttributeMaxDynamicSharedMemorySize, GEMM_SMEM);
    cudaFuncSetAttribute(mmagemm<4>, cudaFuncAttributeMaxDynamicSharedMemorySize, GEMM_SMEM);
    cudaFuncSetAttribute(gemm_qkvg,  cudaFuncAttributeMaxDynamicSharedMemorySize, GEMM_SMEM);
    cudaFuncSetAttribute(wkv_kernel, cudaFuncAttributeMaxDynamicSharedMemorySize, WKV_SMEM);

    const dim3 gCC(CC / 128, BT / 128);        // (16,16)
    const dim3 gFF(FFD / 128, BT / 128);       // (64,16)
    const dim3 gQ4(CC / 128, BT / 128, 4);     // (16,16,4)

    // prep: ln1+mix4 rows (first 4096 blocks) || weight transposes (14336)
    prep_kernel<<<BT + 14336, 256>>>(pa);

    // attention half
    G4Args ga;
    ga.A[0] = XR; ga.B[0] = WrT; ga.C[0] = Rb;
    ga.A[1] = XK; ga.B[1] = WkT; ga.C[1] = Kb;
    ga.A[2] = XV; ga.B[2] = WvT; ga.C[2] = Vb;
    ga.A[3] = XG; ga.B[3] = WgT; ga.Ch3 = Gh;
    gemm_qkvg<<<gQ4, 256, GEMM_SMEM>>>(ga);
    wkv_kernel<<<BB * HH * 2, 128, WKV_SMEM>>>(Rb, Kb, Vb, tdec, tfaa, ATT);
    gn_gate_kernel<<<BT * HH / 8, 256>>>(ATT, Gh, lnx_g, lnx_b, AG);
    mmagemm<3><<<gCC, 256, GEMM_SMEM>>>(AG, WoT, X1, nullptr, BT, CC, CC, x, nullptr);

    // FFN half
    ln_mix2_kernel<<<BT, 256>>>(X1, ln2_g, ln2_b, fm_k, fm_r, CK, CR);
    mmagemm<2><<<gFF, 256, GEMM_SMEM>>>(CK, WkeyT, nullptr, KK, BT, FFD, CC, nullptr, nullptr);
    mmagemm<0><<<gCC, 256, GEMM_SMEM>>>(KK, WvalT, KV, nullptr, BT, CC, FFD, nullptr, nullptr);
    mmagemm<4><<<gCC, 256, GEMM_SMEM>>>(CR, WreT, out, nullptr, BT, CC, CC, X1, KV);
}

// round 17
// speedup vs baseline: 7.5503x; 1.0012x over previous
#include <cuda_runtime.h>
#include <cuda_fp16.h>
#include <math.h>
#include <stdint.h>

#define BB 2
#define TT 1024
#define CC 2048
#define HH 32
#define NNH 64
#define FFD 8192
#define BT (BB*TT)
#define EPS_ 1e-5f

typedef __half h16;

// ---------------- scratch (device globals; allocation-free) ----------------
__device__ float g_R  [BT*CC];
__device__ float g_K  [BT*CC];
__device__ float g_V  [BT*CC];
__device__ float g_ATT[BT*CC];
__device__ float g_X1 [BT*CC];
__device__ float g_KV [BT*CC];

__device__ h16 g_XR[BT*CC], g_XK[BT*CC], g_XV[BT*CC], g_XG[BT*CC];
__device__ h16 g_Gh[BT*CC];
__device__ h16 g_AG[BT*CC], g_CK[BT*CC], g_CR[BT*CC];
__device__ h16 g_KK[(size_t)BT*FFD];

__device__ h16 g_WrT [CC*CC];
__device__ h16 g_WkT [CC*CC];
__device__ h16 g_WvT [CC*CC];
__device__ h16 g_WgT [CC*CC];
__device__ h16 g_WoT [CC*CC];
__device__ h16 g_WreT[CC*CC];
__device__ h16 g_WkeyT[(size_t)FFD*CC];
__device__ h16 g_WvalT[(size_t)CC*FFD];

// ---------------- helpers ----------------
__device__ __forceinline__ uint32_t s2u(const void* p) {
    uint32_t r;
    asm("{ .reg .u64 t; cvta.to.shared.u64 t, %1; cvt.u32.u64 %0, t; }" : "=r"(r) : "l"(p));
    return r;
}
#define CP_COMMIT() asm volatile("cp.async.commit_group;" ::: "memory")
#define CP_WAIT(n)  asm volatile("cp.async.wait_group %0;" :: "n"(n) : "memory")
__device__ __forceinline__ void cp16(uint32_t s, const void* g) {
    asm volatile("cp.async.cg.shared.global [%0], [%1], 16;" :: "r"(s), "l"(g));
}
__device__ __forceinline__ void ldm4(uint32_t* r, uint32_t a) {
    asm volatile("ldmatrix.sync.aligned.m8n8.x4.shared.b16 {%0,%1,%2,%3}, [%4];"
        : "=r"(r[0]), "=r"(r[1]), "=r"(r[2]), "=r"(r[3]) : "r"(a));
}
__device__ __forceinline__ void mma16816(float* d, const uint32_t* a, const uint32_t* b) {
    asm volatile(
        "mma.sync.aligned.m16n8k16.row.col.f32.f16.f16.f32 "
        "{%0,%1,%2,%3}, {%4,%5,%6,%7}, {%8,%9}, {%0,%1,%2,%3};"
        : "+f"(d[0]), "+f"(d[1]), "+f"(d[2]), "+f"(d[3])
        : "r"(a[0]), "r"(a[1]), "r"(a[2]), "r"(a[3]), "r"(b[0]), "r"(b[1]));
}
// 128B-row swizzle
__device__ __forceinline__ uint32_t SWZ(uint32_t o) { return o ^ ((o >> 3) & 0x70); }

// ---------------- prep kernel: ln1+mix4 rows || weight transposes ----------
// blocks [0, 4096): ln1+mix4 for row bid.
// blocks [4096, 4096+14336): transpose tiles (jobs as before).
struct PrepArgs {
    const float* wsrc[8];
    h16* wdst[8];
    const float* x;
    const float* g;
    const float* b;
    const float* mk; const float* mv; const float* mr; const float* mg;
    h16* xk; h16* xv; h16* xr; h16* xg;
};

__device__ __forceinline__ void lnmix_stats(float s, float s2, float sp, float sp2,
                                            float4* red, float4& tot) {
    const int tid = threadIdx.x;
#pragma unroll
    for (int o = 16; o; o >>= 1) {
        s   += __shfl_xor_sync(0xffffffffu, s,   o);
        s2  += __shfl_xor_sync(0xffffffffu, s2,  o);
        sp  += __shfl_xor_sync(0xffffffffu, sp,  o);
        sp2 += __shfl_xor_sync(0xffffffffu, sp2, o);
    }
    if ((tid & 31) == 0) { red[tid >> 5] = make_float4(s, s2, sp, sp2); }
    __syncthreads();
    if (tid == 0) {
        float4 t = red[0];
#pragma unroll
        for (int i = 1; i < 8; i++) {
            t.x += red[i].x; t.y += red[i].y; t.z += red[i].z; t.w += red[i].w;
        }
        red[0] = t;
    }
    __syncthreads();
    tot = red[0];
}

__global__ __launch_bounds__(256)
void prep_kernel(PrepArgs a) {
    __shared__ float ts[64][65];   // transpose staging (union use)
    const int bid = blockIdx.x;
    const int tid = threadIdx.x;

    if (bid < BT) {
        // ---- ln1 + mix4 for row bid ----
        __shared__ float4 red[8];
        const int row = bid;
        const int t = row & (TT - 1);
        const float4* x4 = (const float4*)(a.x + (size_t)row * CC);
        float4 c0 = x4[tid], c1 = x4[tid + 256];
        float4 p0 = make_float4(0.f, 0.f, 0.f, 0.f), p1 = p0;
        if (t > 0) { p0 = x4[tid - 512]; p1 = x4[tid - 256]; }
        float s   = c0.x + c0.y + c0.z + c0.w + c1.x + c1.y + c1.z + c1.w;
        float s2  = c0.x*c0.x + c0.y*c0.y + c0.z*c0.z + c0.w*c0.w
                  + c1.x*c1.x + c1.y*c1.y + c1.z*c1.z + c1.w*c1.w;
        float sp  = p0.x + p0.y + p0.z + p0.w + p1.x + p1.y + p1.z + p1.w;
        float sp2 = p0.x*p0.x + p0.y*p0.y + p0.z*p0.z + p0.w*p0.w
                  + p1.x*p1.x + p1.y*p1.y + p1.z*p1.z + p1.w*p1.w;
        float4 T;
        lnmix_stats(s, s2, sp, sp2, red, T);
        const float mc  = T.x * (1.f / CC);
        const float rc  = rsqrtf(T.y * (1.f / CC) - mc * mc + EPS_);
        const float mp  = T.z * (1.f / CC);
        const float rp  = rsqrtf(T.w * (1.f / CC) - mp * mp + EPS_);
        const size_t ro = (size_t)row * CC;
#pragma unroll
        for (int half = 0; half < 2; half++) {
            const int c4 = tid + half * 256;       // float4 index
            const int c = c4 * 4;
            const float4 cv = half ? c1 : c0;
            const float4 pv = half ? p1 : p0;
            const float4 gg = ((const float4*)a.g)[c4];
            const float4 bb = ((const float4*)a.b)[c4];
            float xl[4], xx[4];
            xl[0] = (cv.x - mc) * rc * gg.x + bb.x;
            xl[1] = (cv.y - mc) * rc * gg.y + bb.y;
            xl[2] = (cv.z - mc) * rc * gg.z + bb.z;
            xl[3] = (cv.w - mc) * rc * gg.w + bb.w;
            if (t > 0) {
                xx[0] = (pv.x - mp) * rp * gg.x + bb.x;
                xx[1] = (pv.y - mp) * rp * gg.y + bb.y;
                xx[2] = (pv.z - mp) * rp * gg.z + bb.z;
                xx[3] = (pv.w - mp) * rp * gg.w + bb.w;
            } else { xx[0] = xx[1] = xx[2] = xx[3] = 0.f; }
            const float4 k4 = ((const float4*)a.mk)[c4];
            const float4 v4 = ((const float4*)a.mv)[c4];
            const float4 r4 = ((const float4*)a.mr)[c4];
            const float4 g4 = ((const float4*)a.mg)[c4];
            const float* km = &k4.x; const float* vm = &v4.x;
            const float* rm = &r4.x; const float* gm = &g4.x;
            h16 ok[4], ov[4], orr[4], og[4];
#pragma unroll
            for (int q = 0; q < 4; q++) {
                const float d = xl[q] - xx[q];
                ok[q]  = __float2half_rn(xx[q] + km[q] * d);
                ov[q]  = __float2half_rn(xx[q] + vm[q] * d);
                orr[q] = __float2half_rn(xx[q] + rm[q] * d);
                og[q]  = __float2half_rn(xx[q] + gm[q] * d);
            }
            *(uint2*)&a.xk[ro + c] = *(uint2*)ok;
            *(uint2*)&a.xv[ro + c] = *(uint2*)ov;
            *(uint2*)&a.xr[ro + c] = *(uint2*)orr;
            *(uint2*)&a.xg[ro + c] = *(uint2*)og;
        }
        return;
    }

    // ---- transpose tiles ----
    const int tb = bid - BT;
    int job, tile;
    if (tb < 6144)       { job = tb >> 10; tile = tb & 1023; }
    else if (tb < 10240) { job = 6; tile = tb - 6144; }
    else                 { job = 7; tile = tb - 10240; }
    const int K = (job == 7) ? FFD : CC;
    const int N = (job == 6) ? FFD : CC;
    const int tn = N >> 6;
    const int k0 = (tile / tn) << 6;
    const int n0 = (tile % tn) << 6;
    const int tx = tid & 15, ty = tid >> 4;
    const float* W = a.wsrc[job];
#pragma unroll
    for (int i = 0; i < 4; i++) {
        const float4 q = *(const float4*)&W[(size_t)(k0 + ty + i * 16) * N + n0 + tx * 4];
        ts[ty + i * 16][tx * 4 + 0] = q.x;
        ts[ty + i * 16][tx * 4 + 1] = q.y;
        ts[ty + i * 16][tx * 4 + 2] = q.z;
        ts[ty + i * 16][tx * 4 + 3] = q.w;
    }
    __syncthreads();
    h16* T = a.wdst[job];
#pragma unroll
    for (int i = 0; i < 4; i++) {
        const int n = ty + i * 16;
        const __half2 h01 = __floats2half2_rn(ts[tx * 4 + 0][n], ts[tx * 4 + 1][n]);
        const __half2 h23 = __floats2half2_rn(ts[tx * 4 + 2][n], ts[tx * 4 + 3][n]);
        uint2 pk;
        pk.x = *(const uint32_t*)&h01;
        pk.y = *(const uint32_t*)&h23;
        *(uint2*)&T[(size_t)(n0 + n) * K + k0 + tx * 4] = pk;
    }
}

// ---------------- ln2 + mix2 fused ----------------
__global__ __launch_bounds__(256)
void ln_mix2_kernel(const float* __restrict__ x, const float* __restrict__ g,
                    const float* __restrict__ b, const float* __restrict__ mk,
                    const float* __restrict__ mr, h16* ck, h16* cr) {
    __shared__ float4 red[8];
    const int row = blockIdx.x;
    const int tid = threadIdx.x;
    const int t = row & (TT - 1);
    const float4* x4 = (const float4*)(x + (size_t)row * CC);
    float4 c0 = x4[tid], c1 = x4[tid + 256];
    float4 p0 = make_float4(0.f, 0.f, 0.f, 0.f), p1 = p0;
    if (t > 0) { p0 = x4[tid - 512]; p1 = x4[tid - 256]; }
    float s   = c0.x + c0.y + c0.z + c0.w + c1.x + c1.y + c1.z + c1.w;
    float s2  = c0.x*c0.x + c0.y*c0.y + c0.z*c0.z + c0.w*c0.w
              + c1.x*c1.x + c1.y*c1.y + c1.z*c1.z + c1.w*c1.w;
    float sp  = p0.x + p0.y + p0.z + p0.w + p1.x + p1.y + p1.z + p1.w;
    float sp2 = p0.x*p0.x + p0.y*p0.y + p0.z*p0.z + p0.w*p0.w
              + p1.x*p1.x + p1.y*p1.y + p1.z*p1.z + p1.w*p1.w;
    float4 T;
    lnmix_stats(s, s2, sp, sp2, red, T);
    const float mc = T.x * (1.f / CC);
    const float rc = rsqrtf(T.y * (1.f / CC) - mc * mc + EPS_);
    const float mp = T.z * (1.f / CC);
    const float rp = rsqrtf(T.w * (1.f / CC) - mp * mp + EPS_);
    const size_t ro = (size_t)row * CC;
#pragma unroll
    for (int half = 0; half < 2; half++) {
        const int c4 = tid + half * 256;
        const int c = c4 * 4;
        const float4 cv = half ? c1 : c0;
        const float4 pv = half ? p1 : p0;
        const float4 gg = ((const float4*)g)[c4];
        const float4 bb = ((const float4*)b)[c4];
        float xl[4], xx[4];
        xl[0] = (cv.x - mc) * rc * gg.x + bb.x;
        xl[1] = (cv.y - mc) * rc * gg.y + bb.y;
        xl[2] = (cv.z - mc) * rc * gg.z + bb.z;
        xl[3] = (cv.w - mc) * rc * gg.w + bb.w;
        if (t > 0) {
            xx[0] = (pv.x - mp) * rp * gg.x + bb.x;
            xx[1] = (pv.y - mp) * rp * gg.y + bb.y;
            xx[2] = (pv.z - mp) * rp * gg.z + bb.z;
            xx[3] = (pv.w - mp) * rp * gg.w + bb.w;
        } else { xx[0] = xx[1] = xx[2] = xx[3] = 0.f; }
        const float4 k4 = ((const float4*)mk)[c4];
        const float4 r4 = ((const float4*)mr)[c4];
        const float* km = &k4.x; const float* rm = &r4.x;
        h16 ok[4], orr[4];
#pragma unroll
        for (int q = 0; q < 4; q++) {
            const float d = xl[q] - xx[q];
            ok[q]  = __float2half_rn(xx[q] + km[q] * d);
            orr[q] = __float2half_rn(xx[q] + rm[q] * d);
        }
        *(uint2*)&ck[ro + c] = *(uint2*)ok;
        *(uint2*)&cr[ro + c] = *(uint2*)orr;
    }
}

// ---------------- mma.sync GEMM core: D = A @ B^T, fp16, BK=64 -------------
// EPI: 0 fp32 | 1 silu->fp16 | 2 relu^2->fp16 | 3 aux1+acc | 4 aux1+sigmoid(acc)*aux2
#define OFF_A 0
#define OFF_B 16384
#define STG   32768
#define GEMM_SMEM (3 * STG)

template <int EPI>
__device__ __forceinline__ void gemm_body(
        const h16* __restrict__ Ah, const h16* __restrict__ Bh,
        float* __restrict__ C, h16* __restrict__ Ch,
        int M, int N, int K, int row0, int col0,
        const float* __restrict__ aux1, const float* __restrict__ aux2,
        char* smem) {
    const uint32_t sb = s2u(smem);
    const int tid = threadIdx.x;
    const int NK = K / 64;

    const int sr = tid >> 3, su = tid & 7;
    uint32_t sdst[4];
#pragma unroll
    for (int p = 0; p < 4; p++) sdst[p] = SWZ((uint32_t)((sr + 32 * p) * 128 + su * 16));
    const h16* pA = Ah + (size_t)(row0 + sr) * K + su * 8;
    const h16* pB = Bh + (size_t)(col0 + sr) * K + su * 8;
    const size_t rs = (size_t)32 * K;

    auto load_stage = [&](int kb, int st) {
        const uint32_t s = sb + (uint32_t)st * STG;
        const size_t ko = (size_t)kb * 64;
#pragma unroll
        for (int p = 0; p < 4; p++) cp16(s + OFF_A + sdst[p], pA + p * rs + ko);
#pragma unroll
        for (int p = 0; p < 4; p++) cp16(s + OFF_B + sdst[p], pB + p * rs + ko);
        CP_COMMIT();
    };

    const int wid = tid >> 5, lane = tid & 31;
    const int wm = wid & 1, wn = wid >> 1;
    const int wmb = wm * 64, wnb = wn * 32;
    const uint32_t a_row  = (uint32_t)(wmb + (lane & 15));
    const uint32_t a_csel = (uint32_t)((lane >> 4) << 4);
    const uint32_t b_row  = (uint32_t)(wnb + ((lane >> 4) << 3) + (lane & 7));
    const uint32_t b_csel = (uint32_t)(((lane >> 3) & 1) << 4);

    float acc[4][4][4];
#pragma unroll
    for (int i = 0; i < 4; i++)
#pragma unroll
        for (int j = 0; j < 4; j++)
#pragma unroll
            for (int q = 0; q < 4; q++) acc[i][j][q] = 0.f;

    load_stage(0, 0);
    if (NK > 1) load_stage(1, 1);

#pragma unroll 1
    for (int kb = 0; kb < NK; kb++) {
        if (kb + 1 < NK) { CP_WAIT(1); } else { CP_WAIT(0); }
        __syncthreads();

        const uint32_t us = sb + (uint32_t)(kb % 3) * STG;
#pragma unroll
        for (int ks = 0; ks < 4; ks++) {
            uint32_t a[4][4], bfr[2][4];
#pragma unroll
            for (int mt = 0; mt < 4; mt++) {
                const uint32_t off = (a_row + mt * 16) * 128 + (uint32_t)(ks * 32) + a_csel;
                ldm4(a[mt], us + OFF_A + SWZ(off));
            }
#pragma unroll
            for (int bp = 0; bp < 2; bp++) {
                const uint32_t off = (b_row + bp * 16) * 128 + (uint32_t)(ks * 32) + b_csel;
                ldm4(bfr[bp], us + OFF_B + SWZ(off));
            }
#pragma unroll
            for (int mt = 0; mt < 4; mt++)
#pragma unroll
                for (int nt = 0; nt < 4; nt++)
                    mma16816(acc[mt][nt], a[mt], &bfr[nt >> 1][(nt & 1) * 2]);
        }
        if (kb + 2 < NK) load_stage(kb + 2, (kb + 2) % 3);
    }

    const int mrow = row0 + wmb + (lane >> 2);
    const int ncol = col0 + wnb + (lane & 3) * 2;
#pragma unroll
    for (int mt = 0; mt < 4; mt++) {
#pragma unroll
        for (int half = 0; half < 2; half++) {
            const size_t m = (size_t)(mrow + mt * 16 + half * 8);
#pragma unroll
            for (int nt = 0; nt < 4; nt++) {
                float vx = acc[mt][nt][half * 2 + 0];
                float vy = acc[mt][nt][half * 2 + 1];
                const size_t idx = m * N + (ncol + nt * 8);
                if (EPI == 1 || EPI == 2) {
                    if (EPI == 1) {
                        vx /= (1.f + expf(-vx)); vy /= (1.f + expf(-vy));
                    } else {
                        vx = fmaxf(vx, 0.f); vx *= vx;
                        vy = fmaxf(vy, 0.f); vy *= vy;
                    }
                    __half2 hp;
                    hp.x = __float2half_rn(vx); hp.y = __float2half_rn(vy);
                    *(__half2*)&Ch[idx] = hp;
                } else {
                    if (EPI == 3) {
                        const float2 a2 = *(const float2*)&aux1[idx];
                        vx += a2.x; vy += a2.y;
                    } else if (EPI == 4) {
                        const float2 a2 = *(const float2*)&aux1[idx];
                        const float2 b2 = *(const float2*)&aux2[idx];
                        vx = a2.x + b2.x / (1.f + expf(-vx));
                        vy = a2.y + b2.y / (1.f + expf(-vy));
                    }
                    float2 p; p.x = vx; p.y = vy;
                    *(float2*)&C[idx] = p;
                }
            }
        }
    }
}

template <int EPI>
__global__ __launch_bounds__(256, 2)
void mmagemm(const h16* __restrict__ Ah, const h16* __restrict__ Bh,
             float* __restrict__ C, h16* __restrict__ Ch,
             int M, int N, int K,
             const float* __restrict__ aux1, const float* __restrict__ aux2) {
    extern __shared__ __align__(1024) char smem[];
    gemm_body<EPI>(Ah, Bh, C, Ch, M, N, K,
                   blockIdx.y * 128, blockIdx.x * 128, aux1, aux2, smem);
}

// Batched QKVG: grid (16,16,4); job 3 (G) = silu -> fp16, others fp32.
struct G4Args {
    const h16* A[4];
    const h16* B[4];
    float* C[3];
    h16* Ch3;
};
__global__ __launch_bounds__(256, 2)
void gemm_qkvg(G4Args ga) {
    extern __shared__ __align__(1024) char smem[];
    const int job = blockIdx.z;
    if (job == 3)
        gemm_body<1>(ga.A[3], ga.B[3], nullptr, ga.Ch3, BT, CC, CC,
                     blockIdx.y * 128, blockIdx.x * 128, nullptr, nullptr, smem);
    else
        gemm_body<0>(ga.A[job], ga.B[job], ga.C[job], nullptr, BT, CC, CC,
                     blockIdx.y * 128, blockIdx.x * 128, nullptr, nullptr, smem);
}

// ---------------- WKV5 recurrence, chunked cp.async staging ----------------
#define TC 32
#define WKV_SMEM (10240 * 4)

__global__ __launch_bounds__(128)
void wkv_kernel(const float* __restrict__ r, const float* __restrict__ k,
                const float* __restrict__ v, const float* __restrict__ w,
                const float* __restrict__ u, float* __restrict__ att) {
    extern __shared__ __align__(16) float sm[];
    float* const srm = sm;
    float* const skm = sm + 4096;
    float* const svm = sm + 8192;
    const uint32_t sr_u = s2u(srm), sk_u = s2u(skm), sv_u = s2u(svm);

    const int blk = blockIdx.x;
    const int jc = blk & 1;
    const int bh = blk >> 1;
    const int b = bh / HH, h = bh % HH;
    const int tid = threadIdx.x;
    const int jl = tid >> 2;
    const int j = jc * 32 + jl;
    const int p = tid & 3;

    const size_t base = ((size_t)b * TT * HH + h) * NNH;

    const int srow = tid >> 2;
    const int scb  = (tid & 3) * 16;
    const uint32_t s_dst = (uint32_t)((srow * 64 + scb) * 4);
    const int vrow0 = tid >> 3, vunit0 = tid & 7;
    const int vrow1 = (tid + 128) >> 3, vunit1 = tid & 7;
    const uint32_t v_dst0 = (uint32_t)((vrow0 * 32 + vunit0 * 4) * 4);
    const uint32_t v_dst1 = (uint32_t)((vrow1 * 32 + vunit1 * 4) * 4);

    auto stage = [&](int ch, int buf) {
        const int t0 = ch * TC;
        const uint32_t bo = (uint32_t)(buf * 2048 * 4);
        const uint32_t bv = (uint32_t)(buf * 1024 * 4);
        const float* rg = r + base + (size_t)(t0 + srow) * 2048 + scb;
        const float* kg = k + base + (size_t)(t0 + srow) * 2048 + scb;
#pragma unroll
        for (int q = 0; q < 4; q++) {
            cp16(sr_u + bo + s_dst + q * 16, rg + q * 4);
            cp16(sk_u + bo + s_dst + q * 16, kg + q * 4);
        }
        cp16(sv_u + bv + v_dst0, v + base + (size_t)(t0 + vrow0) * 2048 + jc * 32 + vunit0 * 4);
        cp16(sv_u + bv + v_dst1, v + base + (size_t)(t0 + vrow1) * 2048 + jc * 32 + vunit1 * 4);
        CP_COMMIT();
    };

    float S[16], dec[16], uu[16];
#pragma unroll
    for (int ii = 0; ii < 16; ii++) S[ii] = 0.f;
#pragma unroll
    for (int ii = 0; ii < 16; ii++) {
        const float wv = w[h * NNH + p * 16 + ii];
        dec[ii] = expf(-expf(wv));
        uu[ii]  = u[h * NNH + p * 16 + ii];
    }

    stage(0, 0);

    const int NC = TT / TC;
#pragma unroll 1
    for (int ch = 0; ch < NC; ch++) {
        CP_WAIT(0);
        __syncthreads();
        if (ch + 1 < NC) stage(ch + 1, (ch + 1) & 1);
        const int buf = ch & 1;
        const float* rp = srm + buf * 2048 + p * 16;
        const float* kp = skm + buf * 2048 + p * 16;
        const float* vp = svm + buf * 1024 + jl;
        const int t0 = ch * TC;
#pragma unroll 2
        for (int tt = 0; tt < TC; tt++) {
            float rr[16], kk[16];
            *(float4*)&rr[0]  = *(const float4*)(rp + tt * 64 + 0);
            *(float4*)&rr[4]  = *(const float4*)(rp + tt * 64 + 4);
            *(float4*)&rr[8]  = *(const float4*)(rp + tt * 64 + 8);
            *(float4*)&rr[12] = *(const float4*)(rp + tt * 64 + 12);
            *(float4*)&kk[0]  = *(const float4*)(kp + tt * 64 + 0);
            *(float4*)&kk[4]  = *(const float4*)(kp + tt * 64 + 4);
            *(float4*)&kk[8]  = *(const float4*)(kp + tt * 64 + 8);
            *(float4*)&kk[12] = *(const float4*)(kp + tt * 64 + 12);
            const float vj = vp[tt * 32];
            float yp = 0.f;
#pragma unroll
            for (int ii = 0; ii < 16; ii++) {
                const float kv = kk[ii] * vj;
                yp = fmaf(rr[ii], fmaf(uu[ii], kv, S[ii]), yp);
                S[ii] = fmaf(dec[ii], S[ii], kv);
            }
            float y = yp + __shfl_xor_sync(0xffffffffu, yp, 1);
            y += __shfl_xor_sync(0xffffffffu, y, 2);
            if (p == 0) att[base + (size_t)(t0 + tt) * 2048 + j] = y;
        }
    }
}

// ---------------- GroupNorm(att/DIV)*g+b, * gate(fp16), fp16 out ----------
__global__ void gn_gate_kernel(const float* __restrict__ att, const h16* __restrict__ gq,
                               const float* __restrict__ gg, const float* __restrict__ gb,
                               h16* __restrict__ oh) {
    const int gid  = blockIdx.x * 8 + (threadIdx.x >> 5);
    const int lane = threadIdx.x & 31;
    const int h = gid & (HH - 1);
    const size_t off = (size_t)gid * NNH;
    const float inv_div = 1.f / 8.f;
    const float v0 = att[off + lane]      * inv_div;
    const float v1 = att[off + lane + 32] * inv_div;
    float s = v0 + v1, s2 = v0 * v0 + v1 * v1;
#pragma unroll
    for (int o = 16; o; o >>= 1) {
        s  += __shfl_xor_sync(0xffffffffu, s,  o);
        s2 += __shfl_xor_sync(0xffffffffu, s2, o);
    }
    const float m = s * (1.f / NNH);
    const float var = s2 * (1.f / NNH) - m * m;
    const float rstd = rsqrtf(var + EPS_);
    const int c0 = h * NNH + lane;
    const float g0 = __half2float(gq[off + lane]);
    const float g1 = __half2float(gq[off + lane + 32]);
    const float o0 = ((v0 - m) * rstd * gg[c0]      + gb[c0])      * g0;
    const float o1 = ((v1 - m) * rstd * gg[c0 + 32] + gb[c0 + 32]) * g1;
    oh[off + lane]      = __float2half_rn(o0);
    oh[off + lane + 32] = __float2half_rn(o1);
}

// ---------------- launch ----------------
extern "C" void kernel_launch(void* const* d_in, const int* in_sizes, int n_in,
                              void* d_out, int out_size) {
    (void)in_sizes; (void)n_in; (void)out_size;
    const float* x     = (const float*)d_in[0];
    const float* ln1_g = (const float*)d_in[1];
    const float* ln1_b = (const float*)d_in[2];
    const float* ln2_g = (const float*)d_in[3];
    const float* ln2_b = (const float*)d_in[4];
    const float* tm_k  = (const float*)d_in[5];
    const float* tm_v  = (const float*)d_in[6];
    const float* tm_r  = (const float*)d_in[7];
    const float* tm_g  = (const float*)d_in[8];
    const float* tdec  = (const float*)d_in[9];
    const float* tfaa  = (const float*)d_in[10];
    const float* Wr    = (const float*)d_in[11];
    const float* Wk    = (const float*)d_in[12];
    const float* Wv    = (const float*)d_in[13];
    const float* Wg    = (const float*)d_in[14];
    const float* Wo    = (const float*)d_in[15];
    const float* lnx_g = (const float*)d_in[16];
    const float* lnx_b = (const float*)d_in[17];
    const float* fm_k  = (const float*)d_in[18];
    const float* fm_r  = (const float*)d_in[19];
    const float* Wkey  = (const float*)d_in[20];
    const float* Wrec  = (const float*)d_in[21];
    const float* Wval  = (const float*)d_in[22];
    float* out = (float*)d_out;

    float *Rb, *Kb, *Vb, *ATT, *X1, *KV;
    cudaGetSymbolAddress((void**)&Rb,  g_R);
    cudaGetSymbolAddress((void**)&Kb,  g_K);
    cudaGetSymbolAddress((void**)&Vb,  g_V);
    cudaGetSymbolAddress((void**)&ATT, g_ATT);
    cudaGetSymbolAddress((void**)&X1,  g_X1);
    cudaGetSymbolAddress((void**)&KV,  g_KV);

    h16 *XR,*XK,*XV,*XG,*Gh,*AG,*CK,*CR,*KK;
    cudaGetSymbolAddress((void**)&XR, g_XR);
    cudaGetSymbolAddress((void**)&XK, g_XK);
    cudaGetSymbolAddress((void**)&XV, g_XV);
    cudaGetSymbolAddress((void**)&XG, g_XG);
    cudaGetSymbolAddress((void**)&Gh, g_Gh);
    cudaGetSymbolAddress((void**)&AG, g_AG);
    cudaGetSymbolAddress((void**)&CK, g_CK);
    cudaGetSymbolAddress((void**)&CR, g_CR);
    cudaGetSymbolAddress((void**)&KK, g_KK);

    PrepArgs pa;
    pa.wsrc[0] = Wr;   cudaGetSymbolAddress((void**)&pa.wdst[0], g_WrT);
    pa.wsrc[1] = Wk;   cudaGetSymbolAddress((void**)&pa.wdst[1], g_WkT);
    pa.wsrc[2] = Wv;   cudaGetSymbolAddress((void**)&pa.wdst[2], g_WvT);
    pa.wsrc[3] = Wg;   cudaGetSymbolAddress((void**)&pa.wdst[3], g_WgT);
    pa.wsrc[4] = Wo;   cudaGetSymbolAddress((void**)&pa.wdst[4], g_WoT);
    pa.wsrc[5] = Wrec; cudaGetSymbolAddress((void**)&pa.wdst[5], g_WreT);
    pa.wsrc[6] = Wkey; cudaGetSymbolAddress((void**)&pa.wdst[6], g_WkeyT);
    pa.wsrc[7] = Wval; cudaGetSymbolAddress((void**)&pa.wdst[7], g_WvalT);
    pa.x = x; pa.g = ln1_g; pa.b = ln1_b;
    pa.mk = tm_k; pa.mv = tm_v; pa.mr = tm_r; pa.mg = tm_g;
    pa.xk = XK; pa.xv = XV; pa.xr = XR; pa.xg = XG;
    h16* WrT   = pa.wdst[0]; h16* WkT   = pa.wdst[1]; h16* WvT  = pa.wdst[2];
    h16* WgT   = pa.wdst[3]; h16* WoT   = pa.wdst[4]; h16* WreT = pa.wdst[5];
    h16* WkeyT = pa.wdst[6]; h16* WvalT = pa.wdst[7];

    cudaFuncSetAttribute(mmagemm<0>, cudaFuncAttributeMaxDynamicSharedMemorySize, GEMM_SMEM);
    cudaFuncSetAttribute(mmagemm<2>, cudaFuncAttributeMaxDynamicSharedMemorySize, GEMM_SMEM);
    cudaFuncSetAttribute(mmagemm<3>, cudaFuncAttributeMaxDynamicSharedMemorySize, GEMM_SMEM);
    cudaFuncSetAttribute(mmagemm<4>, cudaFuncAttributeMaxDynamicSharedMemorySize, GEMM_SMEM);
    cudaFuncSetAttribute(gemm_qkvg,  cudaFuncAttributeMaxDynamicSharedMemorySize, GEMM_SMEM);
    cudaFuncSetAttribute(wkv_kernel, cudaFuncAttributeMaxDynamicSharedMemorySize, WKV_SMEM);

    const dim3 gCC(CC / 128, BT / 128);        // (16,16)
    const dim3 gFF(FFD / 128, BT / 128);       // (64,16)
    const dim3 gQ4(CC / 128, BT / 128, 4);     // (16,16,4)

    // prep: ln1+mix4 rows (first 4096 blocks) || weight transposes (14336)
    prep_kernel<<<BT + 14336, 256>>>(pa);

    // attention half
    G4Args ga;
    ga.A[0] = XR; ga.B[0] = WrT; ga.C[0] = Rb;
    ga.A[1] = XK; ga.B[1] = WkT; ga.C[1] = Kb;
    ga.A[2] = XV; ga.B[2] = WvT; ga.C[2] = Vb;
    ga.A[3] = XG; ga.B[3] = WgT; ga.Ch3 = Gh;
    gemm_qkvg<<<gQ4, 256, GEMM_SMEM>>>(ga);
    wkv_kernel<<<BB * HH * 2, 128, WKV_SMEM>>>(Rb, Kb, Vb, tdec, tfaa, ATT);
    gn_gate_kernel<<<BT * HH / 8, 256>>>(ATT, Gh, lnx_g, lnx_b, AG);
    mmagemm<3><<<gCC, 256, GEMM_SMEM>>>(AG, WoT, X1, nullptr, BT, CC, CC, x, nullptr);

    // FFN half
    ln_mix2_kernel<<<BT, 256>>>(X1, ln2_g, ln2_b, fm_k, fm_r, CK, CR);
    mmagemm<2><<<gFF, 256, GEMM_SMEM>>>(CK, WkeyT, nullptr, KK, BT, FFD, CC, nullptr, nullptr);
    mmagemm<0><<<gCC, 256, GEMM_SMEM>>>(KK, WvalT, KV, nullptr, BT, CC, FFD, nullptr, nullptr);
    mmagemm<4><<<gCC, 256, GEMM_SMEM>>>(CR, WreT, out, nullptr, BT, CC, CC, X1, KV);
}